// round 1
// baseline (speedup 1.0000x reference)
#include <cuda_runtime.h>

#define NN 100000
#define EE 1600000
#define BB 256
#define DIN 64
#define DE 128
#define GI 192
#define LGI (GI*DE)
#define LDE (DE*DE)

typedef unsigned long long u64;

// ---------------- scratch (static device arrays; no allocation) ----------------
__device__ float g_h0[NN*DE];
__device__ float g_h1[NN*DE];
__device__ float g_aggx[NN*DIN];
__device__ float g_aggh[NN*DE];
__device__ int   g_deg[NN];
__device__ int   g_rowptr[NN+1];
__device__ int   g_cursor[NN];
__device__ int   g_col[EE];
__device__ float g_gsum[BB*DE];

// ---------------- f32x2 packed math helpers (sm_103a) ----------------
__device__ __forceinline__ u64 pk2(float a, float b){
  u64 r; asm("mov.b64 %0,{%1,%2};":"=l"(r):"f"(a),"f"(b)); return r;
}
__device__ __forceinline__ float2 upk2(u64 v){
  float2 f; asm("mov.b64 {%0,%1},%2;":"=f"(f.x),"=f"(f.y):"l"(v)); return f;
}
__device__ __forceinline__ void fma2(u64& d, u64 a, u64 b){
  asm("fma.rn.f32x2 %0,%1,%2,%0;":"+l"(d):"l"(a),"l"(b));
}

// Register-tiled GEMM phase: 512 threads = 32 tx (4 cols each) x 16 ty (8 rows each).
// W in SMEM as [K][128] fp32, A in SMEM as [rows][SK]. Output 128 rows x 128 cols.
template<int K, int SK>
__device__ __forceinline__ void mm_phase(const float* __restrict__ wsh,
                                         const float* __restrict__ ash,
                                         int r0, int c0, u64 acc[8][2]){
  for(int k=0;k<K;k+=4){
    const ulonglong2 w0=*reinterpret_cast<const ulonglong2*>(wsh+(k+0)*DE+c0);
    const ulonglong2 w1=*reinterpret_cast<const ulonglong2*>(wsh+(k+1)*DE+c0);
    const ulonglong2 w2=*reinterpret_cast<const ulonglong2*>(wsh+(k+2)*DE+c0);
    const ulonglong2 w3=*reinterpret_cast<const ulonglong2*>(wsh+(k+3)*DE+c0);
#pragma unroll
    for(int r=0;r<8;r++){
      const float4 a=*reinterpret_cast<const float4*>(ash+(r0+r)*SK+k);
      u64 p;
      p=pk2(a.x,a.x); fma2(acc[r][0],p,w0.x); fma2(acc[r][1],p,w0.y);
      p=pk2(a.y,a.y); fma2(acc[r][0],p,w1.x); fma2(acc[r][1],p,w1.y);
      p=pk2(a.z,a.z); fma2(acc[r][0],p,w2.x); fma2(acc[r][1],p,w2.y);
      p=pk2(a.w,a.w); fma2(acc[r][0],p,w3.x); fma2(acc[r][1],p,w3.y);
    }
  }
}

// ---------------- CSR build ----------------
__global__ void k_zero(){
  int i=blockIdx.x*blockDim.x+threadIdx.x;
  if(i<NN) g_deg[i]=0;
  if(i<BB*DE) g_gsum[i]=0.f;
}
__global__ void k_hist(const int* __restrict__ ei){
  int e=blockIdx.x*blockDim.x+threadIdx.x;
  if(e<EE) atomicAdd(&g_deg[ei[EE+e]],1);
}
__global__ void k_scan(){
  __shared__ int wsum[32];
  __shared__ int s_carry;
  int tid=threadIdx.x, lane=tid&31, wid=tid>>5;
  if(tid==0) s_carry=0;
  __syncthreads();
  for(int base=0;base<NN;base+=1024){
    int i=base+tid;
    int v=(i<NN)?g_deg[i]:0;
    int x=v;
#pragma unroll
    for(int o=1;o<32;o<<=1){ int t=__shfl_up_sync(0xffffffffu,x,o); if(lane>=o) x+=t; }
    if(lane==31) wsum[wid]=x;
    __syncthreads();
    if(wid==0){
      int y=wsum[lane];
#pragma unroll
      for(int o=1;o<32;o<<=1){ int t=__shfl_up_sync(0xffffffffu,y,o); if(lane>=o) y+=t; }
      wsum[lane]=y;
    }
    __syncthreads();
    int carry=s_carry;
    int incl=x+((wid>0)?wsum[wid-1]:0);
    if(i<NN){ int ex=carry+incl-v; g_rowptr[i]=ex; g_cursor[i]=ex; }
    __syncthreads();
    if(tid==1023) s_carry=carry+wsum[31];
    __syncthreads();
  }
  if(tid==0) g_rowptr[NN]=EE;
}
__global__ void k_fill(const int* __restrict__ ei){
  int e=blockIdx.x*blockDim.x+threadIdx.x;
  if(e<EE){
    int d=ei[EE+e];
    int p=atomicAdd(&g_cursor[d],1);
    g_col[p]=ei[e];
  }
}

// ---------------- gather-sum aggregation (one warp per node) ----------------
__global__ void k_gather64(const float* __restrict__ x){
  int w=(blockIdx.x*blockDim.x+threadIdx.x)>>5;
  int lane=threadIdx.x&31;
  if(w>=NN) return;
  int s=g_rowptr[w], t=g_rowptr[w+1];
  float2 acc=make_float2(0.f,0.f);
  for(int e=s;e<t;e++){
    int nb=g_col[e];
    float2 v=*reinterpret_cast<const float2*>(x+(size_t)nb*DIN+lane*2);
    acc.x+=v.x; acc.y+=v.y;
  }
  *reinterpret_cast<float2*>(g_aggx+(size_t)w*DIN+lane*2)=acc;
}
__global__ void k_gather128(const float* __restrict__ h){
  int w=(blockIdx.x*blockDim.x+threadIdx.x)>>5;
  int lane=threadIdx.x&31;
  if(w>=NN) return;
  int s=g_rowptr[w], t=g_rowptr[w+1];
  float4 acc=make_float4(0.f,0.f,0.f,0.f);
  for(int e=s;e<t;e++){
    int nb=g_col[e];
    float4 v=*reinterpret_cast<const float4*>(h+(size_t)nb*DE+lane*4);
    acc.x+=v.x; acc.y+=v.y; acc.z+=v.z; acc.w+=v.w;
  }
  *reinterpret_cast<float4*>(g_aggh+(size_t)w*DE+lane*4)=acc;
}

// ---------------- encoder: h0 = relu(x @ W_in + b_in) ----------------
__global__ void __launch_bounds__(512,1) k_encoder(const float* __restrict__ x,
    const float* __restrict__ W, const float* __restrict__ b, float* __restrict__ h){
  extern __shared__ float sm[];
  float* wsh=sm;        // 64*128
  float* tsh=sm+8192;   // 128*64
  int tid=threadIdx.x, tx=tid&31, ty=tid>>5;
  int base=blockIdx.x*128;
  {
    const float4* wg=reinterpret_cast<const float4*>(W);
    float4* w4=reinterpret_cast<float4*>(wsh);
    for(int i=tid;i<2048;i+=512) w4[i]=wg[i];
  }
  for(int i=tid;i<128*DIN;i+=512){
    int r=i>>6, k=i&63; int node=base+r;
    tsh[i]=(node<NN)?x[(size_t)node*DIN+k]:0.f;
  }
  __syncthreads();
  int r0=ty*8, c0=tx*4;
  u64 acc[8][2];
#pragma unroll
  for(int r=0;r<8;r++){acc[r][0]=0ull;acc[r][1]=0ull;}
  mm_phase<DIN,DIN>(wsh,tsh,r0,c0,acc);
  float4 bb=*reinterpret_cast<const float4*>(b+c0);
#pragma unroll
  for(int r=0;r<8;r++){
    int node=base+r0+r;
    if(node<NN){
      float2 lo=upk2(acc[r][0]), hi=upk2(acc[r][1]);
      float4 o;
      o.x=fmaxf(lo.x+bb.x,0.f); o.y=fmaxf(lo.y+bb.y,0.f);
      o.z=fmaxf(hi.x+bb.z,0.f); o.w=fmaxf(hi.y+bb.w,0.f);
      *reinterpret_cast<float4*>(h+(size_t)node*DE+c0)=o;
    }
  }
}

// ---------------- fused GIN layer ----------------
__global__ void __launch_bounds__(512,1) k_gin(const float* __restrict__ x,
    const float* __restrict__ hin, const float* __restrict__ eps, int layer,
    const float* __restrict__ W1, const float* __restrict__ b1,
    const float* __restrict__ W2, const float* __restrict__ b2,
    const float* __restrict__ lng, const float* __restrict__ lnb,
    float* __restrict__ hout){
  extern __shared__ float sm[];
  float* wsh=sm;         // 24576
  float* tsh=sm+24576;   // 24576
  int tid=threadIdx.x, tx=tid&31, ty=tid>>5;
  int base=blockIdx.x*128;
  float e1=1.f+eps[layer];
  {
    const float4* wg=reinterpret_cast<const float4*>(W1+(size_t)layer*LGI);
    float4* w4=reinterpret_cast<float4*>(wsh);
    for(int i=tid;i<LGI/4;i+=512) w4[i]=wg[i];
  }
  for(int i=tid;i<128*GI;i+=512){
    int r=i/GI, k=i-r*GI; int node=base+r;
    float v=0.f;
    if(node<NN){
      v=(k<DIN)?fmaf(e1,x[(size_t)node*DIN+k],g_aggx[(size_t)node*DIN+k])
               :fmaf(e1,hin[(size_t)node*DE+(k-DIN)],g_aggh[(size_t)node*DE+(k-DIN)]);
    }
    tsh[i]=v;
  }
  __syncthreads();
  int r0=ty*8, c0=tx*4;
  u64 acc[8][2];
#pragma unroll
  for(int r=0;r<8;r++){acc[r][0]=0ull;acc[r][1]=0ull;}
  mm_phase<GI,GI>(wsh,tsh,r0,c0,acc);
  float4 bb1=*reinterpret_cast<const float4*>(b1+(size_t)layer*DE+c0);
  __syncthreads();      // everyone done reading wsh/tsh of phase 1
#pragma unroll
  for(int r=0;r<8;r++){
    float2 lo=upk2(acc[r][0]), hi=upk2(acc[r][1]);
    float4 u;
    u.x=fmaxf(lo.x+bb1.x,0.f); u.y=fmaxf(lo.y+bb1.y,0.f);
    u.z=fmaxf(hi.x+bb1.z,0.f); u.w=fmaxf(hi.y+bb1.w,0.f);
    *reinterpret_cast<float4*>(tsh+(size_t)(r0+r)*DE+c0)=u;
  }
  {
    const float4* wg=reinterpret_cast<const float4*>(W2+(size_t)layer*LDE);
    float4* w4=reinterpret_cast<float4*>(wsh);
    for(int i=tid;i<LDE/4;i+=512) w4[i]=wg[i];
  }
  __syncthreads();
#pragma unroll
  for(int r=0;r<8;r++){acc[r][0]=0ull;acc[r][1]=0ull;}
  mm_phase<DE,DE>(wsh,tsh,r0,c0,acc);
  float4 bb2=*reinterpret_cast<const float4*>(b2+(size_t)layer*DE+c0);
  float4 g4 =*reinterpret_cast<const float4*>(lng+(size_t)layer*DE+c0);
  float4 be4=*reinterpret_cast<const float4*>(lnb+(size_t)layer*DE+c0);
#pragma unroll
  for(int r=0;r<8;r++){
    float2 lo=upk2(acc[r][0]), hi=upk2(acc[r][1]);
    float z0=lo.x+bb2.x, z1=lo.y+bb2.y, z2=hi.x+bb2.z, z3=hi.y+bb2.w;
    float s=z0+z1+z2+z3;
    float s2=z0*z0+z1*z1+z2*z2+z3*z3;
#pragma unroll
    for(int o=16;o>0;o>>=1){
      s +=__shfl_xor_sync(0xffffffffu,s ,o);
      s2+=__shfl_xor_sync(0xffffffffu,s2,o);
    }
    float mu=s*(1.f/128.f);
    float var=fmaxf(s2*(1.f/128.f)-mu*mu,0.f);
    float rs=rsqrtf(var+1e-5f);
    float n0=(z0-mu)*rs*g4.x+be4.x;
    float n1=(z1-mu)*rs*g4.y+be4.y;
    float n2=(z2-mu)*rs*g4.z+be4.z;
    float n3=(z3-mu)*rs*g4.w+be4.w;
    float4 o;
    o.x=(n0>0.f)?n0:expm1f(n0);
    o.y=(n1>0.f)?n1:expm1f(n1);
    o.z=(n2>0.f)?n2:expm1f(n2);
    o.w=(n3>0.f)?n3:expm1f(n3);
    int node=base+r0+r;
    if(node<NN) *reinterpret_cast<float4*>(hout+(size_t)node*DE+c0)=o;
  }
}

// ---------------- graph embedding + segmented pooling ----------------
__global__ void __launch_bounds__(512,1) k_graphemb(const float* __restrict__ h,
    const int* __restrict__ bidx, const float* __restrict__ gW, const float* __restrict__ gb,
    const float* __restrict__ lg, const float* __restrict__ lb){
  extern __shared__ float sm[];
  float* wsh=sm;         // 16384
  float* tsh=sm+16384;   // 16384
  __shared__ int sbid[128];
  int tid=threadIdx.x, tx=tid&31, ty=tid>>5;
  int base=blockIdx.x*128;
  {
    const float4* wg=reinterpret_cast<const float4*>(gW);
    float4* w4=reinterpret_cast<float4*>(wsh);
    for(int i=tid;i<4096;i+=512) w4[i]=wg[i];
  }
  for(int i=tid;i<16384;i+=512){
    int r=i>>7, k=i&127; int node=base+r;
    tsh[i]=(node<NN)?h[(size_t)node*DE+k]:0.f;
  }
  if(tid<128){ int node=base+tid; sbid[tid]=(node<NN)?bidx[node]:-1; }
  __syncthreads();
  int r0=ty*8, c0=tx*4;
  u64 acc[8][2];
#pragma unroll
  for(int r=0;r<8;r++){acc[r][0]=0ull;acc[r][1]=0ull;}
  mm_phase<DE,DE>(wsh,tsh,r0,c0,acc);
  float4 bb=*reinterpret_cast<const float4*>(gb+c0);
  float4 g4=*reinterpret_cast<const float4*>(lg+c0);
  float4 b4=*reinterpret_cast<const float4*>(lb+c0);
  float vreg[8][4]; float muv[8], rsv[8];
#pragma unroll
  for(int r=0;r<8;r++){
    float2 lo=upk2(acc[r][0]), hi=upk2(acc[r][1]);
    float v0=fmaxf(lo.x+bb.x,0.f), v1=fmaxf(lo.y+bb.y,0.f);
    float v2=fmaxf(hi.x+bb.z,0.f), v3=fmaxf(hi.y+bb.w,0.f);
    float s=v0+v1+v2+v3, s2=v0*v0+v1*v1+v2*v2+v3*v3;
#pragma unroll
    for(int o=16;o>0;o>>=1){
      s +=__shfl_xor_sync(0xffffffffu,s ,o);
      s2+=__shfl_xor_sync(0xffffffffu,s2,o);
    }
    float mu=s*(1.f/128.f);
    float var=fmaxf(s2*(1.f/128.f)-mu*mu,0.f);
    muv[r]=mu; rsv[r]=rsqrtf(var+1e-5f);
    vreg[r][0]=v0; vreg[r][1]=v1; vreg[r][2]=v2; vreg[r][3]=v3;
  }
  __syncthreads();
#pragma unroll
  for(int r=0;r<8;r++){
    float4 o;
    o.x=(vreg[r][0]-muv[r])*rsv[r]*g4.x+b4.x;
    o.y=(vreg[r][1]-muv[r])*rsv[r]*g4.y+b4.y;
    o.z=(vreg[r][2]-muv[r])*rsv[r]*g4.z+b4.z;
    o.w=(vreg[r][3]-muv[r])*rsv[r]*g4.w+b4.w;
    *reinterpret_cast<float4*>(tsh+(size_t)(r0+r)*DE+c0)=o;
  }
  __syncthreads();
  if(tid<128){
    int col=tid; float acc2=0.f; int cur=-1;
    for(int row=0;row<128;row++){
      int bi=sbid[row];
      if(bi!=cur){
        if(cur>=0) atomicAdd(&g_gsum[cur*DE+col],acc2);
        acc2=0.f; cur=bi;
      }
      if(bi>=0) acc2+=tsh[row*DE+col];
    }
    if(cur>=0) atomicAdd(&g_gsum[cur*DE+col],acc2);
  }
}

// ---------------- node_out + final LN + decoder MLP ----------------
#define DS_DW1 0
#define DS_DB1 6144
#define DS_DW2 6176
#define DS_DB2 6432
#define DS_DW3 6440
#define DS_DB3 6448
#define DS_LG  6464
#define DS_LB  6592
#define DS_TOT 6720

__global__ void __launch_bounds__(512,1) k_nodeout(const float* __restrict__ x,
    const float* __restrict__ h,
    const float* __restrict__ oW, const float* __restrict__ ob,
    const float* __restrict__ lg, const float* __restrict__ lb,
    const float* __restrict__ dW1, const float* __restrict__ db1,
    const float* __restrict__ dW2, const float* __restrict__ db2,
    const float* __restrict__ dW3, const float* __restrict__ db3,
    float* __restrict__ outp){
  extern __shared__ float sm[];
  float* wsh=sm;            // 16384
  float* tsh=sm+16384;      // 16384
  float* xsh=sm+32768;      // 8192
  float* dsh=sm+40960;      // DS_TOT
  int tid=threadIdx.x, tx=tid&31, ty=tid>>5;
  int base=blockIdx.x*128;
  {
    const float4* wg=reinterpret_cast<const float4*>(oW);
    float4* w4=reinterpret_cast<float4*>(wsh);
    for(int i=tid;i<4096;i+=512) w4[i]=wg[i];
  }
  for(int i=tid;i<16384;i+=512){
    int r=i>>7, k=i&127; int node=base+r;
    tsh[i]=(node<NN)?h[(size_t)node*DE+k]:0.f;
  }
  for(int i=tid;i<8192;i+=512){
    int r=i>>6, k=i&63; int node=base+r;
    xsh[i]=(node<NN)?x[(size_t)node*DIN+k]:0.f;
  }
  for(int i=tid;i<6144;i+=512) dsh[DS_DW1+i]=dW1[i];
  if(tid<32)  dsh[DS_DB1+tid]=db1[tid];
  if(tid<256) dsh[DS_DW2+tid]=dW2[tid];
  if(tid<8){ dsh[DS_DB2+tid]=db2[tid]; dsh[DS_DW3+tid]=dW3[tid]; }
  if(tid==0) dsh[DS_DB3]=db3[0];
  if(tid<128){ dsh[DS_LG+tid]=lg[tid]; dsh[DS_LB+tid]=lb[tid]; }
  __syncthreads();
  int r0=ty*8, c0=tx*4;
  u64 acc[8][2];
#pragma unroll
  for(int r=0;r<8;r++){acc[r][0]=0ull;acc[r][1]=0ull;}
  mm_phase<DE,DE>(wsh,tsh,r0,c0,acc);
  float4 bb=*reinterpret_cast<const float4*>(ob+c0);
  float vreg[8][4]; float muv[8], rsv[8];
#pragma unroll
  for(int r=0;r<8;r++){
    float2 lo=upk2(acc[r][0]), hi=upk2(acc[r][1]);
    float v0=fmaxf(lo.x+bb.x,0.f), v1=fmaxf(lo.y+bb.y,0.f);
    float v2=fmaxf(hi.x+bb.z,0.f), v3=fmaxf(hi.y+bb.w,0.f);
    float s=v0+v1+v2+v3, s2=v0*v0+v1*v1+v2*v2+v3*v3;
#pragma unroll
    for(int o=16;o>0;o>>=1){
      s +=__shfl_xor_sync(0xffffffffu,s ,o);
      s2+=__shfl_xor_sync(0xffffffffu,s2,o);
    }
    float mu=s*(1.f/128.f);
    float var=fmaxf(s2*(1.f/128.f)-mu*mu,0.f);
    muv[r]=mu; rsv[r]=rsqrtf(var+1e-5f);
    vreg[r][0]=v0; vreg[r][1]=v1; vreg[r][2]=v2; vreg[r][3]=v3;
  }
  __syncthreads();
  {
    float4 g4=*reinterpret_cast<const float4*>(dsh+DS_LG+c0);
    float4 b4=*reinterpret_cast<const float4*>(dsh+DS_LB+c0);
#pragma unroll
    for(int r=0;r<8;r++){
      float4 o;
      o.x=(vreg[r][0]-muv[r])*rsv[r]*g4.x+b4.x;
      o.y=(vreg[r][1]-muv[r])*rsv[r]*g4.y+b4.y;
      o.z=(vreg[r][2]-muv[r])*rsv[r]*g4.z+b4.z;
      o.w=(vreg[r][3]-muv[r])*rsv[r]*g4.w+b4.w;
      *reinterpret_cast<float4*>(tsh+(size_t)(r0+r)*DE+c0)=o;
    }
  }
  __syncthreads();
  // decoder: each warp handles its 8 rows, lane j = hidden unit
  int j=tx;
  for(int i=0;i<8;i++){
    int row=r0+i; int node=base+row;
    float s1=dsh[DS_DB1+j];
    const float* xrow=xsh+(size_t)row*DIN;
    const float* nrow=tsh+(size_t)row*DE;
#pragma unroll 4
    for(int k=0;k<DIN;k++) s1=fmaf(xrow[k],dsh[DS_DW1+k*32+j],s1);
#pragma unroll 4
    for(int k=0;k<DE;k++)  s1=fmaf(nrow[k],dsh[DS_DW1+(DIN+k)*32+j],s1);
    s1=fmaxf(s1,0.f);
    float s2[8];
#pragma unroll
    for(int m=0;m<8;m++) s2[m]=s1*dsh[DS_DW2+j*8+m];
#pragma unroll
    for(int o=16;o>0;o>>=1)
#pragma unroll
      for(int m=0;m<8;m++) s2[m]+=__shfl_xor_sync(0xffffffffu,s2[m],o);
    float out=dsh[DS_DB3];
#pragma unroll
    for(int m=0;m<8;m++) out=fmaf(fmaxf(s2[m]+dsh[DS_DB2+m],0.f),dsh[DS_DW3+m],out);
    if(j==0 && node<NN) outp[node]=out;
  }
}

// ---------------- graph-level MLP ----------------
__device__ __forceinline__ int lbound(const int* __restrict__ a, int n, int v){
  int lo=0, hi=n;
  while(lo<hi){ int mid=(lo+hi)>>1; if(a[mid]<v) lo=mid+1; else hi=mid; }
  return lo;
}
__global__ void k_gmlp(const int* __restrict__ bidx,
    const float* __restrict__ gW1, const float* __restrict__ gb1,
    const float* __restrict__ gW2, const float* __restrict__ gb2,
    const float* __restrict__ gW3, const float* __restrict__ gb3,
    float* __restrict__ outp){
  int tid=threadIdx.x, lane=tid&31;
  int g=blockIdx.x*8+(tid>>5);
  int lo=lbound(bidx,NN,g), hi=lbound(bidx,NN,g+1);
  float inv=1.f/fmaxf((float)(hi-lo),1.f);
  float s1=gb1[lane];
  for(int k=0;k<DE;k++){
    float ge=g_gsum[g*DE+k]*inv;
    s1=fmaf(ge,gW1[k*32+lane],s1);
  }
  s1=fmaxf(s1,0.f);
  float s2[8];
#pragma unroll
  for(int m=0;m<8;m++) s2[m]=s1*gW2[lane*8+m];
#pragma unroll
  for(int o=16;o>0;o>>=1)
#pragma unroll
    for(int m=0;m<8;m++) s2[m]+=__shfl_xor_sync(0xffffffffu,s2[m],o);
  float out=gb3[0];
#pragma unroll
  for(int m=0;m<8;m++) out=fmaf(fmaxf(s2[m]+gb2[m],0.f),gW3[m],out);
  if(lane==0) outp[NN+g]=out;
}

// ---------------- launch ----------------
extern "C" void kernel_launch(void* const* d_in, const int* in_sizes, int n_in,
                              void* d_out, int out_size){
  (void)in_sizes; (void)n_in; (void)out_size;
  const float* x   =(const float*)d_in[0];
  const int*   ei  =(const int*)  d_in[1];
  const int*   bidx=(const int*)  d_in[2];
  const float* W_in=(const float*)d_in[3];
  const float* b_in=(const float*)d_in[4];
  const float* eps =(const float*)d_in[5];
  const float* mW1 =(const float*)d_in[6];
  const float* mb1 =(const float*)d_in[7];
  const float* mW2 =(const float*)d_in[8];
  const float* mb2 =(const float*)d_in[9];
  const float* lng =(const float*)d_in[10];
  const float* lnb =(const float*)d_in[11];
  const float* oW  =(const float*)d_in[12];
  const float* ob  =(const float*)d_in[13];
  const float* lfg =(const float*)d_in[14];
  const float* lfb =(const float*)d_in[15];
  const float* gW  =(const float*)d_in[16];
  const float* gb  =(const float*)d_in[17];
  const float* glg =(const float*)d_in[18];
  const float* glb =(const float*)d_in[19];
  const float* dW1 =(const float*)d_in[20];
  const float* db1 =(const float*)d_in[21];
  const float* dW2 =(const float*)d_in[22];
  const float* db2 =(const float*)d_in[23];
  const float* dW3 =(const float*)d_in[24];
  const float* db3 =(const float*)d_in[25];
  const float* gW1 =(const float*)d_in[26];
  const float* gb1 =(const float*)d_in[27];
  const float* gW2 =(const float*)d_in[28];
  const float* gb2 =(const float*)d_in[29];
  const float* gW3 =(const float*)d_in[30];
  const float* gb3 =(const float*)d_in[31];
  float* outp=(float*)d_out;

  cudaFuncSetAttribute(k_encoder,  cudaFuncAttributeMaxDynamicSharedMemorySize, 65536);
  cudaFuncSetAttribute(k_gin,      cudaFuncAttributeMaxDynamicSharedMemorySize, 196608);
  cudaFuncSetAttribute(k_nodeout,  cudaFuncAttributeMaxDynamicSharedMemorySize, (40960+DS_TOT)*4);
  cudaFuncSetAttribute(k_graphemb, cudaFuncAttributeMaxDynamicSharedMemorySize, 131072);

  void *ph0, *ph1;
  cudaGetSymbolAddress(&ph0, g_h0);
  cudaGetSymbolAddress(&ph1, g_h1);

  k_zero<<<391,256>>>();
  k_hist<<<6250,256>>>(ei);
  k_scan<<<1,1024>>>();
  k_fill<<<6250,256>>>(ei);

  k_encoder<<<782,512,65536>>>(x, W_in, b_in, (float*)ph0);
  k_gather64<<<12500,256>>>(x);

  float* cur=(float*)ph0;
  float* nxt=(float*)ph1;
  for(int l=0;l<3;l++){
    k_gather128<<<12500,256>>>(cur);
    k_gin<<<782,512,196608>>>(x, cur, eps, l, mW1, mb1, mW2, mb2, lng, lnb, nxt);
    float* t=cur; cur=nxt; nxt=t;
  }

  k_graphemb<<<782,512,131072>>>(cur, bidx, gW, gb, glg, glb);
  k_nodeout<<<782,512,(40960+DS_TOT)*4>>>(x, cur, oW, ob, lfg, lfb,
                                          dW1, db1, dW2, db2, dW3, db3, outp);
  k_gmlp<<<32,256>>>(bidx, gW1, gb1, gW2, gb2, gW3, gb3, outp);
}

// round 2
// speedup vs baseline: 1.0017x; 1.0017x over previous
#include <cuda_runtime.h>

#define NN 100000
#define EE 1600000
#define BB 256
#define DIN 64
#define DE 128
#define GI 192
#define LGI (GI*DE)
#define LDE (DE*DE)

typedef unsigned long long u64;

// ---------------- scratch (static device arrays; no allocation) ----------------
__device__ float g_h0[NN*DE];
__device__ float g_h1[NN*DE];
__device__ float g_aggx[NN*DIN];
__device__ float g_aggh[NN*DE];
__device__ int   g_deg[NN];
__device__ int   g_rowptr[NN+1];
__device__ int   g_cursor[NN];
__device__ int   g_col[EE];
__device__ float g_gsum[BB*DE];

// ---------------- f32x2 packed math helpers (sm_103a) ----------------
__device__ __forceinline__ u64 pk2(float a, float b){
  u64 r; asm("mov.b64 %0,{%1,%2};":"=l"(r):"f"(a),"f"(b)); return r;
}
__device__ __forceinline__ float2 upk2(u64 v){
  float2 f; asm("mov.b64 {%0,%1},%2;":"=f"(f.x),"=f"(f.y):"l"(v)); return f;
}
__device__ __forceinline__ void fma2(u64& d, u64 a, u64 b){
  asm("fma.rn.f32x2 %0,%1,%2,%0;":"+l"(d):"l"(a),"l"(b));
}

// Register-tiled GEMM phase: 512 threads = 32 tx (4 cols each) x 16 ty (8 rows each).
// W in SMEM as [K][128] fp32, A in SMEM as [rows][SK]. Output 128 rows x 128 cols.
template<int K, int SK>
__device__ __forceinline__ void mm_phase(const float* __restrict__ wsh,
                                         const float* __restrict__ ash,
                                         int r0, int c0, u64 acc[8][2]){
  for(int k=0;k<K;k+=4){
    const ulonglong2 w0=*reinterpret_cast<const ulonglong2*>(wsh+(k+0)*DE+c0);
    const ulonglong2 w1=*reinterpret_cast<const ulonglong2*>(wsh+(k+1)*DE+c0);
    const ulonglong2 w2=*reinterpret_cast<const ulonglong2*>(wsh+(k+2)*DE+c0);
    const ulonglong2 w3=*reinterpret_cast<const ulonglong2*>(wsh+(k+3)*DE+c0);
#pragma unroll
    for(int r=0;r<8;r++){
      const float4 a=*reinterpret_cast<const float4*>(ash+(r0+r)*SK+k);
      u64 p;
      p=pk2(a.x,a.x); fma2(acc[r][0],p,w0.x); fma2(acc[r][1],p,w0.y);
      p=pk2(a.y,a.y); fma2(acc[r][0],p,w1.x); fma2(acc[r][1],p,w1.y);
      p=pk2(a.z,a.z); fma2(acc[r][0],p,w2.x); fma2(acc[r][1],p,w2.y);
      p=pk2(a.w,a.w); fma2(acc[r][0],p,w3.x); fma2(acc[r][1],p,w3.y);
    }
  }
}

// ---------------- CSR build ----------------
__global__ void k_zero(){
  int i=blockIdx.x*blockDim.x+threadIdx.x;
  if(i<NN) g_deg[i]=0;
  if(i<BB*DE) g_gsum[i]=0.f;
}
__global__ void k_hist(const int* __restrict__ ei){
  int e=blockIdx.x*blockDim.x+threadIdx.x;
  if(e<EE) atomicAdd(&g_deg[ei[EE+e]],1);
}
__global__ void k_scan(){
  __shared__ int wsum[32];
  __shared__ int s_carry;
  int tid=threadIdx.x, lane=tid&31, wid=tid>>5;
  if(tid==0) s_carry=0;
  __syncthreads();
  for(int base=0;base<NN;base+=1024){
    int i=base+tid;
    int v=(i<NN)?g_deg[i]:0;
    int x=v;
#pragma unroll
    for(int o=1;o<32;o<<=1){ int t=__shfl_up_sync(0xffffffffu,x,o); if(lane>=o) x+=t; }
    if(lane==31) wsum[wid]=x;
    __syncthreads();
    if(wid==0){
      int y=wsum[lane];
#pragma unroll
      for(int o=1;o<32;o<<=1){ int t=__shfl_up_sync(0xffffffffu,y,o); if(lane>=o) y+=t; }
      wsum[lane]=y;
    }
    __syncthreads();
    int carry=s_carry;
    int incl=x+((wid>0)?wsum[wid-1]:0);
    if(i<NN){ int ex=carry+incl-v; g_rowptr[i]=ex; g_cursor[i]=ex; }
    __syncthreads();
    if(tid==1023) s_carry=carry+wsum[31];
    __syncthreads();
  }
  if(tid==0) g_rowptr[NN]=EE;
}
__global__ void k_fill(const int* __restrict__ ei){
  int e=blockIdx.x*blockDim.x+threadIdx.x;
  if(e<EE){
    int d=ei[EE+e];
    int p=atomicAdd(&g_cursor[d],1);
    g_col[p]=ei[e];
  }
}

// ---------------- gather-sum aggregation (one warp per node) ----------------
__global__ void k_gather64(const float* __restrict__ x){
  int w=(blockIdx.x*blockDim.x+threadIdx.x)>>5;
  int lane=threadIdx.x&31;
  if(w>=NN) return;
  int s=g_rowptr[w], t=g_rowptr[w+1];
  float2 acc=make_float2(0.f,0.f);
  for(int e=s;e<t;e++){
    int nb=g_col[e];
    float2 v=*reinterpret_cast<const float2*>(x+(size_t)nb*DIN+lane*2);
    acc.x+=v.x; acc.y+=v.y;
  }
  *reinterpret_cast<float2*>(g_aggx+(size_t)w*DIN+lane*2)=acc;
}
__global__ void k_gather128(const float* __restrict__ h){
  int w=(blockIdx.x*blockDim.x+threadIdx.x)>>5;
  int lane=threadIdx.x&31;
  if(w>=NN) return;
  int s=g_rowptr[w], t=g_rowptr[w+1];
  float4 acc=make_float4(0.f,0.f,0.f,0.f);
  for(int e=s;e<t;e++){
    int nb=g_col[e];
    float4 v=*reinterpret_cast<const float4*>(h+(size_t)nb*DE+lane*4);
    acc.x+=v.x; acc.y+=v.y; acc.z+=v.z; acc.w+=v.w;
  }
  *reinterpret_cast<float4*>(g_aggh+(size_t)w*DE+lane*4)=acc;
}

// ---------------- encoder: h0 = relu(x @ W_in + b_in) ----------------
__global__ void __launch_bounds__(512,1) k_encoder(const float* __restrict__ x,
    const float* __restrict__ W, const float* __restrict__ b, float* __restrict__ h){
  extern __shared__ float sm[];
  float* wsh=sm;        // 64*128
  float* tsh=sm+8192;   // 128*64
  int tid=threadIdx.x, tx=tid&31, ty=tid>>5;
  int base=blockIdx.x*128;
  {
    const float4* wg=reinterpret_cast<const float4*>(W);
    float4* w4=reinterpret_cast<float4*>(wsh);
    for(int i=tid;i<2048;i+=512) w4[i]=wg[i];
  }
  for(int i=tid;i<128*DIN;i+=512){
    int r=i>>6, k=i&63; int node=base+r;
    tsh[i]=(node<NN)?x[(size_t)node*DIN+k]:0.f;
  }
  __syncthreads();
  int r0=ty*8, c0=tx*4;
  u64 acc[8][2];
#pragma unroll
  for(int r=0;r<8;r++){acc[r][0]=0ull;acc[r][1]=0ull;}
  mm_phase<DIN,DIN>(wsh,tsh,r0,c0,acc);
  float4 bb=*reinterpret_cast<const float4*>(b+c0);
#pragma unroll
  for(int r=0;r<8;r++){
    int node=base+r0+r;
    if(node<NN){
      float2 lo=upk2(acc[r][0]), hi=upk2(acc[r][1]);
      float4 o;
      o.x=fmaxf(lo.x+bb.x,0.f); o.y=fmaxf(lo.y+bb.y,0.f);
      o.z=fmaxf(hi.x+bb.z,0.f); o.w=fmaxf(hi.y+bb.w,0.f);
      *reinterpret_cast<float4*>(h+(size_t)node*DE+c0)=o;
    }
  }
}

// ---------------- fused GIN layer ----------------
__global__ void __launch_bounds__(512,1) k_gin(const float* __restrict__ x,
    const float* __restrict__ hin, const float* __restrict__ eps, int layer,
    const float* __restrict__ W1, const float* __restrict__ b1,
    const float* __restrict__ W2, const float* __restrict__ b2,
    const float* __restrict__ lng, const float* __restrict__ lnb,
    float* __restrict__ hout){
  extern __shared__ float sm[];
  float* wsh=sm;         // 24576
  float* tsh=sm+24576;   // 24576
  int tid=threadIdx.x, tx=tid&31, ty=tid>>5;
  int base=blockIdx.x*128;
  float e1=1.f+eps[layer];
  {
    const float4* wg=reinterpret_cast<const float4*>(W1+(size_t)layer*LGI);
    float4* w4=reinterpret_cast<float4*>(wsh);
    for(int i=tid;i<LGI/4;i+=512) w4[i]=wg[i];
  }
  for(int i=tid;i<128*GI;i+=512){
    int r=i/GI, k=i-r*GI; int node=base+r;
    float v=0.f;
    if(node<NN){
      v=(k<DIN)?fmaf(e1,x[(size_t)node*DIN+k],g_aggx[(size_t)node*DIN+k])
               :fmaf(e1,hin[(size_t)node*DE+(k-DIN)],g_aggh[(size_t)node*DE+(k-DIN)]);
    }
    tsh[i]=v;
  }
  __syncthreads();
  int r0=ty*8, c0=tx*4;
  u64 acc[8][2];
#pragma unroll
  for(int r=0;r<8;r++){acc[r][0]=0ull;acc[r][1]=0ull;}
  mm_phase<GI,GI>(wsh,tsh,r0,c0,acc);
  float4 bb1=*reinterpret_cast<const float4*>(b1+(size_t)layer*DE+c0);
  __syncthreads();      // everyone done reading wsh/tsh of phase 1
#pragma unroll
  for(int r=0;r<8;r++){
    float2 lo=upk2(acc[r][0]), hi=upk2(acc[r][1]);
    float4 u;
    u.x=fmaxf(lo.x+bb1.x,0.f); u.y=fmaxf(lo.y+bb1.y,0.f);
    u.z=fmaxf(hi.x+bb1.z,0.f); u.w=fmaxf(hi.y+bb1.w,0.f);
    *reinterpret_cast<float4*>(tsh+(size_t)(r0+r)*DE+c0)=u;
  }
  {
    const float4* wg=reinterpret_cast<const float4*>(W2+(size_t)layer*LDE);
    float4* w4=reinterpret_cast<float4*>(wsh);
    for(int i=tid;i<LDE/4;i+=512) w4[i]=wg[i];
  }
  __syncthreads();
#pragma unroll
  for(int r=0;r<8;r++){acc[r][0]=0ull;acc[r][1]=0ull;}
  mm_phase<DE,DE>(wsh,tsh,r0,c0,acc);
  float4 bb2=*reinterpret_cast<const float4*>(b2+(size_t)layer*DE+c0);
  float4 g4 =*reinterpret_cast<const float4*>(lng+(size_t)layer*DE+c0);
  float4 be4=*reinterpret_cast<const float4*>(lnb+(size_t)layer*DE+c0);
#pragma unroll
  for(int r=0;r<8;r++){
    float2 lo=upk2(acc[r][0]), hi=upk2(acc[r][1]);
    float z0=lo.x+bb2.x, z1=lo.y+bb2.y, z2=hi.x+bb2.z, z3=hi.y+bb2.w;
    float s=z0+z1+z2+z3;
    float s2=z0*z0+z1*z1+z2*z2+z3*z3;
#pragma unroll
    for(int o=16;o>0;o>>=1){
      s +=__shfl_xor_sync(0xffffffffu,s ,o);
      s2+=__shfl_xor_sync(0xffffffffu,s2,o);
    }
    float mu=s*(1.f/128.f);
    float var=fmaxf(s2*(1.f/128.f)-mu*mu,0.f);
    float rs=rsqrtf(var+1e-5f);
    float n0=(z0-mu)*rs*g4.x+be4.x;
    float n1=(z1-mu)*rs*g4.y+be4.y;
    float n2=(z2-mu)*rs*g4.z+be4.z;
    float n3=(z3-mu)*rs*g4.w+be4.w;
    float4 o;
    o.x=(n0>0.f)?n0:expm1f(n0);
    o.y=(n1>0.f)?n1:expm1f(n1);
    o.z=(n2>0.f)?n2:expm1f(n2);
    o.w=(n3>0.f)?n3:expm1f(n3);
    int node=base+r0+r;
    if(node<NN) *reinterpret_cast<float4*>(hout+(size_t)node*DE+c0)=o;
  }
}

// ---------------- graph embedding + segmented pooling ----------------
__global__ void __launch_bounds__(512,1) k_graphemb(const float* __restrict__ h,
    const int* __restrict__ bidx, const float* __restrict__ gW, const float* __restrict__ gb,
    const float* __restrict__ lg, const float* __restrict__ lb){
  extern __shared__ float sm[];
  float* wsh=sm;         // 16384
  float* tsh=sm+16384;   // 16384
  __shared__ int sbid[128];
  int tid=threadIdx.x, tx=tid&31, ty=tid>>5;
  int base=blockIdx.x*128;
  {
    const float4* wg=reinterpret_cast<const float4*>(gW);
    float4* w4=reinterpret_cast<float4*>(wsh);
    for(int i=tid;i<4096;i+=512) w4[i]=wg[i];
  }
  for(int i=tid;i<16384;i+=512){
    int r=i>>7, k=i&127; int node=base+r;
    tsh[i]=(node<NN)?h[(size_t)node*DE+k]:0.f;
  }
  if(tid<128){ int node=base+tid; sbid[tid]=(node<NN)?bidx[node]:-1; }
  __syncthreads();
  int r0=ty*8, c0=tx*4;
  u64 acc[8][2];
#pragma unroll
  for(int r=0;r<8;r++){acc[r][0]=0ull;acc[r][1]=0ull;}
  mm_phase<DE,DE>(wsh,tsh,r0,c0,acc);
  float4 bb=*reinterpret_cast<const float4*>(gb+c0);
  float4 g4=*reinterpret_cast<const float4*>(lg+c0);
  float4 b4=*reinterpret_cast<const float4*>(lb+c0);
  float vreg[8][4]; float muv[8], rsv[8];
#pragma unroll
  for(int r=0;r<8;r++){
    float2 lo=upk2(acc[r][0]), hi=upk2(acc[r][1]);
    float v0=fmaxf(lo.x+bb.x,0.f), v1=fmaxf(lo.y+bb.y,0.f);
    float v2=fmaxf(hi.x+bb.z,0.f), v3=fmaxf(hi.y+bb.w,0.f);
    float s=v0+v1+v2+v3, s2=v0*v0+v1*v1+v2*v2+v3*v3;
#pragma unroll
    for(int o=16;o>0;o>>=1){
      s +=__shfl_xor_sync(0xffffffffu,s ,o);
      s2+=__shfl_xor_sync(0xffffffffu,s2,o);
    }
    float mu=s*(1.f/128.f);
    float var=fmaxf(s2*(1.f/128.f)-mu*mu,0.f);
    muv[r]=mu; rsv[r]=rsqrtf(var+1e-5f);
    vreg[r][0]=v0; vreg[r][1]=v1; vreg[r][2]=v2; vreg[r][3]=v3;
  }
  __syncthreads();
#pragma unroll
  for(int r=0;r<8;r++){
    float4 o;
    o.x=(vreg[r][0]-muv[r])*rsv[r]*g4.x+b4.x;
    o.y=(vreg[r][1]-muv[r])*rsv[r]*g4.y+b4.y;
    o.z=(vreg[r][2]-muv[r])*rsv[r]*g4.z+b4.z;
    o.w=(vreg[r][3]-muv[r])*rsv[r]*g4.w+b4.w;
    *reinterpret_cast<float4*>(tsh+(size_t)(r0+r)*DE+c0)=o;
  }
  __syncthreads();
  if(tid<128){
    int col=tid; float acc2=0.f; int cur=-1;
    for(int row=0;row<128;row++){
      int bi=sbid[row];
      if(bi!=cur){
        if(cur>=0) atomicAdd(&g_gsum[cur*DE+col],acc2);
        acc2=0.f; cur=bi;
      }
      if(bi>=0) acc2+=tsh[row*DE+col];
    }
    if(cur>=0) atomicAdd(&g_gsum[cur*DE+col],acc2);
  }
}

// ---------------- node_out + final LN + decoder MLP ----------------
#define DS_DW1 0
#define DS_DB1 6144
#define DS_DW2 6176
#define DS_DB2 6432
#define DS_DW3 6440
#define DS_DB3 6448
#define DS_LG  6464
#define DS_LB  6592
#define DS_TOT 6720

__global__ void __launch_bounds__(512,1) k_nodeout(const float* __restrict__ x,
    const float* __restrict__ h,
    const float* __restrict__ oW, const float* __restrict__ ob,
    const float* __restrict__ lg, const float* __restrict__ lb,
    const float* __restrict__ dW1, const float* __restrict__ db1,
    const float* __restrict__ dW2, const float* __restrict__ db2,
    const float* __restrict__ dW3, const float* __restrict__ db3,
    float* __restrict__ outp){
  extern __shared__ float sm[];
  float* wsh=sm;            // 16384
  float* tsh=sm+16384;      // 16384
  float* xsh=sm+32768;      // 8192
  float* dsh=sm+40960;      // DS_TOT
  int tid=threadIdx.x, tx=tid&31, ty=tid>>5;
  int base=blockIdx.x*128;
  {
    const float4* wg=reinterpret_cast<const float4*>(oW);
    float4* w4=reinterpret_cast<float4*>(wsh);
    for(int i=tid;i<4096;i+=512) w4[i]=wg[i];
  }
  for(int i=tid;i<16384;i+=512){
    int r=i>>7, k=i&127; int node=base+r;
    tsh[i]=(node<NN)?h[(size_t)node*DE+k]:0.f;
  }
  for(int i=tid;i<8192;i+=512){
    int r=i>>6, k=i&63; int node=base+r;
    xsh[i]=(node<NN)?x[(size_t)node*DIN+k]:0.f;
  }
  for(int i=tid;i<6144;i+=512) dsh[DS_DW1+i]=dW1[i];
  if(tid<32)  dsh[DS_DB1+tid]=db1[tid];
  if(tid<256) dsh[DS_DW2+tid]=dW2[tid];
  if(tid<8){ dsh[DS_DB2+tid]=db2[tid]; dsh[DS_DW3+tid]=dW3[tid]; }
  if(tid==0) dsh[DS_DB3]=db3[0];
  if(tid<128){ dsh[DS_LG+tid]=lg[tid]; dsh[DS_LB+tid]=lb[tid]; }
  __syncthreads();
  int r0=ty*8, c0=tx*4;
  u64 acc[8][2];
#pragma unroll
  for(int r=0;r<8;r++){acc[r][0]=0ull;acc[r][1]=0ull;}
  mm_phase<DE,DE>(wsh,tsh,r0,c0,acc);
  float4 bb=*reinterpret_cast<const float4*>(ob+c0);
  float vreg[8][4]; float muv[8], rsv[8];
#pragma unroll
  for(int r=0;r<8;r++){
    float2 lo=upk2(acc[r][0]), hi=upk2(acc[r][1]);
    float v0=fmaxf(lo.x+bb.x,0.f), v1=fmaxf(lo.y+bb.y,0.f);
    float v2=fmaxf(hi.x+bb.z,0.f), v3=fmaxf(hi.y+bb.w,0.f);
    float s=v0+v1+v2+v3, s2=v0*v0+v1*v1+v2*v2+v3*v3;
#pragma unroll
    for(int o=16;o>0;o>>=1){
      s +=__shfl_xor_sync(0xffffffffu,s ,o);
      s2+=__shfl_xor_sync(0xffffffffu,s2,o);
    }
    float mu=s*(1.f/128.f);
    float var=fmaxf(s2*(1.f/128.f)-mu*mu,0.f);
    muv[r]=mu; rsv[r]=rsqrtf(var+1e-5f);
    vreg[r][0]=v0; vreg[r][1]=v1; vreg[r][2]=v2; vreg[r][3]=v3;
  }
  __syncthreads();
  {
    float4 g4=*reinterpret_cast<const float4*>(dsh+DS_LG+c0);
    float4 b4=*reinterpret_cast<const float4*>(dsh+DS_LB+c0);
#pragma unroll
    for(int r=0;r<8;r++){
      float4 o;
      o.x=(vreg[r][0]-muv[r])*rsv[r]*g4.x+b4.x;
      o.y=(vreg[r][1]-muv[r])*rsv[r]*g4.y+b4.y;
      o.z=(vreg[r][2]-muv[r])*rsv[r]*g4.z+b4.z;
      o.w=(vreg[r][3]-muv[r])*rsv[r]*g4.w+b4.w;
      *reinterpret_cast<float4*>(tsh+(size_t)(r0+r)*DE+c0)=o;
    }
  }
  __syncthreads();
  // decoder: each warp handles its 8 rows, lane j = hidden unit
  int j=tx;
  for(int i=0;i<8;i++){
    int row=r0+i; int node=base+row;
    float s1=dsh[DS_DB1+j];
    const float* xrow=xsh+(size_t)row*DIN;
    const float* nrow=tsh+(size_t)row*DE;
#pragma unroll 4
    for(int k=0;k<DIN;k++) s1=fmaf(xrow[k],dsh[DS_DW1+k*32+j],s1);
#pragma unroll 4
    for(int k=0;k<DE;k++)  s1=fmaf(nrow[k],dsh[DS_DW1+(DIN+k)*32+j],s1);
    s1=fmaxf(s1,0.f);
    float s2[8];
#pragma unroll
    for(int m=0;m<8;m++) s2[m]=s1*dsh[DS_DW2+j*8+m];
#pragma unroll
    for(int o=16;o>0;o>>=1)
#pragma unroll
      for(int m=0;m<8;m++) s2[m]+=__shfl_xor_sync(0xffffffffu,s2[m],o);
    float out=dsh[DS_DB3];
#pragma unroll
    for(int m=0;m<8;m++) out=fmaf(fmaxf(s2[m]+dsh[DS_DB2+m],0.f),dsh[DS_DW3+m],out);
    if(j==0 && node<NN) outp[node]=out;
  }
}

// ---------------- graph-level MLP ----------------
__device__ __forceinline__ int lbound(const int* __restrict__ a, int n, int v){
  int lo=0, hi=n;
  while(lo<hi){ int mid=(lo+hi)>>1; if(a[mid]<v) lo=mid+1; else hi=mid; }
  return lo;
}
__global__ void k_gmlp(const int* __restrict__ bidx,
    const float* __restrict__ gW1, const float* __restrict__ gb1,
    const float* __restrict__ gW2, const float* __restrict__ gb2,
    const float* __restrict__ gW3, const float* __restrict__ gb3,
    float* __restrict__ outp){
  int tid=threadIdx.x, lane=tid&31;
  int g=blockIdx.x*8+(tid>>5);
  int lo=lbound(bidx,NN,g), hi=lbound(bidx,NN,g+1);
  float inv=1.f/fmaxf((float)(hi-lo),1.f);
  float s1=gb1[lane];
  for(int k=0;k<DE;k++){
    float ge=g_gsum[g*DE+k]*inv;
    s1=fmaf(ge,gW1[k*32+lane],s1);
  }
  s1=fmaxf(s1,0.f);
  float s2[8];
#pragma unroll
  for(int m=0;m<8;m++) s2[m]=s1*gW2[lane*8+m];
#pragma unroll
  for(int o=16;o>0;o>>=1)
#pragma unroll
    for(int m=0;m<8;m++) s2[m]+=__shfl_xor_sync(0xffffffffu,s2[m],o);
  float out=gb3[0];
#pragma unroll
  for(int m=0;m<8;m++) out=fmaf(fmaxf(s2[m]+gb2[m],0.f),gW3[m],out);
  if(lane==0) outp[NN+g]=out;
}

// ---------------- launch ----------------
extern "C" void kernel_launch(void* const* d_in, const int* in_sizes, int n_in,
                              void* d_out, int out_size){
  (void)in_sizes; (void)n_in; (void)out_size;
  const float* x   =(const float*)d_in[0];
  const int*   ei  =(const int*)  d_in[1];
  const int*   bidx=(const int*)  d_in[2];
  const float* W_in=(const float*)d_in[3];
  const float* b_in=(const float*)d_in[4];
  const float* eps =(const float*)d_in[5];
  const float* mW1 =(const float*)d_in[6];
  const float* mb1 =(const float*)d_in[7];
  const float* mW2 =(const float*)d_in[8];
  const float* mb2 =(const float*)d_in[9];
  const float* lng =(const float*)d_in[10];
  const float* lnb =(const float*)d_in[11];
  const float* oW  =(const float*)d_in[12];
  const float* ob  =(const float*)d_in[13];
  const float* lfg =(const float*)d_in[14];
  const float* lfb =(const float*)d_in[15];
  const float* gW  =(const float*)d_in[16];
  const float* gb  =(const float*)d_in[17];
  const float* glg =(const float*)d_in[18];
  const float* glb =(const float*)d_in[19];
  const float* dW1 =(const float*)d_in[20];
  const float* db1 =(const float*)d_in[21];
  const float* dW2 =(const float*)d_in[22];
  const float* db2 =(const float*)d_in[23];
  const float* dW3 =(const float*)d_in[24];
  const float* db3 =(const float*)d_in[25];
  const float* gW1 =(const float*)d_in[26];
  const float* gb1 =(const float*)d_in[27];
  const float* gW2 =(const float*)d_in[28];
  const float* gb2 =(const float*)d_in[29];
  const float* gW3 =(const float*)d_in[30];
  const float* gb3 =(const float*)d_in[31];
  float* outp=(float*)d_out;

  cudaFuncSetAttribute(k_encoder,  cudaFuncAttributeMaxDynamicSharedMemorySize, 65536);
  cudaFuncSetAttribute(k_gin,      cudaFuncAttributeMaxDynamicSharedMemorySize, 196608);
  cudaFuncSetAttribute(k_nodeout,  cudaFuncAttributeMaxDynamicSharedMemorySize, (40960+DS_TOT)*4);
  cudaFuncSetAttribute(k_graphemb, cudaFuncAttributeMaxDynamicSharedMemorySize, 131072);

  void *ph0, *ph1;
  cudaGetSymbolAddress(&ph0, g_h0);
  cudaGetSymbolAddress(&ph1, g_h1);

  k_zero<<<391,256>>>();
  k_hist<<<6250,256>>>(ei);
  k_scan<<<1,1024>>>();
  k_fill<<<6250,256>>>(ei);

  k_encoder<<<782,512,65536>>>(x, W_in, b_in, (float*)ph0);
  k_gather64<<<12500,256>>>(x);

  float* cur=(float*)ph0;
  float* nxt=(float*)ph1;
  for(int l=0;l<3;l++){
    k_gather128<<<12500,256>>>(cur);
    k_gin<<<782,512,196608>>>(x, cur, eps, l, mW1, mb1, mW2, mb2, lng, lnb, nxt);
    float* t=cur; cur=nxt; nxt=t;
  }

  k_graphemb<<<782,512,131072>>>(cur, bidx, gW, gb, glg, glb);
  k_nodeout<<<782,512,(40960+DS_TOT)*4>>>(x, cur, oW, ob, lfg, lfb,
                                          dW1, db1, dW2, db2, dW3, db3, outp);
  k_gmlp<<<32,256>>>(bidx, gW1, gb1, gW2, gb2, gW3, gb3, outp);
}

// round 4
// speedup vs baseline: 1.4229x; 1.4205x over previous
#include <cuda_runtime.h>
#include <cuda_bf16.h>
#include <mma.h>

#define NN 100000
#define EE 1600000
#define BB 256
typedef unsigned long long u64;
typedef unsigned int u32;
using namespace nvcuda;

// ---- static scratch ----
__device__ __align__(16) __nv_bfloat16 g_xh[NN*64], g_xl[NN*64];
__device__ __align__(16) __nv_bfloat16 g_hh[NN*128], g_hl[NN*128];
__device__ __align__(16) __nv_bfloat16 g_wimg[327680];
__device__ float g_q[NN*128];
__device__ float g_agg[NN*128];
__device__ float g_gsum[BB*128];
__device__ int g_deg[NN], g_rowptr[NN+1], g_cursor[NN], g_col[EE];

__device__ __forceinline__ void split2(float a,float b,u32&h,u32&l){
  __nv_bfloat162 hh2=__floats2bfloat162_rn(a,b);
  float ra=a-__bfloat162float(hh2.x), rb=b-__bfloat162float(hh2.y);
  __nv_bfloat162 ll2=__floats2bfloat162_rn(ra,rb);
  h=*(u32*)&hh2; l=*(u32*)&ll2;
}

// ---- CSR ----
__global__ void k_zero(){int i=blockIdx.x*blockDim.x+threadIdx.x; if(i<NN)g_deg[i]=0; if(i<BB*128)g_gsum[i]=0.f;}
__global__ void k_hist(const int* __restrict__ ei){int e=blockIdx.x*blockDim.x+threadIdx.x; if(e<EE)atomicAdd(&g_deg[ei[EE+e]],1);}
__global__ void k_scan(){
  __shared__ int ws[32]; __shared__ int sc;
  int tid=threadIdx.x,lane=tid&31,wid=tid>>5;
  if(tid==0)sc=0; __syncthreads();
  for(int base=0;base<NN;base+=1024){
    int i=base+tid; int v=(i<NN)?g_deg[i]:0; int x=v;
#pragma unroll
    for(int o=1;o<32;o<<=1){int t=__shfl_up_sync(~0u,x,o); if(lane>=o)x+=t;}
    if(lane==31)ws[wid]=x; __syncthreads();
    if(wid==0){int y=ws[lane];
#pragma unroll
      for(int o=1;o<32;o<<=1){int t=__shfl_up_sync(~0u,y,o); if(lane>=o)y+=t;} ws[lane]=y;}
    __syncthreads();
    int c=sc; int incl=x+((wid>0)?ws[wid-1]:0);
    if(i<NN){int ex=c+incl-v; g_rowptr[i]=ex; g_cursor[i]=ex;}
    __syncthreads(); if(tid==1023)sc=c+ws[31]; __syncthreads();
  }
  if(tid==0)g_rowptr[NN]=EE;
}
__global__ void k_fill(const int* __restrict__ ei){
  int e=blockIdx.x*blockDim.x+threadIdx.x;
  if(e<EE){int d=ei[EE+e]; int p=atomicAdd(&g_cursor[d],1); g_col[p]=ei[e];}
}

// ---- prep: split x; build transposed/split W images (row-major [K][128] per plane) ----
__global__ void k_prepx(const float* __restrict__ x){
  int i=blockIdx.x*blockDim.x+threadIdx.x; if(i>=NN*32)return;
  float2 v=((const float2*)x)[i];
  u32 h,l; split2(v.x,v.y,h,l);
  ((u32*)g_xh)[i]=h; ((u32*)g_xl)[i]=l;
}
__global__ void k_prepw(const float* __restrict__ Win,const float* __restrict__ W1,
                        const float* __restrict__ W2,const float* __restrict__ gW,
                        const float* __restrict__ oW){
  int gid=blockIdx.x*blockDim.x+threadIdx.x; if(gid>=163840)return;
  const float* src; int idx,K; __nv_bfloat16* img;
  if(gid<8192){src=Win;idx=gid;K=64;img=g_wimg;}
  else if(gid<81920){int t=gid-8192;int l=t/24576;idx=t%24576;K=192;src=W1+l*24576;img=g_wimg+16384+l*49152;}
  else if(gid<131072){int t=gid-81920;int l=t/16384;idx=t%16384;K=128;src=W2+l*16384;img=g_wimg+163840+l*32768;}
  else if(gid<147456){idx=gid-131072;K=128;src=gW;img=g_wimg+262144;}
  else {idx=gid-147456;K=128;src=oW;img=g_wimg+294912;}
  float w=src[idx];
  __nv_bfloat16 h=__float2bfloat16(w);
  __nv_bfloat16 l=__float2bfloat16(w-__bfloat162float(h));
  img[idx]=h; img[K*128+idx]=l;   // idx = k*128+n already row-major
}

// ---- gather-sum of q (one warp / node) ----
__global__ void k_gather(){
  int w=(blockIdx.x*blockDim.x+threadIdx.x)>>5, lane=threadIdx.x&31;
  if(w>=NN)return;
  int s=g_rowptr[w],t=g_rowptr[w+1];
  float4 acc=make_float4(0,0,0,0);
  for(int e=s;e<t;e++){
    int nb=g_col[e];
    float4 v=*(const float4*)(g_q+(size_t)nb*128+lane*4);
    acc.x+=v.x;acc.y+=v.y;acc.z+=v.z;acc.w+=v.w;
  }
  *(float4*)(g_agg+(size_t)w*128+lane*4)=acc;
}

#define HDR 8192
#define SNB 136
#define DST 132
// decoder smem layout (floats, inside B-region for EPI3)
#define DS_DW1 0
#define DS_DB1 6144
#define DS_DW2 6176
#define DS_DB2 6432
#define DS_DW3 6440
#define DS_DB3 6448
#define DS_TOT 6464

// wmma core: 16 warps, warp = 16 rows x 64 cols. 3-plane split accumulate into D (float, stride DST).
template<int K>
__device__ __forceinline__ void wmma_core(const __nv_bfloat16* Ah,const __nv_bfloat16* Al,
    const __nv_bfloat16* Bh,const __nv_bfloat16* Bl,float* D,int wid){
  constexpr int SKA=K+8;
  wmma::fragment<wmma::accumulator,16,16,16,float> acc[4];
#pragma unroll
  for(int t=0;t<4;t++) wmma::fill_fragment(acc[t],0.f);
  int r0=(wid>>1)*16, c0=(wid&1)*64;
  for(int kc=0;kc<K;kc+=16){
    wmma::fragment<wmma::matrix_a,16,16,16,__nv_bfloat16,wmma::row_major> ah,al;
    wmma::load_matrix_sync(ah,Ah+(size_t)r0*SKA+kc,SKA);
    wmma::load_matrix_sync(al,Al+(size_t)r0*SKA+kc,SKA);
#pragma unroll
    for(int t=0;t<4;t++){
      wmma::fragment<wmma::matrix_b,16,16,16,__nv_bfloat16,wmma::row_major> bh,bl;
      wmma::load_matrix_sync(bh,Bh+(size_t)kc*SNB+c0+t*16,SNB);
      wmma::mma_sync(acc[t],ah,bh,acc[t]);
      wmma::mma_sync(acc[t],al,bh,acc[t]);
      wmma::load_matrix_sync(bl,Bl+(size_t)kc*SNB+c0+t*16,SNB);
      wmma::mma_sync(acc[t],ah,bl,acc[t]);
    }
  }
  __syncthreads();   // done reading A/B; D aliases them
#pragma unroll
  for(int t=0;t<4;t++)
    wmma::store_matrix_sync(D+(size_t)r0*DST+c0+t*16,acc[t],DST,wmma::mem_row_major);
  __syncthreads();
}

// ---- generic GEMM: EPI 0=relu->planes, 1=q raw, 2=graphemb LN+pool, 3=nodeout LN+decoder ----
template<int K0,int K1,int EPI>
__global__ void __launch_bounds__(512,1) k_mmp(
    const float* __restrict__ bias,const float* __restrict__ lg,const float* __restrict__ lb,
    int woff,const int* __restrict__ bidx,const float* __restrict__ x,
    const float* __restrict__ dW1,const float* __restrict__ db1,
    const float* __restrict__ dW2,const float* __restrict__ db2,
    const float* __restrict__ dW3,const float* __restrict__ db3,
    float* __restrict__ outp)
{
  constexpr int KT=K0+K1, SKA=KT+8, U=KT/8;
  constexpr int ABYTES=2*128*SKA*2;
  extern __shared__ unsigned char smx[];
  int* sbid=(int*)(smx+64);
  float* sr1=(float*)(smx+576);
  float* sr2=(float*)(smx+2624);
  __nv_bfloat16* Ah=(__nv_bfloat16*)(smx+HDR);
  __nv_bfloat16* Al=Ah+(size_t)128*SKA;
  __nv_bfloat16* Bh=(__nv_bfloat16*)(smx+HDR+ABYTES);
  __nv_bfloat16* Bl=Bh+(size_t)KT*SNB;
  float* D=(float*)(smx+HDR);
  int tid=threadIdx.x,lane=tid&31,wid=tid>>5;
  int base=blockIdx.x*128;
  if(EPI==2&&tid<128){int nd=base+tid; sbid[tid]=(nd<NN)?bidx[nd]:-1;}
  // stage B
  {
    const __nv_bfloat16* ws=g_wimg+woff;
    for(int i=tid;i<KT*16;i+=512){
      int k=i>>4,c8=(i&15)*8;
      *(uint4*)(Bh+(size_t)k*SNB+c8)=*(const uint4*)(ws+(size_t)k*128+c8);
      *(uint4*)(Bl+(size_t)k*SNB+c8)=*(const uint4*)(ws+(size_t)(KT+k)*128+c8);
    }
  }
  // stage A
  for(int i=tid;i<128*U;i+=512){
    int row=i/U, c8=(i-row*U)*8, node=base+row;
    uint4 hv=make_uint4(0,0,0,0), lv=hv;
    if(node<NN){
      if(K1==0||c8<K0){
        const __nv_bfloat16* ph=(K0==64)?g_xh:g_hh;
        const __nv_bfloat16* pl=(K0==64)?g_xl:g_hl;
        hv=*(const uint4*)(ph+(size_t)node*K0+c8);
        lv=*(const uint4*)(pl+(size_t)node*K0+c8);
      }else{
        hv=*(const uint4*)(g_hh+(size_t)node*K1+c8-K0);
        lv=*(const uint4*)(g_hl+(size_t)node*K1+c8-K0);
      }
    }
    *(uint4*)(Ah+(size_t)row*SKA+c8)=hv;
    *(uint4*)(Al+(size_t)row*SKA+c8)=lv;
  }
  __syncthreads();
  wmma_core<KT>(Ah,Al,Bh,Bl,D,wid);
  // epilogue: thread -> (R row, C0 col-chunk of 32)
  int C0=(wid>>2)*32, R=(wid&3)*32+lane, node=base+R;
  float v[32];
#pragma unroll
  for(int j=0;j<32;j++)v[j]=D[(size_t)R*DST+C0+j];
  if(EPI==1){
    if(node<NN){
      float* qr=g_q+(size_t)node*128+C0;
#pragma unroll
      for(int j=0;j<32;j+=4)*(float4*)(qr+j)=make_float4(v[j],v[j+1],v[j+2],v[j+3]);
    }
  }else if(EPI==0){
#pragma unroll
    for(int j=0;j<32;j++)v[j]=fmaxf(v[j]+bias[C0+j],0.f);
    if(node<NN){
      u32 hw[16],lw[16];
#pragma unroll
      for(int j=0;j<16;j++)split2(v[2*j],v[2*j+1],hw[j],lw[j]);
      uint4* oh=(uint4*)(g_hh+(size_t)node*128+C0);
      uint4* ol=(uint4*)(g_hl+(size_t)node*128+C0);
#pragma unroll
      for(int j=0;j<4;j++){oh[j]=((uint4*)hw)[j];ol[j]=((uint4*)lw)[j];}
    }
  }else{
    float s=0.f,s2=0.f;
#pragma unroll
    for(int j=0;j<32;j++){v[j]=fmaxf(v[j]+bias[C0+j],0.f); s+=v[j]; s2+=v[j]*v[j];}
    sr1[(wid>>2)*128+R]=s; sr2[(wid>>2)*128+R]=s2;
    __syncthreads();
    s=sr1[R]+sr1[128+R]+sr1[256+R]+sr1[384+R];
    s2=sr2[R]+sr2[128+R]+sr2[256+R]+sr2[384+R];
    float mu=s*(1.f/128.f), var=fmaxf(s2*(1.f/128.f)-mu*mu,0.f), rs=rsqrtf(var+1e-5f);
#pragma unroll
    for(int j=0;j<32;j++)D[(size_t)R*DST+C0+j]=(v[j]-mu)*rs*lg[C0+j]+lb[C0+j];
    __syncthreads();
    if(EPI==2){
      if(tid<128){
        int col=tid; float a=0.f; int cur=-1;
        for(int r=0;r<128;r++){
          int bi=sbid[r];
          if(bi!=cur){ if(cur>=0)atomicAdd(&g_gsum[cur*128+col],a); a=0.f; cur=bi; }
          if(bi>=0)a+=D[(size_t)r*DST+col];
        }
        if(cur>=0)atomicAdd(&g_gsum[cur*128+col],a);
      }
    }else{ // EPI==3: decoder
      float* xsh=(float*)(smx+HDR+ABYTES);   // B-region free now
      float* dsh=xsh+8192;
      for(int i=tid;i<8192;i+=512){int r=i>>6,k=i&63;int nd=base+r;xsh[i]=(nd<NN)?x[(size_t)nd*64+k]:0.f;}
      for(int i=tid;i<6144;i+=512)dsh[DS_DW1+i]=dW1[i];
      if(tid<32)dsh[DS_DB1+tid]=db1[tid];
      if(tid<256)dsh[DS_DW2+tid]=dW2[tid];
      if(tid<8){dsh[DS_DB2+tid]=db2[tid];dsh[DS_DW3+tid]=dW3[tid];}
      if(tid==0)dsh[DS_DB3]=db3[0];
      __syncthreads();
      int j=lane, r0=wid*8;
      for(int i=0;i<8;i++){
        int row=r0+i, nd=base+row;
        float s1=dsh[DS_DB1+j];
        const float* xr=xsh+(size_t)row*64;
        const float* nr=D+(size_t)row*DST;
#pragma unroll 4
        for(int k=0;k<64;k++)s1=fmaf(xr[k],dsh[DS_DW1+k*32+j],s1);
#pragma unroll 4
        for(int k=0;k<128;k++)s1=fmaf(nr[k],dsh[DS_DW1+(64+k)*32+j],s1);
        s1=fmaxf(s1,0.f);
        float t2[8];
#pragma unroll
        for(int m=0;m<8;m++)t2[m]=s1*dsh[DS_DW2+j*8+m];
#pragma unroll
        for(int o=16;o>0;o>>=1)
#pragma unroll
          for(int m=0;m<8;m++)t2[m]+=__shfl_xor_sync(~0u,t2[m],o);
        float out=dsh[DS_DB3];
#pragma unroll
        for(int m=0;m<8;m++)out=fmaf(fmaxf(t2[m]+dsh[DS_DB2+m],0.f),dsh[DS_DW3+m],out);
        if(j==0&&nd<NN)outp[nd]=out;
      }
    }
  }
}

// ---- GIN GEMM2: A = relu((1+eps)q + agg + b1) split on the fly; epilogue LN+ELU -> planes ----
__global__ void __launch_bounds__(512,1) k_mmu(
    const float* __restrict__ eps,int layer,
    const float* __restrict__ b1,const float* __restrict__ b2,
    const float* __restrict__ lng,const float* __restrict__ lnb,int woff)
{
  constexpr int KT=128, SKA=KT+8;
  constexpr int ABYTES=2*128*SKA*2;
  extern __shared__ unsigned char smx[];
  float* sr1=(float*)(smx+576);
  float* sr2=(float*)(smx+2624);
  __nv_bfloat16* Ah=(__nv_bfloat16*)(smx+HDR);
  __nv_bfloat16* Al=Ah+(size_t)128*SKA;
  __nv_bfloat16* Bh=(__nv_bfloat16*)(smx+HDR+ABYTES);
  __nv_bfloat16* Bl=Bh+(size_t)KT*SNB;
  float* D=(float*)(smx+HDR);
  int tid=threadIdx.x,lane=tid&31,wid=tid>>5;
  int base=blockIdx.x*128;
  float e1=1.f+eps[layer];
  {
    const __nv_bfloat16* ws=g_wimg+woff;
    for(int i=tid;i<KT*16;i+=512){
      int k=i>>4,c8=(i&15)*8;
      *(uint4*)(Bh+(size_t)k*SNB+c8)=*(const uint4*)(ws+(size_t)k*128+c8);
      *(uint4*)(Bl+(size_t)k*SNB+c8)=*(const uint4*)(ws+(size_t)(KT+k)*128+c8);
    }
  }
  for(int i=tid;i<128*16;i+=512){
    int row=i>>4, c8=(i&15)*8, node=base+row;
    uint4 hv=make_uint4(0,0,0,0), lv=hv;
    if(node<NN){
      const float* qr=g_q+(size_t)node*128+c8;
      const float* ar=g_agg+(size_t)node*128+c8;
      float4 qa=*(const float4*)qr, qb=*(const float4*)(qr+4);
      float4 aa=*(const float4*)ar, ab=*(const float4*)(ar+4);
      float u0=fmaxf(fmaf(e1,qa.x,aa.x)+b1[c8+0],0.f);
      float u1=fmaxf(fmaf(e1,qa.y,aa.y)+b1[c8+1],0.f);
      float u2=fmaxf(fmaf(e1,qa.z,aa.z)+b1[c8+2],0.f);
      float u3=fmaxf(fmaf(e1,qa.w,aa.w)+b1[c8+3],0.f);
      float u4=fmaxf(fmaf(e1,qb.x,ab.x)+b1[c8+4],0.f);
      float u5=fmaxf(fmaf(e1,qb.y,ab.y)+b1[c8+5],0.f);
      float u6=fmaxf(fmaf(e1,qb.z,ab.z)+b1[c8+6],0.f);
      float u7=fmaxf(fmaf(e1,qb.w,ab.w)+b1[c8+7],0.f);
      u32 hw[4],lw[4];
      split2(u0,u1,hw[0],lw[0]); split2(u2,u3,hw[1],lw[1]);
      split2(u4,u5,hw[2],lw[2]); split2(u6,u7,hw[3],lw[3]);
      hv=*(uint4*)hw; lv=*(uint4*)lw;
    }
    *(uint4*)(Ah+(size_t)row*SKA+c8)=hv;
    *(uint4*)(Al+(size_t)row*SKA+c8)=lv;
  }
  __syncthreads();
  wmma_core<KT>(Ah,Al,Bh,Bl,D,wid);
  int C0=(wid>>2)*32, R=(wid&3)*32+lane, node=base+R;
  float v[32]; float s=0.f,s2=0.f;
#pragma unroll
  for(int j=0;j<32;j++){v[j]=D[(size_t)R*DST+C0+j]+b2[C0+j]; s+=v[j]; s2+=v[j]*v[j];}
  sr1[(wid>>2)*128+R]=s; sr2[(wid>>2)*128+R]=s2;
  __syncthreads();
  s=sr1[R]+sr1[128+R]+sr1[256+R]+sr1[384+R];
  s2=sr2[R]+sr2[128+R]+sr2[256+R]+sr2[384+R];
  float mu=s*(1.f/128.f), var=fmaxf(s2*(1.f/128.f)-mu*mu,0.f), rs=rsqrtf(var+1e-5f);
  if(node<NN){
    u32 hw[16],lw[16];
#pragma unroll
    for(int j=0;j<16;j++){
      float n0=(v[2*j]-mu)*rs*lng[C0+2*j]+lnb[C0+2*j];
      float n1=(v[2*j+1]-mu)*rs*lng[C0+2*j+1]+lnb[C0+2*j+1];
      n0=(n0>0.f)?n0:expm1f(n0);
      n1=(n1>0.f)?n1:expm1f(n1);
      split2(n0,n1,hw[j],lw[j]);
    }
    uint4* oh=(uint4*)(g_hh+(size_t)node*128+C0);
    uint4* ol=(uint4*)(g_hl+(size_t)node*128+C0);
#pragma unroll
    for(int j=0;j<4;j++){oh[j]=((uint4*)hw)[j];ol[j]=((uint4*)lw)[j];}
  }
}

// ---- graph-level MLP ----
__device__ __forceinline__ int lbound(const int* __restrict__ a,int n,int v){
  int lo=0,hi=n;
  while(lo<hi){int m=(lo+hi)>>1; if(a[m]<v)lo=m+1; else hi=m;}
  return lo;
}
__global__ void k_gmlp(const int* __restrict__ bidx,
    const float* __restrict__ gW1,const float* __restrict__ gb1,
    const float* __restrict__ gW2,const float* __restrict__ gb2,
    const float* __restrict__ gW3,const float* __restrict__ gb3,
    float* __restrict__ outp){
  int tid=threadIdx.x,lane=tid&31;
  int g=blockIdx.x*8+(tid>>5);
  int lo=lbound(bidx,NN,g),hi=lbound(bidx,NN,g+1);
  float inv=1.f/fmaxf((float)(hi-lo),1.f);
  float s1=gb1[lane];
  for(int k=0;k<128;k++)s1=fmaf(g_gsum[g*128+k]*inv,gW1[k*32+lane],s1);
  s1=fmaxf(s1,0.f);
  float t2[8];
#pragma unroll
  for(int m=0;m<8;m++)t2[m]=s1*gW2[lane*8+m];
#pragma unroll
  for(int o=16;o>0;o>>=1)
#pragma unroll
    for(int m=0;m<8;m++)t2[m]+=__shfl_xor_sync(~0u,t2[m],o);
  float out=gb3[0];
#pragma unroll
  for(int m=0;m<8;m++)out=fmaf(fmaxf(t2[m]+gb2[m],0.f),gW3[m],out);
  if(lane==0)outp[NN+g]=out;
}

extern "C" void kernel_launch(void* const* d_in,const int* in_sizes,int n_in,
                              void* d_out,int out_size){
  (void)in_sizes;(void)n_in;(void)out_size;
  const float* x   =(const float*)d_in[0];
  const int*   ei  =(const int*)  d_in[1];
  const int*   bidx=(const int*)  d_in[2];
  const float* W_in=(const float*)d_in[3];
  const float* b_in=(const float*)d_in[4];
  const float* eps =(const float*)d_in[5];
  const float* mW1 =(const float*)d_in[6];
  const float* mb1 =(const float*)d_in[7];
  const float* mW2 =(const float*)d_in[8];
  const float* mb2 =(const float*)d_in[9];
  const float* lng =(const float*)d_in[10];
  const float* lnb =(const float*)d_in[11];
  const float* oW  =(const float*)d_in[12];
  const float* ob  =(const float*)d_in[13];
  const float* lfg =(const float*)d_in[14];
  const float* lfb =(const float*)d_in[15];
  const float* gW  =(const float*)d_in[16];
  const float* gb  =(const float*)d_in[17];
  const float* glg =(const float*)d_in[18];
  const float* glb =(const float*)d_in[19];
  const float* dW1 =(const float*)d_in[20];
  const float* db1 =(const float*)d_in[21];
  const float* dW2 =(const float*)d_in[22];
  const float* db2 =(const float*)d_in[23];
  const float* dW3 =(const float*)d_in[24];
  const float* db3 =(const float*)d_in[25];
  const float* gW1 =(const float*)d_in[26];
  const float* gb1 =(const float*)d_in[27];
  const float* gW2 =(const float*)d_in[28];
  const float* gb2 =(const float*)d_in[29];
  const float* gW3 =(const float*)d_in[30];
  const float* gb3 =(const float*)d_in[31];
  float* outp=(float*)d_out;

  const int SM_ENC=HDR+2*128*72*2 +2*64*SNB*2;   // 79872
  const int SM_192=HDR+2*128*200*2+2*192*SNB*2;  // 215040
  const int SM_128=HDR+2*128*136*2+2*128*SNB*2;  // 147456+8192=155648
  cudaFuncSetAttribute((const void*)k_mmp<64,0,0>,  cudaFuncAttributeMaxDynamicSharedMemorySize,SM_ENC);
  cudaFuncSetAttribute((const void*)k_mmp<64,128,1>,cudaFuncAttributeMaxDynamicSharedMemorySize,SM_192);
  cudaFuncSetAttribute((const void*)k_mmp<128,0,2>, cudaFuncAttributeMaxDynamicSharedMemorySize,SM_128);
  cudaFuncSetAttribute((const void*)k_mmp<128,0,3>, cudaFuncAttributeMaxDynamicSharedMemorySize,SM_128);
  cudaFuncSetAttribute((const void*)k_mmu,          cudaFuncAttributeMaxDynamicSharedMemorySize,SM_128);

  k_zero<<<391,256>>>();
  k_hist<<<6250,256>>>(ei);
  k_scan<<<1,1024>>>();
  k_fill<<<6250,256>>>(ei);
  k_prepx<<<12500,256>>>(x);
  k_prepw<<<640,256>>>(W_in,mW1,mW2,gW,oW);

  k_mmp<64,0,0><<<782,512,SM_ENC>>>(b_in,nullptr,nullptr,0,nullptr,nullptr,
      nullptr,nullptr,nullptr,nullptr,nullptr,nullptr,nullptr);
  for(int l=0;l<3;l++){
    k_mmp<64,128,1><<<782,512,SM_192>>>(nullptr,nullptr,nullptr,16384+l*49152,nullptr,nullptr,
        nullptr,nullptr,nullptr,nullptr,nullptr,nullptr,nullptr);
    k_gather<<<12500,256>>>();
    k_mmu<<<782,512,SM_128>>>(eps,l,mb1+l*128,mb2+l*128,lng+l*128,lnb+l*128,163840+l*32768);
  }
  k_mmp<128,0,2><<<782,512,SM_128>>>(gb,glg,glb,262144,bidx,nullptr,
      nullptr,nullptr,nullptr,nullptr,nullptr,nullptr,nullptr);
  k_mmp<128,0,3><<<782,512,SM_128>>>(ob,lfg,lfb,294912,nullptr,x,
      dW1,db1,dW2,db2,dW3,db3,outp);
  k_gmlp<<<32,256>>>(bidx,gW1,gb1,gW2,gb2,gW3,gb3,outp);
}

// round 5
// speedup vs baseline: 1.5498x; 1.0892x over previous
#include <cuda_runtime.h>
#include <cuda_bf16.h>
#include <mma.h>

#define NN 100000
#define EE 1600000
#define BB 256
typedef unsigned long long u64;
typedef unsigned int u32;
using namespace nvcuda;

// ---- static scratch ----
__device__ __align__(16) __nv_bfloat16 g_xh[NN*64], g_xl[NN*64];
__device__ __align__(16) __nv_bfloat16 g_hh[NN*128], g_hl[NN*128];
__device__ __align__(16) __nv_bfloat16 g_wimg[327680];
__device__ float g_q[NN*128];
__device__ float g_agg[NN*128];
__device__ float g_gsum[BB*128];
__device__ int g_deg[NN], g_rowptr[NN+1], g_cursor[NN], g_col[EE];
__device__ int g_bsum[128], g_boff[128];

__device__ __forceinline__ void split2(float a,float b,u32&h,u32&l){
  __nv_bfloat162 hh2=__floats2bfloat162_rn(a,b);
  float ra=a-__bfloat162float(hh2.x), rb=b-__bfloat162float(hh2.y);
  __nv_bfloat162 ll2=__floats2bfloat162_rn(ra,rb);
  h=*(u32*)&hh2; l=*(u32*)&ll2;
}
__device__ __forceinline__ void cpa16(void* dst,const void* src){
  u32 d=(u32)__cvta_generic_to_shared(dst);
  asm volatile("cp.async.cg.shared.global [%0],[%1],16;"::"r"(d),"l"(src));
}
__device__ __forceinline__ void cpwait(){ asm volatile("cp.async.wait_all;":::"memory"); }

// ---- CSR ----
__global__ void k_zero(){int i=blockIdx.x*blockDim.x+threadIdx.x; if(i<NN)g_deg[i]=0; if(i<BB*128)g_gsum[i]=0.f;}
__global__ void k_hist(const int* __restrict__ ei){int e=blockIdx.x*blockDim.x+threadIdx.x; if(e<EE)atomicAdd(&g_deg[ei[EE+e]],1);}
// pass1: per-block sums
__global__ void k_scan1(){
  __shared__ int ws[32];
  int tid=threadIdx.x,lane=tid&31,wid=tid>>5;
  int i=blockIdx.x*1024+tid;
  int v=(i<NN)?g_deg[i]:0;
  int x=v;
#pragma unroll
  for(int o=16;o>0;o>>=1)x+=__shfl_xor_sync(~0u,x,o);
  if(lane==0)ws[wid]=x;
  __syncthreads();
  if(tid==0){int s=0;
#pragma unroll
    for(int w=0;w<32;w++)s+=ws[w];
    g_bsum[blockIdx.x]=s;}
}
// pass2: exclusive scan of 98 block sums (1 block, 128 thr)
__global__ void k_scan2(){
  __shared__ int ws[4];
  int tid=threadIdx.x,lane=tid&31,wid=tid>>5;
  int v=(tid<98)?g_bsum[tid]:0;
  int x=v;
#pragma unroll
  for(int o=1;o<32;o<<=1){int t=__shfl_up_sync(~0u,x,o); if(lane>=o)x+=t;}
  if(lane==31)ws[wid]=x;
  __syncthreads();
  int add=0;
  for(int w=0;w<wid;w++)add+=ws[w];
  if(tid<98)g_boff[tid]=add+x-v;
  if(tid==0)g_rowptr[NN]=EE;
}
// pass3: block exclusive scan + offset
__global__ void k_scan3(){
  __shared__ int ws[32];
  int tid=threadIdx.x,lane=tid&31,wid=tid>>5;
  int i=blockIdx.x*1024+tid;
  int v=(i<NN)?g_deg[i]:0;
  int x=v;
#pragma unroll
  for(int o=1;o<32;o<<=1){int t=__shfl_up_sync(~0u,x,o); if(lane>=o)x+=t;}
  if(lane==31)ws[wid]=x;
  __syncthreads();
  if(wid==0){int y=ws[lane];
#pragma unroll
    for(int o=1;o<32;o<<=1){int t=__shfl_up_sync(~0u,y,o); if(lane>=o)y+=t;} ws[lane]=y;}
  __syncthreads();
  if(i<NN){
    int ex=g_boff[blockIdx.x]+x-v+((wid>0)?ws[wid-1]:0);
    g_rowptr[i]=ex; g_cursor[i]=ex;
  }
}
__global__ void k_fill(const int* __restrict__ ei){
  int e=blockIdx.x*blockDim.x+threadIdx.x;
  if(e<EE){int d=ei[EE+e]; int p=atomicAdd(&g_cursor[d],1); g_col[p]=ei[e];}
}

// ---- prep ----
__global__ void k_prepx(const float* __restrict__ x){
  int i=blockIdx.x*blockDim.x+threadIdx.x; if(i>=NN*32)return;
  float2 v=((const float2*)x)[i];
  u32 h,l; split2(v.x,v.y,h,l);
  ((u32*)g_xh)[i]=h; ((u32*)g_xl)[i]=l;
}
__global__ void k_prepw(const float* __restrict__ Win,const float* __restrict__ W1,
                        const float* __restrict__ W2,const float* __restrict__ gW,
                        const float* __restrict__ oW){
  int gid=blockIdx.x*blockDim.x+threadIdx.x; if(gid>=163840)return;
  const float* src; int idx,K; __nv_bfloat16* img;
  if(gid<8192){src=Win;idx=gid;K=64;img=g_wimg;}
  else if(gid<81920){int t=gid-8192;int l=t/24576;idx=t%24576;K=192;src=W1+l*24576;img=g_wimg+16384+l*49152;}
  else if(gid<131072){int t=gid-81920;int l=t/16384;idx=t%16384;K=128;src=W2+l*16384;img=g_wimg+163840+l*32768;}
  else if(gid<147456){idx=gid-131072;K=128;src=gW;img=g_wimg+262144;}
  else {idx=gid-147456;K=128;src=oW;img=g_wimg+294912;}
  float w=src[idx];
  __nv_bfloat16 h=__float2bfloat16(w);
  __nv_bfloat16 l=__float2bfloat16(w-__bfloat162float(h));
  img[idx]=h; img[K*128+idx]=l;
}

// ---- gather-sum of q (one warp/node, 4-way MLP) ----
__global__ void k_gather(){
  int w=(blockIdx.x*blockDim.x+threadIdx.x)>>5, lane=threadIdx.x&31;
  if(w>=NN)return;
  int s=g_rowptr[w],t=g_rowptr[w+1];
  float4 a0=make_float4(0,0,0,0),a1=a0,a2=a0,a3=a0;
  int e=s;
  for(;e+4<=t;e+=4){
    int n0=g_col[e],n1=g_col[e+1],n2=g_col[e+2],n3=g_col[e+3];
    float4 v0=*(const float4*)(g_q+(size_t)n0*128+lane*4);
    float4 v1=*(const float4*)(g_q+(size_t)n1*128+lane*4);
    float4 v2=*(const float4*)(g_q+(size_t)n2*128+lane*4);
    float4 v3=*(const float4*)(g_q+(size_t)n3*128+lane*4);
    a0.x+=v0.x;a0.y+=v0.y;a0.z+=v0.z;a0.w+=v0.w;
    a1.x+=v1.x;a1.y+=v1.y;a1.z+=v1.z;a1.w+=v1.w;
    a2.x+=v2.x;a2.y+=v2.y;a2.z+=v2.z;a2.w+=v2.w;
    a3.x+=v3.x;a3.y+=v3.y;a3.z+=v3.z;a3.w+=v3.w;
  }
  for(;e<t;e++){
    int nb=g_col[e];
    float4 v=*(const float4*)(g_q+(size_t)nb*128+lane*4);
    a0.x+=v.x;a0.y+=v.y;a0.z+=v.z;a0.w+=v.w;
  }
  a0.x+=a1.x+a2.x+a3.x; a0.y+=a1.y+a2.y+a3.y;
  a0.z+=a1.z+a2.z+a3.z; a0.w+=a1.w+a2.w+a3.w;
  *(float4*)(g_agg+(size_t)w*128+lane*4)=a0;
}

#define HDR 8192
#define SNB 136
#define DST 132
#define DS_DW1 0
#define DS_DB1 6144
#define DS_DW2 6176
#define DS_DB2 6432
#define DS_DW3 6440
#define DS_DB3 6448

template<int K>
__device__ __forceinline__ void wmma_core(const __nv_bfloat16* Ah,const __nv_bfloat16* Al,
    const __nv_bfloat16* Bh,const __nv_bfloat16* Bl,float* D,int wid){
  constexpr int SKA=K+8;
  wmma::fragment<wmma::accumulator,16,16,16,float> acc[4];
#pragma unroll
  for(int t=0;t<4;t++) wmma::fill_fragment(acc[t],0.f);
  int r0=(wid>>1)*16, c0=(wid&1)*64;
  for(int kc=0;kc<K;kc+=16){
    wmma::fragment<wmma::matrix_a,16,16,16,__nv_bfloat16,wmma::row_major> ah,al;
    wmma::load_matrix_sync(ah,Ah+(size_t)r0*SKA+kc,SKA);
    wmma::load_matrix_sync(al,Al+(size_t)r0*SKA+kc,SKA);
#pragma unroll
    for(int t=0;t<4;t++){
      wmma::fragment<wmma::matrix_b,16,16,16,__nv_bfloat16,wmma::row_major> bh,bl;
      wmma::load_matrix_sync(bh,Bh+(size_t)kc*SNB+c0+t*16,SNB);
      wmma::mma_sync(acc[t],ah,bh,acc[t]);
      wmma::mma_sync(acc[t],al,bh,acc[t]);
      wmma::load_matrix_sync(bl,Bl+(size_t)kc*SNB+c0+t*16,SNB);
      wmma::mma_sync(acc[t],ah,bl,acc[t]);
    }
  }
  __syncthreads();
#pragma unroll
  for(int t=0;t<4;t++)
    wmma::store_matrix_sync(D+(size_t)r0*DST+c0+t*16,acc[t],DST,wmma::mem_row_major);
  __syncthreads();
}

// ---- generic GEMM: EPI 0=relu->planes, 1=q raw, 2=graphemb LN+pool, 3=nodeout LN+decoder ----
template<int K0,int K1,int EPI>
__global__ void __launch_bounds__(512,1) k_mmp(
    const float* __restrict__ bias,const float* __restrict__ lg,const float* __restrict__ lb,
    int woff,const int* __restrict__ bidx,const float* __restrict__ x,
    const float* __restrict__ dW1,const float* __restrict__ db1,
    const float* __restrict__ dW2,const float* __restrict__ db2,
    const float* __restrict__ dW3,const float* __restrict__ db3,
    float* __restrict__ outp)
{
  constexpr int KT=K0+K1, SKA=KT+8, U=KT/8;
  constexpr int ABYTES=2*128*SKA*2;
  extern __shared__ unsigned char smx[];
  int* sbid=(int*)(smx+64);
  float* sr1=(float*)(smx+576);
  float* sr2=(float*)(smx+2624);
  __nv_bfloat16* Ah=(__nv_bfloat16*)(smx+HDR);
  __nv_bfloat16* Al=Ah+(size_t)128*SKA;
  __nv_bfloat16* Bh=(__nv_bfloat16*)(smx+HDR+ABYTES);
  __nv_bfloat16* Bl=Bh+(size_t)KT*SNB;
  float* D=(float*)(smx+HDR);
  int tid=threadIdx.x,lane=tid&31,wid=tid>>5;
  int base=blockIdx.x*128;
  if(EPI==2&&tid<128){int nd=base+tid; sbid[tid]=(nd<NN)?bidx[nd]:-1;}
  // stage B via cp.async
  {
    const __nv_bfloat16* ws=g_wimg+woff;
    for(int i=tid;i<KT*16;i+=512){
      int k=i>>4,c8=(i&15)*8;
      cpa16(Bh+(size_t)k*SNB+c8, ws+(size_t)k*128+c8);
      cpa16(Bl+(size_t)k*SNB+c8, ws+(size_t)(KT+k)*128+c8);
    }
  }
  // stage A via cp.async (zero-fill OOB rows)
  for(int i=tid;i<128*U;i+=512){
    int row=i/U, c8=(i-row*U)*8, node=base+row;
    if(node<NN){
      const __nv_bfloat16 *ph,*pl; size_t off;
      if(K1==0||c8<K0){
        ph=(K0==64)?g_xh:g_hh; pl=(K0==64)?g_xl:g_hl; off=(size_t)node*K0+c8;
      }else{
        ph=g_hh; pl=g_hl; off=(size_t)node*K1+c8-K0;
      }
      cpa16(Ah+(size_t)row*SKA+c8, ph+off);
      cpa16(Al+(size_t)row*SKA+c8, pl+off);
    }else{
      uint4 z=make_uint4(0,0,0,0);
      *(uint4*)(Ah+(size_t)row*SKA+c8)=z;
      *(uint4*)(Al+(size_t)row*SKA+c8)=z;
    }
  }
  cpwait();
  __syncthreads();
  wmma_core<KT>(Ah,Al,Bh,Bl,D,wid);
  int C0=(wid>>2)*32, R=(wid&3)*32+lane, node=base+R;
  float v[32];
#pragma unroll
  for(int j=0;j<32;j++)v[j]=D[(size_t)R*DST+C0+j];
  if(EPI==1){
    if(node<NN){
      float* qr=g_q+(size_t)node*128+C0;
#pragma unroll
      for(int j=0;j<32;j+=4)*(float4*)(qr+j)=make_float4(v[j],v[j+1],v[j+2],v[j+3]);
    }
  }else if(EPI==0){
#pragma unroll
    for(int j=0;j<32;j++)v[j]=fmaxf(v[j]+bias[C0+j],0.f);
    if(node<NN){
      u32 hw[16],lw[16];
#pragma unroll
      for(int j=0;j<16;j++)split2(v[2*j],v[2*j+1],hw[j],lw[j]);
      uint4* oh=(uint4*)(g_hh+(size_t)node*128+C0);
      uint4* ol=(uint4*)(g_hl+(size_t)node*128+C0);
#pragma unroll
      for(int j=0;j<4;j++){oh[j]=((uint4*)hw)[j];ol[j]=((uint4*)lw)[j];}
    }
  }else{
    float s=0.f,s2=0.f;
#pragma unroll
    for(int j=0;j<32;j++){v[j]=fmaxf(v[j]+bias[C0+j],0.f); s+=v[j]; s2+=v[j]*v[j];}
    sr1[(wid>>2)*128+R]=s; sr2[(wid>>2)*128+R]=s2;
    __syncthreads();
    s=sr1[R]+sr1[128+R]+sr1[256+R]+sr1[384+R];
    s2=sr2[R]+sr2[128+R]+sr2[256+R]+sr2[384+R];
    float mu=s*(1.f/128.f), var=fmaxf(s2*(1.f/128.f)-mu*mu,0.f), rs=rsqrtf(var+1e-5f);
#pragma unroll
    for(int j=0;j<32;j++)D[(size_t)R*DST+C0+j]=(v[j]-mu)*rs*lg[C0+j]+lb[C0+j];
    __syncthreads();
    if(EPI==2){
      if(tid<128){
        int col=tid; float a=0.f; int cur=-1;
        for(int r=0;r<128;r++){
          int bi=sbid[r];
          if(bi!=cur){ if(cur>=0)atomicAdd(&g_gsum[cur*128+col],a); a=0.f; cur=bi; }
          if(bi>=0)a+=D[(size_t)r*DST+col];
        }
        if(cur>=0)atomicAdd(&g_gsum[cur*128+col],a);
      }
    }else{
      float* xsh=(float*)(smx+HDR+ABYTES);
      float* dsh=xsh+8192;
      for(int i=tid;i<8192;i+=512){int r=i>>6,k=i&63;int nd=base+r;xsh[i]=(nd<NN)?x[(size_t)nd*64+k]:0.f;}
      for(int i=tid;i<6144;i+=512)dsh[DS_DW1+i]=dW1[i];
      if(tid<32)dsh[DS_DB1+tid]=db1[tid];
      if(tid<256)dsh[DS_DW2+tid]=dW2[tid];
      if(tid<8){dsh[DS_DB2+tid]=db2[tid];dsh[DS_DW3+tid]=dW3[tid];}
      if(tid==0)dsh[DS_DB3]=db3[0];
      __syncthreads();
      int j=lane, r0=wid*8;
      for(int i=0;i<8;i++){
        int row=r0+i, nd=base+row;
        float s1=dsh[DS_DB1+j];
        const float* xr=xsh+(size_t)row*64;
        const float* nr=D+(size_t)row*DST;
#pragma unroll 4
        for(int k=0;k<64;k++)s1=fmaf(xr[k],dsh[DS_DW1+k*32+j],s1);
#pragma unroll 4
        for(int k=0;k<128;k++)s1=fmaf(nr[k],dsh[DS_DW1+(64+k)*32+j],s1);
        s1=fmaxf(s1,0.f);
        float t2[8];
#pragma unroll
        for(int m=0;m<8;m++)t2[m]=s1*dsh[DS_DW2+j*8+m];
#pragma unroll
        for(int o=16;o>0;o>>=1)
#pragma unroll
          for(int m=0;m<8;m++)t2[m]+=__shfl_xor_sync(~0u,t2[m],o);
        float out=dsh[DS_DB3];
#pragma unroll
        for(int m=0;m<8;m++)out=fmaf(fmaxf(t2[m]+dsh[DS_DB2+m],0.f),dsh[DS_DW3+m],out);
        if(j==0&&nd<NN)outp[nd]=out;
      }
    }
  }
}

// ---- GIN GEMM2: A = relu((1+eps)q + agg + b1); epilogue LN+ELU -> planes ----
__global__ void __launch_bounds__(512,1) k_mmu(
    const float* __restrict__ eps,int layer,
    const float* __restrict__ b1,const float* __restrict__ b2,
    const float* __restrict__ lng,const float* __restrict__ lnb,int woff)
{
  constexpr int KT=128, SKA=KT+8;
  constexpr int ABYTES=2*128*SKA*2;
  extern __shared__ unsigned char smx[];
  float* sr1=(float*)(smx+576);
  float* sr2=(float*)(smx+2624);
  __nv_bfloat16* Ah=(__nv_bfloat16*)(smx+HDR);
  __nv_bfloat16* Al=Ah+(size_t)128*SKA;
  __nv_bfloat16* Bh=(__nv_bfloat16*)(smx+HDR+ABYTES);
  __nv_bfloat16* Bl=Bh+(size_t)KT*SNB;
  float* D=(float*)(smx+HDR);
  int tid=threadIdx.x,lane=tid&31,wid=tid>>5;
  int base=blockIdx.x*128;
  float e1=1.f+eps[layer];
  {
    const __nv_bfloat16* ws=g_wimg+woff;
    for(int i=tid;i<KT*16;i+=512){
      int k=i>>4,c8=(i&15)*8;
      cpa16(Bh+(size_t)k*SNB+c8, ws+(size_t)k*128+c8);
      cpa16(Bl+(size_t)k*SNB+c8, ws+(size_t)(KT+k)*128+c8);
    }
  }
  for(int i=tid;i<128*16;i+=512){
    int row=i>>4, c8=(i&15)*8, node=base+row;
    uint4 hv=make_uint4(0,0,0,0), lv=hv;
    if(node<NN){
      const float* qr=g_q+(size_t)node*128+c8;
      const float* ar=g_agg+(size_t)node*128+c8;
      float4 qa=*(const float4*)qr, qb=*(const float4*)(qr+4);
      float4 aa=*(const float4*)ar, ab=*(const float4*)(ar+4);
      float u0=fmaxf(fmaf(e1,qa.x,aa.x)+b1[c8+0],0.f);
      float u1=fmaxf(fmaf(e1,qa.y,aa.y)+b1[c8+1],0.f);
      float u2=fmaxf(fmaf(e1,qa.z,aa.z)+b1[c8+2],0.f);
      float u3=fmaxf(fmaf(e1,qa.w,aa.w)+b1[c8+3],0.f);
      float u4=fmaxf(fmaf(e1,qb.x,ab.x)+b1[c8+4],0.f);
      float u5=fmaxf(fmaf(e1,qb.y,ab.y)+b1[c8+5],0.f);
      float u6=fmaxf(fmaf(e1,qb.z,ab.z)+b1[c8+6],0.f);
      float u7=fmaxf(fmaf(e1,qb.w,ab.w)+b1[c8+7],0.f);
      u32 hw[4],lw[4];
      split2(u0,u1,hw[0],lw[0]); split2(u2,u3,hw[1],lw[1]);
      split2(u4,u5,hw[2],lw[2]); split2(u6,u7,hw[3],lw[3]);
      hv=*(uint4*)hw; lv=*(uint4*)lw;
    }
    *(uint4*)(Ah+(size_t)row*SKA+c8)=hv;
    *(uint4*)(Al+(size_t)row*SKA+c8)=lv;
  }
  cpwait();
  __syncthreads();
  wmma_core<KT>(Ah,Al,Bh,Bl,D,wid);
  int C0=(wid>>2)*32, R=(wid&3)*32+lane, node=base+R;
  float v[32]; float s=0.f,s2=0.f;
#pragma unroll
  for(int j=0;j<32;j++){v[j]=D[(size_t)R*DST+C0+j]+b2[C0+j]; s+=v[j]; s2+=v[j]*v[j];}
  sr1[(wid>>2)*128+R]=s; sr2[(wid>>2)*128+R]=s2;
  __syncthreads();
  s=sr1[R]+sr1[128+R]+sr1[256+R]+sr1[384+R];
  s2=sr2[R]+sr2[128+R]+sr2[256+R]+sr2[384+R];
  float mu=s*(1.f/128.f), var=fmaxf(s2*(1.f/128.f)-mu*mu,0.f), rs=rsqrtf(var+1e-5f);
  if(node<NN){
    u32 hw[16],lw[16];
#pragma unroll
    for(int j=0;j<16;j++){
      float n0=(v[2*j]-mu)*rs*lng[C0+2*j]+lnb[C0+2*j];
      float n1=(v[2*j+1]-mu)*rs*lng[C0+2*j+1]+lnb[C0+2*j+1];
      n0=(n0>0.f)?n0:expm1f(n0);
      n1=(n1>0.f)?n1:expm1f(n1);
      split2(n0,n1,hw[j],lw[j]);
    }
    uint4* oh=(uint4*)(g_hh+(size_t)node*128+C0);
    uint4* ol=(uint4*)(g_hl+(size_t)node*128+C0);
#pragma unroll
    for(int j=0;j<4;j++){oh[j]=((uint4*)hw)[j];ol[j]=((uint4*)lw)[j];}
  }
}

// ---- graph-level MLP ----
__device__ __forceinline__ int lbound(const int* __restrict__ a,int n,int v){
  int lo=0,hi=n;
  while(lo<hi){int m=(lo+hi)>>1; if(a[m]<v)lo=m+1; else hi=m;}
  return lo;
}
__global__ void k_gmlp(const int* __restrict__ bidx,
    const float* __restrict__ gW1,const float* __restrict__ gb1,
    const float* __restrict__ gW2,const float* __restrict__ gb2,
    const float* __restrict__ gW3,const float* __restrict__ gb3,
    float* __restrict__ outp){
  int tid=threadIdx.x,lane=tid&31;
  int g=blockIdx.x*8+(tid>>5);
  int lo=lbound(bidx,NN,g),hi=lbound(bidx,NN,g+1);
  float inv=1.f/fmaxf((float)(hi-lo),1.f);
  float s1=gb1[lane];
  for(int k=0;k<128;k++)s1=fmaf(g_gsum[g*128+k]*inv,gW1[k*32+lane],s1);
  s1=fmaxf(s1,0.f);
  float t2[8];
#pragma unroll
  for(int m=0;m<8;m++)t2[m]=s1*gW2[lane*8+m];
#pragma unroll
  for(int o=16;o>0;o>>=1)
#pragma unroll
    for(int m=0;m<8;m++)t2[m]+=__shfl_xor_sync(~0u,t2[m],o);
  float out=gb3[0];
#pragma unroll
  for(int m=0;m<8;m++)out=fmaf(fmaxf(t2[m]+gb2[m],0.f),gW3[m],out);
  if(lane==0)outp[NN+g]=out;
}

extern "C" void kernel_launch(void* const* d_in,const int* in_sizes,int n_in,
                              void* d_out,int out_size){
  (void)in_sizes;(void)n_in;(void)out_size;
  const float* x   =(const float*)d_in[0];
  const int*   ei  =(const int*)  d_in[1];
  const int*   bidx=(const int*)  d_in[2];
  const float* W_in=(const float*)d_in[3];
  const float* b_in=(const float*)d_in[4];
  const float* eps =(const float*)d_in[5];
  const float* mW1 =(const float*)d_in[6];
  const float* mb1 =(const float*)d_in[7];
  const float* mW2 =(const float*)d_in[8];
  const float* mb2 =(const float*)d_in[9];
  const float* lng =(const float*)d_in[10];
  const float* lnb =(const float*)d_in[11];
  const float* oW  =(const float*)d_in[12];
  const float* ob  =(const float*)d_in[13];
  const float* lfg =(const float*)d_in[14];
  const float* lfb =(const float*)d_in[15];
  const float* gW  =(const float*)d_in[16];
  const float* gb  =(const float*)d_in[17];
  const float* glg =(const float*)d_in[18];
  const float* glb =(const float*)d_in[19];
  const float* dW1 =(const float*)d_in[20];
  const float* db1 =(const float*)d_in[21];
  const float* dW2 =(const float*)d_in[22];
  const float* db2 =(const float*)d_in[23];
  const float* dW3 =(const float*)d_in[24];
  const float* db3 =(const float*)d_in[25];
  const float* gW1 =(const float*)d_in[26];
  const float* gb1 =(const float*)d_in[27];
  const float* gW2 =(const float*)d_in[28];
  const float* gb2 =(const float*)d_in[29];
  const float* gW3 =(const float*)d_in[30];
  const float* gb3 =(const float*)d_in[31];
  float* outp=(float*)d_out;

  const int SM_ENC=HDR+2*128*72*2 +2*64*SNB*2;
  const int SM_192=HDR+2*128*200*2+2*192*SNB*2;
  const int SM_128=HDR+2*128*136*2+2*128*SNB*2;
  cudaFuncSetAttribute((const void*)k_mmp<64,0,0>,  cudaFuncAttributeMaxDynamicSharedMemorySize,SM_ENC);
  cudaFuncSetAttribute((const void*)k_mmp<64,128,1>,cudaFuncAttributeMaxDynamicSharedMemorySize,SM_192);
  cudaFuncSetAttribute((const void*)k_mmp<128,0,2>, cudaFuncAttributeMaxDynamicSharedMemorySize,SM_128);
  cudaFuncSetAttribute((const void*)k_mmp<128,0,3>, cudaFuncAttributeMaxDynamicSharedMemorySize,SM_128);
  cudaFuncSetAttribute((const void*)k_mmu,          cudaFuncAttributeMaxDynamicSharedMemorySize,SM_128);

  // GEMM-heavy prefix so the profiler slot lands on the K=192 GEMM
  k_prepx<<<12500,256>>>(x);                                             //0
  k_prepw<<<640,256>>>(W_in,mW1,mW2,gW,oW);                              //1
  k_mmp<64,0,0><<<782,512,SM_ENC>>>(b_in,nullptr,nullptr,0,nullptr,nullptr,
      nullptr,nullptr,nullptr,nullptr,nullptr,nullptr,nullptr);          //2
  k_mmp<64,128,1><<<782,512,SM_192>>>(nullptr,nullptr,nullptr,16384,nullptr,nullptr,
      nullptr,nullptr,nullptr,nullptr,nullptr,nullptr,nullptr);          //3 (GEMM1 l0)
  // CSR build
  k_zero<<<391,256>>>();                                                 //4
  k_hist<<<6250,256>>>(ei);                                              //5
  k_scan1<<<98,1024>>>();                                                //6
  k_scan2<<<1,128>>>();                                                  //7
  k_scan3<<<98,1024>>>();                                                //8
  k_fill<<<6250,256>>>(ei);                                              //9

  for(int l=0;l<3;l++){
    k_gather<<<12500,256>>>();
    k_mmu<<<782,512,SM_128>>>(eps,l,mb1+l*128,mb2+l*128,lng+l*128,lnb+l*128,163840+l*32768);
    if(l<2)
      k_mmp<64,128,1><<<782,512,SM_192>>>(nullptr,nullptr,nullptr,16384+(l+1)*49152,nullptr,nullptr,
          nullptr,nullptr,nullptr,nullptr,nullptr,nullptr,nullptr);
  }
  k_mmp<128,0,2><<<782,512,SM_128>>>(gb,glg,glb,262144,bidx,nullptr,
      nullptr,nullptr,nullptr,nullptr,nullptr,nullptr,nullptr);
  k_mmp<128,0,3><<<782,512,SM_128>>>(ob,lfg,lfb,294912,nullptr,x,
      dW1,db1,dW2,db2,dW3,db3,outp);
  k_gmlp<<<32,256>>>(bidx,gW1,gb1,gW2,gb2,gW3,gb3,outp);
}

// round 6
// speedup vs baseline: 1.7266x; 1.1141x over previous
#include <cuda_runtime.h>
#include <cuda_bf16.h>
#include <mma.h>

#define NN 100000
#define EE 1600000
#define BB 256
typedef unsigned long long u64;
typedef unsigned int u32;
using namespace nvcuda;

// ---- static scratch ----
__device__ __align__(16) __nv_bfloat16 g_xh[NN*64], g_xl[NN*64];
__device__ __align__(16) __nv_bfloat16 g_hh[NN*128], g_hl[NN*128];
__device__ __align__(16) __nv_bfloat16 g_uh[NN*128], g_ul[NN*128];
__device__ __align__(16) __nv_bfloat16 g_wimg[327680];
__device__ float g_q[NN*128];
__device__ float g_gsum[BB*128];
__device__ int g_deg[NN], g_rowptr[NN+1], g_cursor[NN], g_col[EE];
__device__ int g_bsum[128], g_boff[128];

__device__ __forceinline__ void split2(float a,float b,u32&h,u32&l){
  __nv_bfloat162 hh2=__floats2bfloat162_rn(a,b);
  float ra=a-__bfloat162float(hh2.x), rb=b-__bfloat162float(hh2.y);
  __nv_bfloat162 ll2=__floats2bfloat162_rn(ra,rb);
  h=*(u32*)&hh2; l=*(u32*)&ll2;
}
__device__ __forceinline__ void cpa16(void* dst,const void* src){
  u32 d=(u32)__cvta_generic_to_shared(dst);
  asm volatile("cp.async.cg.shared.global [%0],[%1],16;"::"r"(d),"l"(src));
}
__device__ __forceinline__ void cpcommit(){ asm volatile("cp.async.commit_group;":::"memory"); }
template<int N> __device__ __forceinline__ void cpwaitg(){ asm volatile("cp.async.wait_group %0;"::"n"(N):"memory"); }

// ---- CSR ----
__global__ void k_zero(){int i=blockIdx.x*blockDim.x+threadIdx.x; if(i<NN)g_deg[i]=0; if(i<BB*128)g_gsum[i]=0.f;}
__global__ void k_hist(const int* __restrict__ ei){int e=blockIdx.x*blockDim.x+threadIdx.x; if(e<EE)atomicAdd(&g_deg[ei[EE+e]],1);}
__global__ void k_scan1(){
  __shared__ int ws[32];
  int tid=threadIdx.x,lane=tid&31,wid=tid>>5;
  int i=blockIdx.x*1024+tid;
  int v=(i<NN)?g_deg[i]:0;
  int x=v;
#pragma unroll
  for(int o=16;o>0;o>>=1)x+=__shfl_xor_sync(~0u,x,o);
  if(lane==0)ws[wid]=x;
  __syncthreads();
  if(tid==0){int s=0;
#pragma unroll
    for(int w=0;w<32;w++)s+=ws[w];
    g_bsum[blockIdx.x]=s;}
}
__global__ void k_scan2(){
  __shared__ int ws[4];
  int tid=threadIdx.x,lane=tid&31,wid=tid>>5;
  int v=(tid<98)?g_bsum[tid]:0;
  int x=v;
#pragma unroll
  for(int o=1;o<32;o<<=1){int t=__shfl_up_sync(~0u,x,o); if(lane>=o)x+=t;}
  if(lane==31)ws[wid]=x;
  __syncthreads();
  int add=0;
  for(int w=0;w<wid;w++)add+=ws[w];
  if(tid<98)g_boff[tid]=add+x-v;
  if(tid==0)g_rowptr[NN]=EE;
}
__global__ void k_scan3(){
  __shared__ int ws[32];
  int tid=threadIdx.x,lane=tid&31,wid=tid>>5;
  int i=blockIdx.x*1024+tid;
  int v=(i<NN)?g_deg[i]:0;
  int x=v;
#pragma unroll
  for(int o=1;o<32;o<<=1){int t=__shfl_up_sync(~0u,x,o); if(lane>=o)x+=t;}
  if(lane==31)ws[wid]=x;
  __syncthreads();
  if(wid==0){int y=ws[lane];
#pragma unroll
    for(int o=1;o<32;o<<=1){int t=__shfl_up_sync(~0u,y,o); if(lane>=o)y+=t;} ws[lane]=y;}
  __syncthreads();
  if(i<NN){
    int ex=g_boff[blockIdx.x]+x-v+((wid>0)?ws[wid-1]:0);
    g_rowptr[i]=ex; g_cursor[i]=ex;
  }
}
__global__ void k_fill(const int* __restrict__ ei){
  int e=blockIdx.x*blockDim.x+threadIdx.x;
  if(e<EE){int d=ei[EE+e]; int p=atomicAdd(&g_cursor[d],1); g_col[p]=ei[e];}
}

// ---- prep ----
__global__ void k_prepx(const float* __restrict__ x){
  int i=blockIdx.x*blockDim.x+threadIdx.x; if(i>=NN*32)return;
  float2 v=((const float2*)x)[i];
  u32 h,l; split2(v.x,v.y,h,l);
  ((u32*)g_xh)[i]=h; ((u32*)g_xl)[i]=l;
}
__global__ void k_prepw(const float* __restrict__ Win,const float* __restrict__ W1,
                        const float* __restrict__ W2,const float* __restrict__ gW,
                        const float* __restrict__ oW){
  int gid=blockIdx.x*blockDim.x+threadIdx.x; if(gid>=163840)return;
  const float* src; int idx,K; __nv_bfloat16* img;
  if(gid<8192){src=Win;idx=gid;K=64;img=g_wimg;}
  else if(gid<81920){int t=gid-8192;int l=t/24576;idx=t%24576;K=192;src=W1+l*24576;img=g_wimg+16384+l*49152;}
  else if(gid<131072){int t=gid-81920;int l=t/16384;idx=t%16384;K=128;src=W2+l*16384;img=g_wimg+163840+l*32768;}
  else if(gid<147456){idx=gid-131072;K=128;src=gW;img=g_wimg+262144;}
  else {idx=gid-147456;K=128;src=oW;img=g_wimg+294912;}
  float w=src[idx];
  __nv_bfloat16 h=__float2bfloat16(w);
  __nv_bfloat16 l=__float2bfloat16(w-__bfloat162float(h));
  img[idx]=h; img[K*128+idx]=l;
}

// ---- fused gather + GIN pre-act: u = relu((1+eps)q + sum_nbr q + b1) -> bf16 planes ----
__global__ void k_gatheru(const float* __restrict__ eps,int layer,const float* __restrict__ b1){
  int w=(blockIdx.x*blockDim.x+threadIdx.x)>>5, lane=threadIdx.x&31;
  if(w>=NN)return;
  float e1=1.f+eps[layer];
  int s=g_rowptr[w],t=g_rowptr[w+1];
  float4 a0=make_float4(0,0,0,0),a1=a0,a2=a0,a3=a0;
  int e=s;
  for(;e+4<=t;e+=4){
    int n0=g_col[e],n1=g_col[e+1],n2=g_col[e+2],n3=g_col[e+3];
    float4 v0=*(const float4*)(g_q+(size_t)n0*128+lane*4);
    float4 v1=*(const float4*)(g_q+(size_t)n1*128+lane*4);
    float4 v2=*(const float4*)(g_q+(size_t)n2*128+lane*4);
    float4 v3=*(const float4*)(g_q+(size_t)n3*128+lane*4);
    a0.x+=v0.x;a0.y+=v0.y;a0.z+=v0.z;a0.w+=v0.w;
    a1.x+=v1.x;a1.y+=v1.y;a1.z+=v1.z;a1.w+=v1.w;
    a2.x+=v2.x;a2.y+=v2.y;a2.z+=v2.z;a2.w+=v2.w;
    a3.x+=v3.x;a3.y+=v3.y;a3.z+=v3.z;a3.w+=v3.w;
  }
  for(;e<t;e++){
    int nb=g_col[e];
    float4 v=*(const float4*)(g_q+(size_t)nb*128+lane*4);
    a0.x+=v.x;a0.y+=v.y;a0.z+=v.z;a0.w+=v.w;
  }
  a0.x+=a1.x+a2.x+a3.x; a0.y+=a1.y+a2.y+a3.y;
  a0.z+=a1.z+a2.z+a3.z; a0.w+=a1.w+a2.w+a3.w;
  float4 qo=*(const float4*)(g_q+(size_t)w*128+lane*4);
  float4 bv=*(const float4*)(b1+lane*4);
  float u0=fmaxf(fmaf(e1,qo.x,a0.x)+bv.x,0.f);
  float u1=fmaxf(fmaf(e1,qo.y,a0.y)+bv.y,0.f);
  float u2=fmaxf(fmaf(e1,qo.z,a0.z)+bv.z,0.f);
  float u3=fmaxf(fmaf(e1,qo.w,a0.w)+bv.w,0.f);
  u32 h0,l0,h1,l1;
  split2(u0,u1,h0,l0); split2(u2,u3,h1,l1);
  *(uint2*)(g_uh+(size_t)w*128+lane*4)=make_uint2(h0,h1);
  *(uint2*)(g_ul+(size_t)w*128+lane*4)=make_uint2(l0,l1);
}

#define HDR 8192
#define SNB 136
#define SKA 72
#define DST 132
#define APL (128*SKA)
#define BPL (64*SNB)
#define SM_ALL (HDR + 2*2*APL*2 + 2*2*BPL*2)   // 8192+73728+69632 = 151552
#define DS_DW1 0
#define DS_DB1 6144
#define DS_DW2 6176
#define DS_DB2 6432
#define DS_DW3 6440
#define DS_DB3 6448

// ---- pipelined GEMM: ASRC 0=x,1=h,2=u planes for first K0 cols (rest = h planes).
// EPI: 0=relu+bias->h planes, 1=raw->q, 2=bias+relu+LN->pool, 3=bias+relu+LN->decoder, 4=bias+LN+ELU->h planes
template<int KT,int K0,int ASRC,int EPI>
__global__ void __launch_bounds__(512,1) k_mmp(
    int woff,const float* __restrict__ bias,const float* __restrict__ lg,const float* __restrict__ lb,
    const int* __restrict__ bidx,const float* __restrict__ x,
    const float* __restrict__ dW1,const float* __restrict__ db1,
    const float* __restrict__ dW2,const float* __restrict__ db2,
    const float* __restrict__ dW3,const float* __restrict__ db3,
    float* __restrict__ outp)
{
  constexpr int C=KT/64;
  extern __shared__ unsigned char smx[];
  int* sbid=(int*)(smx+64);
  float* sr1=(float*)(smx+576);
  float* sr2=(float*)(smx+2624);
  __nv_bfloat16* As=(__nv_bfloat16*)(smx+HDR);
  __nv_bfloat16* Bs=(__nv_bfloat16*)(smx+HDR+2*2*APL*2);
  float* D=(float*)(smx+HDR);
  int tid=threadIdx.x,lane=tid&31,wid=tid>>5;
  int base=blockIdx.x*128;
  const __nv_bfloat16 *p0h,*p0l;
  if(ASRC==0){p0h=g_xh;p0l=g_xl;}
  else if(ASRC==2){p0h=g_uh;p0l=g_ul;}
  else {p0h=g_hh;p0l=g_hl;}
  if(EPI==2&&tid<128){int nd=base+tid; sbid[tid]=(nd<NN)?bidx[nd]:-1;}

  auto stage=[&](int c,int buf){
    const __nv_bfloat16* ws=g_wimg+woff;
    for(int i=tid;i<2048;i+=512){
      int pl=i>>10,j=i&1023,kk=j>>4,u=j&15;
      cpa16(Bs+(size_t)(buf*2+pl)*BPL+kk*SNB+u*8,
            ws+(size_t)pl*KT*128+(size_t)(c*64+kk)*128+u*8);
    }
    for(int i=tid;i<2048;i+=512){
      int pl=i>>10,j=i&1023,row=j>>3,u=j&7;
      int gc=c*64+u*8, node=base+row;
      __nv_bfloat16* dst=As+(size_t)(buf*2+pl)*APL+row*SKA+u*8;
      if(node<NN){
        const __nv_bfloat16* srcp;
        if(gc<K0) srcp=(pl?p0l:p0h)+(size_t)node*K0+gc;
        else      srcp=(pl?g_hl:g_hh)+(size_t)node*128+gc-K0;
        cpa16(dst,srcp);
      }else *(uint4*)dst=make_uint4(0,0,0,0);
    }
  };

  wmma::fragment<wmma::accumulator,16,16,16,float> a00,a01,a10,a11;
  wmma::fill_fragment(a00,0.f); wmma::fill_fragment(a01,0.f);
  wmma::fill_fragment(a10,0.f); wmma::fill_fragment(a11,0.f);
  int r0=(wid&3)*32, cw=(wid>>2)*32;

  stage(0,0); cpcommit();
  for(int c=0;c<C;c++){
    int buf=c&1;
    if(c+1<C){ stage(c+1,buf^1); cpcommit(); cpwaitg<1>(); }
    else cpwaitg<0>();
    __syncthreads();
    const __nv_bfloat16* Ah=As+(size_t)(buf*2)*APL;
    const __nv_bfloat16* Al=Ah+APL;
    const __nv_bfloat16* Bh=Bs+(size_t)(buf*2)*BPL;
    const __nv_bfloat16* Bl=Bh+BPL;
#pragma unroll
    for(int kc=0;kc<4;kc++){
      wmma::fragment<wmma::matrix_a,16,16,16,__nv_bfloat16,wmma::row_major> ah0,ah1,al0,al1;
      wmma::load_matrix_sync(ah0,Ah+(size_t)r0*SKA+kc*16,SKA);
      wmma::load_matrix_sync(ah1,Ah+(size_t)(r0+16)*SKA+kc*16,SKA);
      wmma::load_matrix_sync(al0,Al+(size_t)r0*SKA+kc*16,SKA);
      wmma::load_matrix_sync(al1,Al+(size_t)(r0+16)*SKA+kc*16,SKA);
      wmma::fragment<wmma::matrix_b,16,16,16,__nv_bfloat16,wmma::row_major> bh0,bh1,bl0,bl1;
      wmma::load_matrix_sync(bh0,Bh+(size_t)(kc*16)*SNB+cw,SNB);
      wmma::load_matrix_sync(bh1,Bh+(size_t)(kc*16)*SNB+cw+16,SNB);
      wmma::load_matrix_sync(bl0,Bl+(size_t)(kc*16)*SNB+cw,SNB);
      wmma::load_matrix_sync(bl1,Bl+(size_t)(kc*16)*SNB+cw+16,SNB);
      wmma::mma_sync(a00,ah0,bh0,a00); wmma::mma_sync(a00,al0,bh0,a00); wmma::mma_sync(a00,ah0,bl0,a00);
      wmma::mma_sync(a01,ah0,bh1,a01); wmma::mma_sync(a01,al0,bh1,a01); wmma::mma_sync(a01,ah0,bl1,a01);
      wmma::mma_sync(a10,ah1,bh0,a10); wmma::mma_sync(a10,al1,bh0,a10); wmma::mma_sync(a10,ah1,bl0,a10);
      wmma::mma_sync(a11,ah1,bh1,a11); wmma::mma_sync(a11,al1,bh1,a11); wmma::mma_sync(a11,ah1,bl1,a11);
    }
    __syncthreads();
  }
  wmma::store_matrix_sync(D+(size_t)r0*DST+cw,a00,DST,wmma::mem_row_major);
  wmma::store_matrix_sync(D+(size_t)r0*DST+cw+16,a01,DST,wmma::mem_row_major);
  wmma::store_matrix_sync(D+(size_t)(r0+16)*DST+cw,a10,DST,wmma::mem_row_major);
  wmma::store_matrix_sync(D+(size_t)(r0+16)*DST+cw+16,a11,DST,wmma::mem_row_major);
  __syncthreads();

  int C0=(wid>>2)*32, R=(wid&3)*32+lane, node=base+R;
  float v[32];
#pragma unroll
  for(int j=0;j<32;j++)v[j]=D[(size_t)R*DST+C0+j];
  if(EPI==1){
    if(node<NN){
      float* qr=g_q+(size_t)node*128+C0;
#pragma unroll
      for(int j=0;j<32;j+=4)*(float4*)(qr+j)=make_float4(v[j],v[j+1],v[j+2],v[j+3]);
    }
  }else if(EPI==0){
#pragma unroll
    for(int j=0;j<32;j++)v[j]=fmaxf(v[j]+bias[C0+j],0.f);
    if(node<NN){
      u32 hw[16],lw[16];
#pragma unroll
      for(int j=0;j<16;j++)split2(v[2*j],v[2*j+1],hw[j],lw[j]);
      uint4* oh=(uint4*)(g_hh+(size_t)node*128+C0);
      uint4* ol=(uint4*)(g_hl+(size_t)node*128+C0);
#pragma unroll
      for(int j=0;j<4;j++){oh[j]=((uint4*)hw)[j];ol[j]=((uint4*)lw)[j];}
    }
  }else if(EPI==4){
    float s=0.f,s2=0.f;
#pragma unroll
    for(int j=0;j<32;j++){v[j]+=bias[C0+j]; s+=v[j]; s2+=v[j]*v[j];}
    sr1[(wid>>2)*128+R]=s; sr2[(wid>>2)*128+R]=s2;
    __syncthreads();
    s=sr1[R]+sr1[128+R]+sr1[256+R]+sr1[384+R];
    s2=sr2[R]+sr2[128+R]+sr2[256+R]+sr2[384+R];
    float mu=s*(1.f/128.f), var=fmaxf(s2*(1.f/128.f)-mu*mu,0.f), rs=rsqrtf(var+1e-5f);
    if(node<NN){
      u32 hw[16],lw[16];
#pragma unroll
      for(int j=0;j<16;j++){
        float n0=(v[2*j]-mu)*rs*lg[C0+2*j]+lb[C0+2*j];
        float n1=(v[2*j+1]-mu)*rs*lg[C0+2*j+1]+lb[C0+2*j+1];
        n0=(n0>0.f)?n0:expm1f(n0);
        n1=(n1>0.f)?n1:expm1f(n1);
        split2(n0,n1,hw[j],lw[j]);
      }
      uint4* oh=(uint4*)(g_hh+(size_t)node*128+C0);
      uint4* ol=(uint4*)(g_hl+(size_t)node*128+C0);
#pragma unroll
      for(int j=0;j<4;j++){oh[j]=((uint4*)hw)[j];ol[j]=((uint4*)lw)[j];}
    }
  }else{ // EPI 2/3: bias+relu+LN
    float s=0.f,s2=0.f;
#pragma unroll
    for(int j=0;j<32;j++){v[j]=fmaxf(v[j]+bias[C0+j],0.f); s+=v[j]; s2+=v[j]*v[j];}
    sr1[(wid>>2)*128+R]=s; sr2[(wid>>2)*128+R]=s2;
    __syncthreads();
    s=sr1[R]+sr1[128+R]+sr1[256+R]+sr1[384+R];
    s2=sr2[R]+sr2[128+R]+sr2[256+R]+sr2[384+R];
    float mu=s*(1.f/128.f), var=fmaxf(s2*(1.f/128.f)-mu*mu,0.f), rs=rsqrtf(var+1e-5f);
#pragma unroll
    for(int j=0;j<32;j++)D[(size_t)R*DST+C0+j]=(v[j]-mu)*rs*lg[C0+j]+lb[C0+j];
    __syncthreads();
    if(EPI==2){
      if(tid<128){
        int col=tid; float a=0.f; int cur=-1;
        for(int r=0;r<128;r++){
          int bi=sbid[r];
          if(bi!=cur){ if(cur>=0)atomicAdd(&g_gsum[cur*128+col],a); a=0.f; cur=bi; }
          if(bi>=0)a+=D[(size_t)r*DST+col];
        }
        if(cur>=0)atomicAdd(&g_gsum[cur*128+col],a);
      }
    }else{
      float* xsh=(float*)Bs;
      float* dsh=xsh+8192;
      for(int i=tid;i<8192;i+=512){int r=i>>6,k=i&63;int nd=base+r;xsh[i]=(nd<NN)?x[(size_t)nd*64+k]:0.f;}
      for(int i=tid;i<6144;i+=512)dsh[DS_DW1+i]=dW1[i];
      if(tid<32)dsh[DS_DB1+tid]=db1[tid];
      if(tid<256)dsh[DS_DW2+tid]=dW2[tid];
      if(tid<8){dsh[DS_DB2+tid]=db2[tid];dsh[DS_DW3+tid]=dW3[tid];}
      if(tid==0)dsh[DS_DB3]=db3[0];
      __syncthreads();
      int j=lane, rr0=wid*8;
      for(int i=0;i<8;i++){
        int row=rr0+i, nd=base+row;
        float s1=dsh[DS_DB1+j];
        const float* xr=xsh+(size_t)row*64;
        const float* nr=D+(size_t)row*DST;
#pragma unroll 4
        for(int k=0;k<64;k++)s1=fmaf(xr[k],dsh[DS_DW1+k*32+j],s1);
#pragma unroll 4
        for(int k=0;k<128;k++)s1=fmaf(nr[k],dsh[DS_DW1+(64+k)*32+j],s1);
        s1=fmaxf(s1,0.f);
        float t2[8];
#pragma unroll
        for(int m=0;m<8;m++)t2[m]=s1*dsh[DS_DW2+j*8+m];
#pragma unroll
        for(int o=16;o>0;o>>=1)
#pragma unroll
          for(int m=0;m<8;m++)t2[m]+=__shfl_xor_sync(~0u,t2[m],o);
        float out=dsh[DS_DB3];
#pragma unroll
        for(int m=0;m<8;m++)out=fmaf(fmaxf(t2[m]+dsh[DS_DB2+m],0.f),dsh[DS_DW3+m],out);
        if(j==0&&nd<NN)outp[nd]=out;
      }
    }
  }
}

// ---- graph-level MLP ----
__device__ __forceinline__ int lbound(const int* __restrict__ a,int n,int v){
  int lo=0,hi=n;
  while(lo<hi){int m=(lo+hi)>>1; if(a[m]<v)lo=m+1; else hi=m;}
  return lo;
}
__global__ void k_gmlp(const int* __restrict__ bidx,
    const float* __restrict__ gW1,const float* __restrict__ gb1,
    const float* __restrict__ gW2,const float* __restrict__ gb2,
    const float* __restrict__ gW3,const float* __restrict__ gb3,
    float* __restrict__ outp){
  int tid=threadIdx.x,lane=tid&31;
  int g=blockIdx.x*8+(tid>>5);
  int lo=lbound(bidx,NN,g),hi=lbound(bidx,NN,g+1);
  float inv=1.f/fmaxf((float)(hi-lo),1.f);
  float s1=gb1[lane];
  for(int k=0;k<128;k++)s1=fmaf(g_gsum[g*128+k]*inv,gW1[k*32+lane],s1);
  s1=fmaxf(s1,0.f);
  float t2[8];
#pragma unroll
  for(int m=0;m<8;m++)t2[m]=s1*gW2[lane*8+m];
#pragma unroll
  for(int o=16;o>0;o>>=1)
#pragma unroll
    for(int m=0;m<8;m++)t2[m]+=__shfl_xor_sync(~0u,t2[m],o);
  float out=gb3[0];
#pragma unroll
  for(int m=0;m<8;m++)out=fmaf(fmaxf(t2[m]+gb2[m],0.f),gW3[m],out);
  if(lane==0)outp[NN+g]=out;
}

extern "C" void kernel_launch(void* const* d_in,const int* in_sizes,int n_in,
                              void* d_out,int out_size){
  (void)in_sizes;(void)n_in;(void)out_size;
  const float* x   =(const float*)d_in[0];
  const int*   ei  =(const int*)  d_in[1];
  const int*   bidx=(const int*)  d_in[2];
  const float* W_in=(const float*)d_in[3];
  const float* b_in=(const float*)d_in[4];
  const float* eps =(const float*)d_in[5];
  const float* mW1 =(const float*)d_in[6];
  const float* mb1 =(const float*)d_in[7];
  const float* mW2 =(const float*)d_in[8];
  const float* mb2 =(const float*)d_in[9];
  const float* lng =(const float*)d_in[10];
  const float* lnb =(const float*)d_in[11];
  const float* oW  =(const float*)d_in[12];
  const float* ob  =(const float*)d_in[13];
  const float* lfg =(const float*)d_in[14];
  const float* lfb =(const float*)d_in[15];
  const float* gW  =(const float*)d_in[16];
  const float* gb  =(const float*)d_in[17];
  const float* glg =(const float*)d_in[18];
  const float* glb =(const float*)d_in[19];
  const float* dW1 =(const float*)d_in[20];
  const float* db1 =(const float*)d_in[21];
  const float* dW2 =(const float*)d_in[22];
  const float* db2 =(const float*)d_in[23];
  const float* dW3 =(const float*)d_in[24];
  const float* db3 =(const float*)d_in[25];
  const float* gW1 =(const float*)d_in[26];
  const float* gb1 =(const float*)d_in[27];
  const float* gW2 =(const float*)d_in[28];
  const float* gb2 =(const float*)d_in[29];
  const float* gW3 =(const float*)d_in[30];
  const float* gb3 =(const float*)d_in[31];
  float* outp=(float*)d_out;

  cudaFuncSetAttribute((const void*)k_mmp<64,64,0,0>,   cudaFuncAttributeMaxDynamicSharedMemorySize,SM_ALL);
  cudaFuncSetAttribute((const void*)k_mmp<192,64,0,1>,  cudaFuncAttributeMaxDynamicSharedMemorySize,SM_ALL);
  cudaFuncSetAttribute((const void*)k_mmp<128,128,2,4>, cudaFuncAttributeMaxDynamicSharedMemorySize,SM_ALL);
  cudaFuncSetAttribute((const void*)k_mmp<128,128,1,2>, cudaFuncAttributeMaxDynamicSharedMemorySize,SM_ALL);
  cudaFuncSetAttribute((const void*)k_mmp<128,128,1,3>, cudaFuncAttributeMaxDynamicSharedMemorySize,SM_ALL);

  k_prepx<<<12500,256>>>(x);                                             //0
  k_prepw<<<640,256>>>(W_in,mW1,mW2,gW,oW);                              //1
  k_mmp<64,64,0,0><<<782,512,SM_ALL>>>(0,b_in,nullptr,nullptr,nullptr,nullptr,
      nullptr,nullptr,nullptr,nullptr,nullptr,nullptr,nullptr);          //2 encoder
  k_mmp<192,64,0,1><<<782,512,SM_ALL>>>(16384,nullptr,nullptr,nullptr,nullptr,nullptr,
      nullptr,nullptr,nullptr,nullptr,nullptr,nullptr,nullptr);          //3 GEMM1 l0 (profiled)
  k_zero<<<391,256>>>();                                                 //4
  k_hist<<<6250,256>>>(ei);                                              //5
  k_scan1<<<98,1024>>>();                                                //6
  k_scan2<<<1,128>>>();                                                  //7
  k_scan3<<<98,1024>>>();                                                //8
  k_fill<<<6250,256>>>(ei);                                              //9

  for(int l=0;l<3;l++){
    k_gatheru<<<12500,256>>>(eps,l,mb1+l*128);
    k_mmp<128,128,2,4><<<782,512,SM_ALL>>>(163840+l*32768,mb2+l*128,lng+l*128,lnb+l*128,
        nullptr,nullptr,nullptr,nullptr,nullptr,nullptr,nullptr,nullptr,nullptr);
    if(l<2)
      k_mmp<192,64,0,1><<<782,512,SM_ALL>>>(16384+(l+1)*49152,nullptr,nullptr,nullptr,nullptr,nullptr,
          nullptr,nullptr,nullptr,nullptr,nullptr,nullptr,nullptr);
  }
  k_mmp<128,128,1,2><<<782,512,SM_ALL>>>(262144,gb,glg,glb,bidx,nullptr,
      nullptr,nullptr,nullptr,nullptr,nullptr,nullptr,nullptr);
  k_mmp<128,128,1,3><<<782,512,SM_ALL>>>(294912,ob,lfg,lfb,nullptr,x,
      dW1,db1,dW2,db2,dW3,db3,outp);
  k_gmlp<<<32,256>>>(bidx,gW1,gb1,gW2,gb2,gW3,gb3,outp);
}

// round 7
// speedup vs baseline: 1.8948x; 1.0974x over previous
#include <cuda_runtime.h>
#include <cuda_bf16.h>
#include <mma.h>

#define NN 100000
#define EE 1600000
#define BB 256
typedef unsigned long long u64;
typedef unsigned int u32;
using namespace nvcuda;

// ---- static scratch ----
__device__ __align__(16) __nv_bfloat16 g_xh[NN*64], g_xl[NN*64];
__device__ __align__(16) __nv_bfloat16 g_hh[NN*128], g_hl[NN*128];
__device__ __align__(16) __nv_bfloat16 g_uh[NN*128], g_ul[NN*128];
__device__ __align__(16) __nv_bfloat16 g_wimg[327680];
__device__ float g_q[NN*128];
__device__ float g_gsum[BB*128];
__device__ int g_deg[NN], g_rowptr[NN+1], g_cursor[NN], g_col[EE];
__device__ int g_bsum[128], g_boff[128];

__device__ __forceinline__ void split2(float a,float b,u32&h,u32&l){
  __nv_bfloat162 hh2=__floats2bfloat162_rn(a,b);
  float ra=a-__bfloat162float(hh2.x), rb=b-__bfloat162float(hh2.y);
  __nv_bfloat162 ll2=__floats2bfloat162_rn(ra,rb);
  h=*(u32*)&hh2; l=*(u32*)&ll2;
}
__device__ __forceinline__ void cpa16(void* dst,const void* src){
  u32 d=(u32)__cvta_generic_to_shared(dst);
  asm volatile("cp.async.cg.shared.global [%0],[%1],16;"::"r"(d),"l"(src));
}
__device__ __forceinline__ void cpcommit(){ asm volatile("cp.async.commit_group;":::"memory"); }
template<int N> __device__ __forceinline__ void cpwaitg(){ asm volatile("cp.async.wait_group %0;"::"n"(N):"memory"); }

// ---- CSR ----
__global__ void k_zero(){int i=blockIdx.x*blockDim.x+threadIdx.x; if(i<NN)g_deg[i]=0; if(i<BB*128)g_gsum[i]=0.f;}
__global__ void k_hist(const int* __restrict__ ei){int e=blockIdx.x*blockDim.x+threadIdx.x; if(e<EE)atomicAdd(&g_deg[ei[EE+e]],1);}
__global__ void k_scan1(){
  __shared__ int ws[32];
  int tid=threadIdx.x,lane=tid&31,wid=tid>>5;
  int i=blockIdx.x*1024+tid;
  int v=(i<NN)?g_deg[i]:0;
  int x=v;
#pragma unroll
  for(int o=16;o>0;o>>=1)x+=__shfl_xor_sync(~0u,x,o);
  if(lane==0)ws[wid]=x;
  __syncthreads();
  if(tid==0){int s=0;
#pragma unroll
    for(int w=0;w<32;w++)s+=ws[w];
    g_bsum[blockIdx.x]=s;}
}
__global__ void k_scan2(){
  __shared__ int ws[4];
  int tid=threadIdx.x,lane=tid&31,wid=tid>>5;
  int v=(tid<98)?g_bsum[tid]:0;
  int x=v;
#pragma unroll
  for(int o=1;o<32;o<<=1){int t=__shfl_up_sync(~0u,x,o); if(lane>=o)x+=t;}
  if(lane==31)ws[wid]=x;
  __syncthreads();
  int add=0;
  for(int w=0;w<wid;w++)add+=ws[w];
  if(tid<98)g_boff[tid]=add+x-v;
  if(tid==0)g_rowptr[NN]=EE;
}
__global__ void k_scan3(){
  __shared__ int ws[32];
  int tid=threadIdx.x,lane=tid&31,wid=tid>>5;
  int i=blockIdx.x*1024+tid;
  int v=(i<NN)?g_deg[i]:0;
  int x=v;
#pragma unroll
  for(int o=1;o<32;o<<=1){int t=__shfl_up_sync(~0u,x,o); if(lane>=o)x+=t;}
  if(lane==31)ws[wid]=x;
  __syncthreads();
  if(wid==0){int y=ws[lane];
#pragma unroll
    for(int o=1;o<32;o<<=1){int t=__shfl_up_sync(~0u,y,o); if(lane>=o)y+=t;} ws[lane]=y;}
  __syncthreads();
  if(i<NN){
    int ex=g_boff[blockIdx.x]+x-v+((wid>0)?ws[wid-1]:0);
    g_rowptr[i]=ex; g_cursor[i]=ex;
  }
}
__global__ void k_fill(const int* __restrict__ ei){
  int e=blockIdx.x*blockDim.x+threadIdx.x;
  if(e<EE){int d=ei[EE+e]; int p=atomicAdd(&g_cursor[d],1); g_col[p]=ei[e];}
}

// ---- prep ----
__global__ void k_prepx(const float* __restrict__ x){
  int i=blockIdx.x*blockDim.x+threadIdx.x; if(i>=NN*32)return;
  float2 v=((const float2*)x)[i];
  u32 h,l; split2(v.x,v.y,h,l);
  ((u32*)g_xh)[i]=h; ((u32*)g_xl)[i]=l;
}
__global__ void k_prepw(const float* __restrict__ Win,const float* __restrict__ W1,
                        const float* __restrict__ W2,const float* __restrict__ gW,
                        const float* __restrict__ oW){
  int gid=blockIdx.x*blockDim.x+threadIdx.x; if(gid>=163840)return;
  const float* src; int idx,K; __nv_bfloat16* img;
  if(gid<8192){src=Win;idx=gid;K=64;img=g_wimg;}
  else if(gid<81920){int t=gid-8192;int l=t/24576;idx=t%24576;K=192;src=W1+l*24576;img=g_wimg+16384+l*49152;}
  else if(gid<131072){int t=gid-81920;int l=t/16384;idx=t%16384;K=128;src=W2+l*16384;img=g_wimg+163840+l*32768;}
  else if(gid<147456){idx=gid-131072;K=128;src=gW;img=g_wimg+262144;}
  else {idx=gid-147456;K=128;src=oW;img=g_wimg+294912;}
  float w=src[idx];
  __nv_bfloat16 h=__float2bfloat16(w);
  __nv_bfloat16 l=__float2bfloat16(w-__bfloat162float(h));
  img[idx]=h; img[K*128+idx]=l;
}

// ---- fused gather + GIN pre-act: u = relu((1+eps)q + sum_nbr q + b1) -> bf16 planes ----
__global__ void k_gatheru(const float* __restrict__ eps,int layer,const float* __restrict__ b1){
  int w=(blockIdx.x*blockDim.x+threadIdx.x)>>5, lane=threadIdx.x&31;
  if(w>=NN)return;
  float e1=1.f+eps[layer];
  int s=g_rowptr[w],t=g_rowptr[w+1];
  float4 a0=make_float4(0,0,0,0),a1=a0,a2=a0,a3=a0;
  int e=s;
  for(;e+4<=t;e+=4){
    int n0=g_col[e],n1=g_col[e+1],n2=g_col[e+2],n3=g_col[e+3];
    float4 v0=*(const float4*)(g_q+(size_t)n0*128+lane*4);
    float4 v1=*(const float4*)(g_q+(size_t)n1*128+lane*4);
    float4 v2=*(const float4*)(g_q+(size_t)n2*128+lane*4);
    float4 v3=*(const float4*)(g_q+(size_t)n3*128+lane*4);
    a0.x+=v0.x;a0.y+=v0.y;a0.z+=v0.z;a0.w+=v0.w;
    a1.x+=v1.x;a1.y+=v1.y;a1.z+=v1.z;a1.w+=v1.w;
    a2.x+=v2.x;a2.y+=v2.y;a2.z+=v2.z;a2.w+=v2.w;
    a3.x+=v3.x;a3.y+=v3.y;a3.z+=v3.z;a3.w+=v3.w;
  }
  for(;e<t;e++){
    int nb=g_col[e];
    float4 v=*(const float4*)(g_q+(size_t)nb*128+lane*4);
    a0.x+=v.x;a0.y+=v.y;a0.z+=v.z;a0.w+=v.w;
  }
  a0.x+=a1.x+a2.x+a3.x; a0.y+=a1.y+a2.y+a3.y;
  a0.z+=a1.z+a2.z+a3.z; a0.w+=a1.w+a2.w+a3.w;
  float4 qo=*(const float4*)(g_q+(size_t)w*128+lane*4);
  float4 bv=*(const float4*)(b1+lane*4);
  float u0=fmaxf(fmaf(e1,qo.x,a0.x)+bv.x,0.f);
  float u1=fmaxf(fmaf(e1,qo.y,a0.y)+bv.y,0.f);
  float u2=fmaxf(fmaf(e1,qo.z,a0.z)+bv.z,0.f);
  float u3=fmaxf(fmaf(e1,qo.w,a0.w)+bv.w,0.f);
  u32 h0,l0,h1,l1;
  split2(u0,u1,h0,l0); split2(u2,u3,h1,l1);
  *(uint2*)(g_uh+(size_t)w*128+lane*4)=make_uint2(h0,h1);
  *(uint2*)(g_ul+(size_t)w*128+lane*4)=make_uint2(l0,l1);
}

// 64-row tiles, 256 threads, 2 CTAs/SM
#define HDR 4096
#define SNB 136
#define SKA 72
#define DST 132
#define TM 64
#define APL (TM*SKA)
#define BPL (64*SNB)
#define SM_ALL (HDR + 2*2*APL*2 + 2*2*BPL*2)   // 4096+36864+69632 = 110592
#define DS_DW1 0
#define DS_DB1 6144
#define DS_DW2 6176
#define DS_DB2 6432
#define DS_DW3 6440
#define DS_DB3 6448

// ---- pipelined GEMM: ASRC 0=x,1=h,2=u planes for first K0 cols (rest = h planes).
// EPI: 0=relu+bias->h planes, 1=raw->q, 2=bias+relu+LN->pool, 3=bias+relu+LN->decoder, 4=bias+LN+ELU->h planes
template<int KT,int K0,int ASRC,int EPI>
__global__ void __launch_bounds__(256,2) k_mmp(
    int woff,const float* __restrict__ bias,const float* __restrict__ lg,const float* __restrict__ lb,
    const int* __restrict__ bidx,const float* __restrict__ x,
    const float* __restrict__ dW1,const float* __restrict__ db1,
    const float* __restrict__ dW2,const float* __restrict__ db2,
    const float* __restrict__ dW3,const float* __restrict__ db3,
    float* __restrict__ outp)
{
  constexpr int C=KT/64;
  extern __shared__ unsigned char smx[];
  int* sbid=(int*)(smx);
  float* sr1=(float*)(smx+512);
  float* sr2=(float*)(smx+1536);
  __nv_bfloat16* As=(__nv_bfloat16*)(smx+HDR);
  __nv_bfloat16* Bs=(__nv_bfloat16*)(smx+HDR+2*2*APL*2);
  float* D=(float*)(smx+HDR);
  int tid=threadIdx.x,lane=tid&31,wid=tid>>5;
  int base=blockIdx.x*TM;
  const __nv_bfloat16 *p0h,*p0l;
  if(ASRC==0){p0h=g_xh;p0l=g_xl;}
  else if(ASRC==2){p0h=g_uh;p0l=g_ul;}
  else {p0h=g_hh;p0l=g_hl;}
  if(EPI==2&&tid<TM){int nd=base+tid; sbid[tid]=(nd<NN)?bidx[nd]:-1;}

  auto stage=[&](int c,int buf){
    const __nv_bfloat16* ws=g_wimg+woff;
    for(int i=tid;i<2048;i+=256){
      int pl=i>>10,j=i&1023,kk=j>>4,u=j&15;
      cpa16(Bs+(size_t)(buf*2+pl)*BPL+kk*SNB+u*8,
            ws+(size_t)pl*KT*128+(size_t)(c*64+kk)*128+u*8);
    }
    for(int i=tid;i<1024;i+=256){
      int pl=i>>9,j=i&511,row=j>>3,u=j&7;
      int gc=c*64+u*8, node=base+row;
      __nv_bfloat16* dst=As+(size_t)(buf*2+pl)*APL+row*SKA+u*8;
      if(node<NN){
        const __nv_bfloat16* srcp;
        if(gc<K0) srcp=(pl?p0l:p0h)+(size_t)node*K0+gc;
        else      srcp=(pl?g_hl:g_hh)+(size_t)node*128+gc-K0;
        cpa16(dst,srcp);
      }else *(uint4*)dst=make_uint4(0,0,0,0);
    }
  };

  // warp grid: 2 row-groups x 4 col-groups; warp tile 32x32
  wmma::fragment<wmma::accumulator,16,16,16,float> a00,a01,a10,a11;
  wmma::fill_fragment(a00,0.f); wmma::fill_fragment(a01,0.f);
  wmma::fill_fragment(a10,0.f); wmma::fill_fragment(a11,0.f);
  int r0=(wid&1)*32, cw=(wid>>1)*32;

  stage(0,0); cpcommit();
  for(int c=0;c<C;c++){
    int buf=c&1;
    if(c+1<C){ stage(c+1,buf^1); cpcommit(); cpwaitg<1>(); }
    else cpwaitg<0>();
    __syncthreads();
    const __nv_bfloat16* Ah=As+(size_t)(buf*2)*APL;
    const __nv_bfloat16* Al=Ah+APL;
    const __nv_bfloat16* Bh=Bs+(size_t)(buf*2)*BPL;
    const __nv_bfloat16* Bl=Bh+BPL;
#pragma unroll
    for(int kc=0;kc<4;kc++){
      wmma::fragment<wmma::matrix_a,16,16,16,__nv_bfloat16,wmma::row_major> ah0,ah1,al0,al1;
      wmma::load_matrix_sync(ah0,Ah+(size_t)r0*SKA+kc*16,SKA);
      wmma::load_matrix_sync(ah1,Ah+(size_t)(r0+16)*SKA+kc*16,SKA);
      wmma::load_matrix_sync(al0,Al+(size_t)r0*SKA+kc*16,SKA);
      wmma::load_matrix_sync(al1,Al+(size_t)(r0+16)*SKA+kc*16,SKA);
      wmma::fragment<wmma::matrix_b,16,16,16,__nv_bfloat16,wmma::row_major> bh0,bh1,bl0,bl1;
      wmma::load_matrix_sync(bh0,Bh+(size_t)(kc*16)*SNB+cw,SNB);
      wmma::load_matrix_sync(bh1,Bh+(size_t)(kc*16)*SNB+cw+16,SNB);
      wmma::load_matrix_sync(bl0,Bl+(size_t)(kc*16)*SNB+cw,SNB);
      wmma::load_matrix_sync(bl1,Bl+(size_t)(kc*16)*SNB+cw+16,SNB);
      wmma::mma_sync(a00,ah0,bh0,a00); wmma::mma_sync(a00,al0,bh0,a00); wmma::mma_sync(a00,ah0,bl0,a00);
      wmma::mma_sync(a01,ah0,bh1,a01); wmma::mma_sync(a01,al0,bh1,a01); wmma::mma_sync(a01,ah0,bl1,a01);
      wmma::mma_sync(a10,ah1,bh0,a10); wmma::mma_sync(a10,al1,bh0,a10); wmma::mma_sync(a10,ah1,bl0,a10);
      wmma::mma_sync(a11,ah1,bh1,a11); wmma::mma_sync(a11,al1,bh1,a11); wmma::mma_sync(a11,ah1,bl1,a11);
    }
    __syncthreads();
  }
  wmma::store_matrix_sync(D+(size_t)r0*DST+cw,a00,DST,wmma::mem_row_major);
  wmma::store_matrix_sync(D+(size_t)r0*DST+cw+16,a01,DST,wmma::mem_row_major);
  wmma::store_matrix_sync(D+(size_t)(r0+16)*DST+cw,a10,DST,wmma::mem_row_major);
  wmma::store_matrix_sync(D+(size_t)(r0+16)*DST+cw+16,a11,DST,wmma::mem_row_major);
  __syncthreads();

  // epilogue: 256 threads = 64 rows x 4 col-groups of 32
  int C0=(tid>>6)*32, R=tid&63, node=base+R;
  float v[32];
#pragma unroll
  for(int j=0;j<32;j++)v[j]=D[(size_t)R*DST+C0+j];
  if(EPI==1){
    if(node<NN){
      float* qr=g_q+(size_t)node*128+C0;
#pragma unroll
      for(int j=0;j<32;j+=4)*(float4*)(qr+j)=make_float4(v[j],v[j+1],v[j+2],v[j+3]);
    }
  }else if(EPI==0){
#pragma unroll
    for(int j=0;j<32;j++)v[j]=fmaxf(v[j]+bias[C0+j],0.f);
    if(node<NN){
      u32 hw[16],lw[16];
#pragma unroll
      for(int j=0;j<16;j++)split2(v[2*j],v[2*j+1],hw[j],lw[j]);
      uint4* oh=(uint4*)(g_hh+(size_t)node*128+C0);
      uint4* ol=(uint4*)(g_hl+(size_t)node*128+C0);
#pragma unroll
      for(int j=0;j<4;j++){oh[j]=((uint4*)hw)[j];ol[j]=((uint4*)lw)[j];}
    }
  }else if(EPI==4){
    float s=0.f,s2=0.f;
#pragma unroll
    for(int j=0;j<32;j++){v[j]+=bias[C0+j]; s+=v[j]; s2+=v[j]*v[j];}
    sr1[(tid>>6)*64+R]=s; sr2[(tid>>6)*64+R]=s2;
    __syncthreads();
    s=sr1[R]+sr1[64+R]+sr1[128+R]+sr1[192+R];
    s2=sr2[R]+sr2[64+R]+sr2[128+R]+sr2[192+R];
    float mu=s*(1.f/128.f), var=fmaxf(s2*(1.f/128.f)-mu*mu,0.f), rs=rsqrtf(var+1e-5f);
    if(node<NN){
      u32 hw[16],lw[16];
#pragma unroll
      for(int j=0;j<16;j++){
        float n0=(v[2*j]-mu)*rs*lg[C0+2*j]+lb[C0+2*j];
        float n1=(v[2*j+1]-mu)*rs*lg[C0+2*j+1]+lb[C0+2*j+1];
        n0=(n0>0.f)?n0:expm1f(n0);
        n1=(n1>0.f)?n1:expm1f(n1);
        split2(n0,n1,hw[j],lw[j]);
      }
      uint4* oh=(uint4*)(g_hh+(size_t)node*128+C0);
      uint4* ol=(uint4*)(g_hl+(size_t)node*128+C0);
#pragma unroll
      for(int j=0;j<4;j++){oh[j]=((uint4*)hw)[j];ol[j]=((uint4*)lw)[j];}
    }
  }else{ // EPI 2/3: bias+relu+LN
    float s=0.f,s2=0.f;
#pragma unroll
    for(int j=0;j<32;j++){v[j]=fmaxf(v[j]+bias[C0+j],0.f); s+=v[j]; s2+=v[j]*v[j];}
    sr1[(tid>>6)*64+R]=s; sr2[(tid>>6)*64+R]=s2;
    __syncthreads();
    s=sr1[R]+sr1[64+R]+sr1[128+R]+sr1[192+R];
    s2=sr2[R]+sr2[64+R]+sr2[128+R]+sr2[192+R];
    float mu=s*(1.f/128.f), var=fmaxf(s2*(1.f/128.f)-mu*mu,0.f), rs=rsqrtf(var+1e-5f);
#pragma unroll
    for(int j=0;j<32;j++)D[(size_t)R*DST+C0+j]=(v[j]-mu)*rs*lg[C0+j]+lb[C0+j];
    __syncthreads();
    if(EPI==2){
      if(tid<128){
        int col=tid; float a=0.f; int cur=-1;
        for(int r=0;r<TM;r++){
          int bi=sbid[r];
          if(bi!=cur){ if(cur>=0)atomicAdd(&g_gsum[cur*128+col],a); a=0.f; cur=bi; }
          if(bi>=0)a+=D[(size_t)r*DST+col];
        }
        if(cur>=0)atomicAdd(&g_gsum[cur*128+col],a);
      }
    }else{
      float* xsh=(float*)Bs;
      float* dsh=xsh+4096;
      for(int i=tid;i<4096;i+=256){int r=i>>6,k=i&63;int nd=base+r;xsh[i]=(nd<NN)?x[(size_t)nd*64+k]:0.f;}
      for(int i=tid;i<6144;i+=256)dsh[DS_DW1+i]=dW1[i];
      if(tid<32)dsh[DS_DB1+tid]=db1[tid];
      if(tid<256)dsh[DS_DW2+tid]=dW2[tid];
      if(tid<8){dsh[DS_DB2+tid]=db2[tid];dsh[DS_DW3+tid]=dW3[tid];}
      if(tid==0)dsh[DS_DB3]=db3[0];
      __syncthreads();
      int j=lane, rr0=wid*8;
      for(int i=0;i<8;i++){
        int row=rr0+i, nd=base+row;
        float s1=dsh[DS_DB1+j];
        const float* xr=xsh+(size_t)row*64;
        const float* nr=D+(size_t)row*DST;
#pragma unroll 4
        for(int k=0;k<64;k++)s1=fmaf(xr[k],dsh[DS_DW1+k*32+j],s1);
#pragma unroll 4
        for(int k=0;k<128;k++)s1=fmaf(nr[k],dsh[DS_DW1+(64+k)*32+j],s1);
        s1=fmaxf(s1,0.f);
        float t2[8];
#pragma unroll
        for(int m=0;m<8;m++)t2[m]=s1*dsh[DS_DW2+j*8+m];
#pragma unroll
        for(int o=16;o>0;o>>=1)
#pragma unroll
          for(int m=0;m<8;m++)t2[m]+=__shfl_xor_sync(~0u,t2[m],o);
        float out=dsh[DS_DB3];
#pragma unroll
        for(int m=0;m<8;m++)out=fmaf(fmaxf(t2[m]+dsh[DS_DB2+m],0.f),dsh[DS_DW3+m],out);
        if(j==0&&nd<NN)outp[nd]=out;
      }
    }
  }
}

// ---- graph-level MLP ----
__device__ __forceinline__ int lbound(const int* __restrict__ a,int n,int v){
  int lo=0,hi=n;
  while(lo<hi){int m=(lo+hi)>>1; if(a[m]<v)lo=m+1; else hi=m;}
  return lo;
}
__global__ void k_gmlp(const int* __restrict__ bidx,
    const float* __restrict__ gW1,const float* __restrict__ gb1,
    const float* __restrict__ gW2,const float* __restrict__ gb2,
    const float* __restrict__ gW3,const float* __restrict__ gb3,
    float* __restrict__ outp){
  int tid=threadIdx.x,lane=tid&31;
  int g=blockIdx.x*8+(tid>>5);
  int lo=lbound(bidx,NN,g),hi=lbound(bidx,NN,g+1);
  float inv=1.f/fmaxf((float)(hi-lo),1.f);
  float s1=gb1[lane];
  for(int k=0;k<128;k++)s1=fmaf(g_gsum[g*128+k]*inv,gW1[k*32+lane],s1);
  s1=fmaxf(s1,0.f);
  float t2[8];
#pragma unroll
  for(int m=0;m<8;m++)t2[m]=s1*gW2[lane*8+m];
#pragma unroll
  for(int o=16;o>0;o>>=1)
#pragma unroll
    for(int m=0;m<8;m++)t2[m]+=__shfl_xor_sync(~0u,t2[m],o);
  float out=gb3[0];
#pragma unroll
  for(int m=0;m<8;m++)out=fmaf(fmaxf(t2[m]+gb2[m],0.f),gW3[m],out);
  if(lane==0)outp[NN+g]=out;
}

extern "C" void kernel_launch(void* const* d_in,const int* in_sizes,int n_in,
                              void* d_out,int out_size){
  (void)in_sizes;(void)n_in;(void)out_size;
  const float* x   =(const float*)d_in[0];
  const int*   ei  =(const int*)  d_in[1];
  const int*   bidx=(const int*)  d_in[2];
  const float* W_in=(const float*)d_in[3];
  const float* b_in=(const float*)d_in[4];
  const float* eps =(const float*)d_in[5];
  const float* mW1 =(const float*)d_in[6];
  const float* mb1 =(const float*)d_in[7];
  const float* mW2 =(const float*)d_in[8];
  const float* mb2 =(const float*)d_in[9];
  const float* lng =(const float*)d_in[10];
  const float* lnb =(const float*)d_in[11];
  const float* oW  =(const float*)d_in[12];
  const float* ob  =(const float*)d_in[13];
  const float* lfg =(const float*)d_in[14];
  const float* lfb =(const float*)d_in[15];
  const float* gW  =(const float*)d_in[16];
  const float* gb  =(const float*)d_in[17];
  const float* glg =(const float*)d_in[18];
  const float* glb =(const float*)d_in[19];
  const float* dW1 =(const float*)d_in[20];
  const float* db1 =(const float*)d_in[21];
  const float* dW2 =(const float*)d_in[22];
  const float* db2 =(const float*)d_in[23];
  const float* dW3 =(const float*)d_in[24];
  const float* db3 =(const float*)d_in[25];
  const float* gW1 =(const float*)d_in[26];
  const float* gb1 =(const float*)d_in[27];
  const float* gW2 =(const float*)d_in[28];
  const float* gb2 =(const float*)d_in[29];
  const float* gW3 =(const float*)d_in[30];
  const float* gb3 =(const float*)d_in[31];
  float* outp=(float*)d_out;

  const int NG=(NN+TM-1)/TM;   // 1563
  cudaFuncSetAttribute((const void*)k_mmp<64,64,0,0>,   cudaFuncAttributeMaxDynamicSharedMemorySize,SM_ALL);
  cudaFuncSetAttribute((const void*)k_mmp<192,64,0,1>,  cudaFuncAttributeMaxDynamicSharedMemorySize,SM_ALL);
  cudaFuncSetAttribute((const void*)k_mmp<128,128,2,4>, cudaFuncAttributeMaxDynamicSharedMemorySize,SM_ALL);
  cudaFuncSetAttribute((const void*)k_mmp<128,128,1,2>, cudaFuncAttributeMaxDynamicSharedMemorySize,SM_ALL);
  cudaFuncSetAttribute((const void*)k_mmp<128,128,1,3>, cudaFuncAttributeMaxDynamicSharedMemorySize,SM_ALL);

  k_prepx<<<12500,256>>>(x);                                             //0
  k_prepw<<<640,256>>>(W_in,mW1,mW2,gW,oW);                              //1
  k_mmp<64,64,0,0><<<NG,256,SM_ALL>>>(0,b_in,nullptr,nullptr,nullptr,nullptr,
      nullptr,nullptr,nullptr,nullptr,nullptr,nullptr,nullptr);          //2 encoder
  k_mmp<192,64,0,1><<<NG,256,SM_ALL>>>(16384,nullptr,nullptr,nullptr,nullptr,nullptr,
      nullptr,nullptr,nullptr,nullptr,nullptr,nullptr,nullptr);          //3 GEMM1 l0 (profiled)
  k_zero<<<391,256>>>();                                                 //4
  k_hist<<<6250,256>>>(ei);                                              //5
  k_scan1<<<98,1024>>>();                                                //6
  k_scan2<<<1,128>>>();                                                  //7
  k_scan3<<<98,1024>>>();                                                //8
  k_fill<<<6250,256>>>(ei);                                              //9

  for(int l=0;l<3;l++){
    k_gatheru<<<12500,256>>>(eps,l,mb1+l*128);
    k_mmp<128,128,2,4><<<NG,256,SM_ALL>>>(163840+l*32768,mb2+l*128,lng+l*128,lnb+l*128,
        nullptr,nullptr,nullptr,nullptr,nullptr,nullptr,nullptr,nullptr,nullptr);
    if(l<2)
      k_mmp<192,64,0,1><<<NG,256,SM_ALL>>>(16384+(l+1)*49152,nullptr,nullptr,nullptr,nullptr,nullptr,
          nullptr,nullptr,nullptr,nullptr,nullptr,nullptr,nullptr);
  }
  k_mmp<128,128,1,2><<<NG,256,SM_ALL>>>(262144,gb,glg,glb,bidx,nullptr,
      nullptr,nullptr,nullptr,nullptr,nullptr,nullptr,nullptr);
  k_mmp<128,128,1,3><<<NG,256,SM_ALL>>>(294912,ob,lfg,lfb,nullptr,x,
      dW1,db1,dW2,db2,dW3,db3,outp);
  k_gmlp<<<32,256>>>(bidx,gW1,gb1,gW2,gb2,gW3,gb3,outp);
}

// round 8
// speedup vs baseline: 2.5965x; 1.3703x over previous
#include <cuda_runtime.h>
#include <cuda_bf16.h>
#include <cuda_fp16.h>
#include <mma.h>

#define NN 100000
#define EE 1600000
#define BB 256
typedef unsigned long long u64;
typedef unsigned int u32;
using namespace nvcuda;

// ---- static scratch ----
__device__ __align__(16) __half g_xf[NN*64];
__device__ __align__(16) __half g_hf[NN*128];
__device__ __align__(16) __half g_uf[NN*128];
__device__ __align__(16) __half g_q[NN*128];
__device__ __align__(16) __half g_wimg[327680];
__device__ float g_gsum[BB*128];
__device__ int g_deg[NN], g_rowptr[NN+1], g_cursor[NN], g_col[EE];
__device__ int g_bsum[128], g_boff[128];

__device__ __forceinline__ u32 pack_h2(float a,float b){
  __half2 h=__floats2half2_rn(a,b); return *(u32*)&h;
}
__device__ __forceinline__ void cpa16(void* dst,const void* src){
  u32 d=(u32)__cvta_generic_to_shared(dst);
  asm volatile("cp.async.cg.shared.global [%0],[%1],16;"::"r"(d),"l"(src));
}
__device__ __forceinline__ void cpcommit(){ asm volatile("cp.async.commit_group;":::"memory"); }
template<int N> __device__ __forceinline__ void cpwaitg(){ asm volatile("cp.async.wait_group %0;"::"n"(N):"memory"); }

// ---- CSR ----
__global__ void k_zero(){int i=blockIdx.x*blockDim.x+threadIdx.x; if(i<NN)g_deg[i]=0; if(i<BB*128)g_gsum[i]=0.f;}
__global__ void k_hist(const int* __restrict__ ei){int e=blockIdx.x*blockDim.x+threadIdx.x; if(e<EE)atomicAdd(&g_deg[ei[EE+e]],1);}
__global__ void k_scan1(){
  __shared__ int ws[32];
  int tid=threadIdx.x,lane=tid&31,wid=tid>>5;
  int i=blockIdx.x*1024+tid;
  int v=(i<NN)?g_deg[i]:0;
  int x=v;
#pragma unroll
  for(int o=16;o>0;o>>=1)x+=__shfl_xor_sync(~0u,x,o);
  if(lane==0)ws[wid]=x;
  __syncthreads();
  if(tid==0){int s=0;
#pragma unroll
    for(int w=0;w<32;w++)s+=ws[w];
    g_bsum[blockIdx.x]=s;}
}
__global__ void k_scan2(){
  __shared__ int ws[4];
  int tid=threadIdx.x,lane=tid&31,wid=tid>>5;
  int v=(tid<98)?g_bsum[tid]:0;
  int x=v;
#pragma unroll
  for(int o=1;o<32;o<<=1){int t=__shfl_up_sync(~0u,x,o); if(lane>=o)x+=t;}
  if(lane==31)ws[wid]=x;
  __syncthreads();
  int add=0;
  for(int w=0;w<wid;w++)add+=ws[w];
  if(tid<98)g_boff[tid]=add+x-v;
  if(tid==0)g_rowptr[NN]=EE;
}
__global__ void k_scan3(){
  __shared__ int ws[32];
  int tid=threadIdx.x,lane=tid&31,wid=tid>>5;
  int i=blockIdx.x*1024+tid;
  int v=(i<NN)?g_deg[i]:0;
  int x=v;
#pragma unroll
  for(int o=1;o<32;o<<=1){int t=__shfl_up_sync(~0u,x,o); if(lane>=o)x+=t;}
  if(lane==31)ws[wid]=x;
  __syncthreads();
  if(wid==0){int y=ws[lane];
#pragma unroll
    for(int o=1;o<32;o<<=1){int t=__shfl_up_sync(~0u,y,o); if(lane>=o)y+=t;} ws[lane]=y;}
  __syncthreads();
  if(i<NN){
    int ex=g_boff[blockIdx.x]+x-v+((wid>0)?ws[wid-1]:0);
    g_rowptr[i]=ex; g_cursor[i]=ex;
  }
}
__global__ void k_fill(const int* __restrict__ ei){
  int e=blockIdx.x*blockDim.x+threadIdx.x;
  if(e<EE){int d=ei[EE+e]; int p=atomicAdd(&g_cursor[d],1); g_col[p]=ei[e];}
}

// ---- prep ----
__global__ void k_prepx(const float* __restrict__ x){
  int i=blockIdx.x*blockDim.x+threadIdx.x; if(i>=NN*32)return;
  float2 v=((const float2*)x)[i];
  ((u32*)g_xf)[i]=pack_h2(v.x,v.y);
}
__global__ void k_prepw(const float* __restrict__ Win,const float* __restrict__ W1,
                        const float* __restrict__ W2,const float* __restrict__ gW,
                        const float* __restrict__ oW){
  int gid=blockIdx.x*blockDim.x+threadIdx.x; if(gid>=163840)return;
  const float* src; int idx,K; __half* img;
  if(gid<8192){src=Win;idx=gid;K=64;img=g_wimg;}
  else if(gid<81920){int t=gid-8192;int l=t/24576;idx=t%24576;K=192;src=W1+l*24576;img=g_wimg+16384+l*49152;}
  else if(gid<131072){int t=gid-81920;int l=t/16384;idx=t%16384;K=128;src=W2+l*16384;img=g_wimg+163840+l*32768;}
  else if(gid<147456){idx=gid-131072;K=128;src=gW;img=g_wimg+262144;}
  else {idx=gid-147456;K=128;src=oW;img=g_wimg+294912;}
  float w=src[idx];
  __half h=__float2half_rn(w);
  __half l=__float2half_rn(w-__half2float(h));
  img[idx]=h; img[K*128+idx]=l;
}

// ---- fused gather + GIN pre-act: u = relu((1+eps)q + sum_nbr q + b1) -> fp16 plane ----
__global__ void k_gatheru(const float* __restrict__ eps,int layer,const float* __restrict__ b1){
  int w=(blockIdx.x*blockDim.x+threadIdx.x)>>5, lane=threadIdx.x&31;
  if(w>=NN)return;
  float e1=1.f+eps[layer];
  int s=g_rowptr[w],t=g_rowptr[w+1];
  float4 a0=make_float4(0,0,0,0),a1=a0,a2=a0,a3=a0;
  int e=s;
  auto ld4=[&](int nb)->float4{
    uint2 r=*(const uint2*)(g_q+(size_t)nb*128+lane*4);
    float2 f0=__half22float2(*(__half2*)&r.x);
    float2 f1=__half22float2(*(__half2*)&r.y);
    return make_float4(f0.x,f0.y,f1.x,f1.y);
  };
  for(;e+4<=t;e+=4){
    float4 v0=ld4(g_col[e]),v1=ld4(g_col[e+1]),v2=ld4(g_col[e+2]),v3=ld4(g_col[e+3]);
    a0.x+=v0.x;a0.y+=v0.y;a0.z+=v0.z;a0.w+=v0.w;
    a1.x+=v1.x;a1.y+=v1.y;a1.z+=v1.z;a1.w+=v1.w;
    a2.x+=v2.x;a2.y+=v2.y;a2.z+=v2.z;a2.w+=v2.w;
    a3.x+=v3.x;a3.y+=v3.y;a3.z+=v3.z;a3.w+=v3.w;
  }
  for(;e<t;e++){
    float4 v=ld4(g_col[e]);
    a0.x+=v.x;a0.y+=v.y;a0.z+=v.z;a0.w+=v.w;
  }
  a0.x+=a1.x+a2.x+a3.x; a0.y+=a1.y+a2.y+a3.y;
  a0.z+=a1.z+a2.z+a3.z; a0.w+=a1.w+a2.w+a3.w;
  float4 qo=ld4(w);
  float4 bv=*(const float4*)(b1+lane*4);
  float u0=fmaxf(fmaf(e1,qo.x,a0.x)+bv.x,0.f);
  float u1=fmaxf(fmaf(e1,qo.y,a0.y)+bv.y,0.f);
  float u2=fmaxf(fmaf(e1,qo.z,a0.z)+bv.z,0.f);
  float u3=fmaxf(fmaf(e1,qo.w,a0.w)+bv.w,0.f);
  *(uint2*)(g_uf+(size_t)w*128+lane*4)=make_uint2(pack_h2(u0,u1),pack_h2(u2,u3));
}

// 64-row tiles, 256 threads, 2 CTAs/SM
#define HDR 4096
#define SNB 136
#define SKA 72
#define DST 132
#define TM 64
#define APL (TM*SKA)
#define BPL (64*SNB)
#define SM_ALL (HDR + 2*APL*2 + 2*2*BPL*2)   // 4096+18432+69632 = 92160
#define XSH_OFF 37888
#define DSH_OFF 54272
#define DS_DW1 0
#define DS_DB1 6144
#define DS_DW2 6176
#define DS_DB2 6432
#define DS_DW3 6440
#define DS_DB3 6448

// ---- pipelined fp16 2-term GEMM: A single plane (x/h/u), B = Wh+Wl planes.
// EPI: 0=relu+bias->h, 1=raw->q(fp16), 2=bias+relu+LN->pool, 3=bias+relu+LN->decoder, 4=bias+LN+ELU->h
template<int KT,int K0,int ASRC,int EPI>
__global__ void __launch_bounds__(256,2) k_mmp(
    int woff,const float* __restrict__ bias,const float* __restrict__ lg,const float* __restrict__ lb,
    const int* __restrict__ bidx,const float* __restrict__ x,
    const float* __restrict__ dW1,const float* __restrict__ db1,
    const float* __restrict__ dW2,const float* __restrict__ db2,
    const float* __restrict__ dW3,const float* __restrict__ db3,
    float* __restrict__ outp)
{
  constexpr int C=KT/64;
  extern __shared__ unsigned char smx[];
  int* sbid=(int*)(smx);
  float* sr1=(float*)(smx+512);
  float* sr2=(float*)(smx+1536);
  __half* As=(__half*)(smx+HDR);
  __half* Bs=(__half*)(smx+HDR+2*APL*2);
  float* D=(float*)(smx+HDR);
  int tid=threadIdx.x,lane=tid&31,wid=tid>>5;
  int base=blockIdx.x*TM;
  const __half* p0=(ASRC==0)?g_xf:((ASRC==2)?g_uf:g_hf);
  if(EPI==2&&tid<TM){int nd=base+tid; sbid[tid]=(nd<NN)?bidx[nd]:-1;}

  auto stage=[&](int c,int buf){
    const __half* ws=g_wimg+woff;
    for(int i=tid;i<2048;i+=256){
      int pl=i>>10,j=i&1023,kk=j>>4,u=j&15;
      cpa16(Bs+(size_t)(buf*2+pl)*BPL+kk*SNB+u*8,
            ws+(size_t)pl*KT*128+(size_t)(c*64+kk)*128+u*8);
    }
    for(int i=tid;i<512;i+=256){
      int row=i>>3,u=i&7;
      int gc=c*64+u*8, node=base+row;
      __half* dst=As+(size_t)buf*APL+row*SKA+u*8;
      if(node<NN){
        const __half* srcp;
        if(gc<K0) srcp=p0+(size_t)node*K0+gc;
        else      srcp=g_hf+(size_t)node*128+gc-K0;
        cpa16(dst,srcp);
      }else *(uint4*)dst=make_uint4(0,0,0,0);
    }
  };

  // warp grid: 2 row-groups x 4 col-groups; warp tile 32x32
  wmma::fragment<wmma::accumulator,16,16,16,float> a00,a01,a10,a11;
  wmma::fill_fragment(a00,0.f); wmma::fill_fragment(a01,0.f);
  wmma::fill_fragment(a10,0.f); wmma::fill_fragment(a11,0.f);
  int r0=(wid&1)*32, cw=(wid>>1)*32;

  stage(0,0); cpcommit();
  for(int c=0;c<C;c++){
    int buf=c&1;
    if(c+1<C){ stage(c+1,buf^1); cpcommit(); cpwaitg<1>(); }
    else cpwaitg<0>();
    __syncthreads();
    const __half* Ap=As+(size_t)buf*APL;
    const __half* Bh=Bs+(size_t)(buf*2)*BPL;
    const __half* Bl=Bh+BPL;
#pragma unroll
    for(int kc=0;kc<4;kc++){
      wmma::fragment<wmma::matrix_a,16,16,16,__half,wmma::row_major> ah0,ah1;
      wmma::load_matrix_sync(ah0,Ap+(size_t)r0*SKA+kc*16,SKA);
      wmma::load_matrix_sync(ah1,Ap+(size_t)(r0+16)*SKA+kc*16,SKA);
      wmma::fragment<wmma::matrix_b,16,16,16,__half,wmma::row_major> bh0,bh1,bl0,bl1;
      wmma::load_matrix_sync(bh0,Bh+(size_t)(kc*16)*SNB+cw,SNB);
      wmma::load_matrix_sync(bh1,Bh+(size_t)(kc*16)*SNB+cw+16,SNB);
      wmma::load_matrix_sync(bl0,Bl+(size_t)(kc*16)*SNB+cw,SNB);
      wmma::load_matrix_sync(bl1,Bl+(size_t)(kc*16)*SNB+cw+16,SNB);
      wmma::mma_sync(a00,ah0,bh0,a00); wmma::mma_sync(a00,ah0,bl0,a00);
      wmma::mma_sync(a01,ah0,bh1,a01); wmma::mma_sync(a01,ah0,bl1,a01);
      wmma::mma_sync(a10,ah1,bh0,a10); wmma::mma_sync(a10,ah1,bl0,a10);
      wmma::mma_sync(a11,ah1,bh1,a11); wmma::mma_sync(a11,ah1,bl1,a11);
    }
    __syncthreads();
  }
  wmma::store_matrix_sync(D+(size_t)r0*DST+cw,a00,DST,wmma::mem_row_major);
  wmma::store_matrix_sync(D+(size_t)r0*DST+cw+16,a01,DST,wmma::mem_row_major);
  wmma::store_matrix_sync(D+(size_t)(r0+16)*DST+cw,a10,DST,wmma::mem_row_major);
  wmma::store_matrix_sync(D+(size_t)(r0+16)*DST+cw+16,a11,DST,wmma::mem_row_major);
  __syncthreads();

  // epilogue: 256 threads = 64 rows x 4 col-groups of 32
  int C0=(tid>>6)*32, R=tid&63, node=base+R;
  float v[32];
#pragma unroll
  for(int j=0;j<32;j++)v[j]=D[(size_t)R*DST+C0+j];
  if(EPI==1){
    if(node<NN){
      u32 hw[16];
#pragma unroll
      for(int j=0;j<16;j++)hw[j]=pack_h2(v[2*j],v[2*j+1]);
      uint4* oq=(uint4*)(g_q+(size_t)node*128+C0);
#pragma unroll
      for(int j=0;j<4;j++)oq[j]=((uint4*)hw)[j];
    }
  }else if(EPI==0){
#pragma unroll
    for(int j=0;j<32;j++)v[j]=fmaxf(v[j]+bias[C0+j],0.f);
    if(node<NN){
      u32 hw[16];
#pragma unroll
      for(int j=0;j<16;j++)hw[j]=pack_h2(v[2*j],v[2*j+1]);
      uint4* oh=(uint4*)(g_hf+(size_t)node*128+C0);
#pragma unroll
      for(int j=0;j<4;j++)oh[j]=((uint4*)hw)[j];
    }
  }else if(EPI==4){
    float s=0.f,s2=0.f;
#pragma unroll
    for(int j=0;j<32;j++){v[j]+=bias[C0+j]; s+=v[j]; s2+=v[j]*v[j];}
    sr1[(tid>>6)*64+R]=s; sr2[(tid>>6)*64+R]=s2;
    __syncthreads();
    s=sr1[R]+sr1[64+R]+sr1[128+R]+sr1[192+R];
    s2=sr2[R]+sr2[64+R]+sr2[128+R]+sr2[192+R];
    float mu=s*(1.f/128.f), var=fmaxf(s2*(1.f/128.f)-mu*mu,0.f), rs=rsqrtf(var+1e-5f);
    if(node<NN){
      u32 hw[16];
#pragma unroll
      for(int j=0;j<16;j++){
        float n0=(v[2*j]-mu)*rs*lg[C0+2*j]+lb[C0+2*j];
        float n1=(v[2*j+1]-mu)*rs*lg[C0+2*j+1]+lb[C0+2*j+1];
        n0=(n0>0.f)?n0:expm1f(n0);
        n1=(n1>0.f)?n1:expm1f(n1);
        hw[j]=pack_h2(n0,n1);
      }
      uint4* oh=(uint4*)(g_hf+(size_t)node*128+C0);
#pragma unroll
      for(int j=0;j<4;j++)oh[j]=((uint4*)hw)[j];
    }
  }else{ // EPI 2/3: bias+relu+LN
    float s=0.f,s2=0.f;
#pragma unroll
    for(int j=0;j<32;j++){v[j]=fmaxf(v[j]+bias[C0+j],0.f); s+=v[j]; s2+=v[j]*v[j];}
    sr1[(tid>>6)*64+R]=s; sr2[(tid>>6)*64+R]=s2;
    __syncthreads();
    s=sr1[R]+sr1[64+R]+sr1[128+R]+sr1[192+R];
    s2=sr2[R]+sr2[64+R]+sr2[128+R]+sr2[192+R];
    float mu=s*(1.f/128.f), var=fmaxf(s2*(1.f/128.f)-mu*mu,0.f), rs=rsqrtf(var+1e-5f);
#pragma unroll
    for(int j=0;j<32;j++)D[(size_t)R*DST+C0+j]=(v[j]-mu)*rs*lg[C0+j]+lb[C0+j];
    __syncthreads();
    if(EPI==2){
      if(tid<128){
        int col=tid; float a=0.f; int cur=-1;
        for(int r=0;r<TM;r++){
          int bi=sbid[r];
          if(bi!=cur){ if(cur>=0)atomicAdd(&g_gsum[cur*128+col],a); a=0.f; cur=bi; }
          if(bi>=0)a+=D[(size_t)r*DST+col];
        }
        if(cur>=0)atomicAdd(&g_gsum[cur*128+col],a);
      }
    }else{
      float* xsh=(float*)(smx+XSH_OFF);
      float* dsh=(float*)(smx+DSH_OFF);
      for(int i=tid;i<4096;i+=256){int r=i>>6,k=i&63;int nd=base+r;xsh[i]=(nd<NN)?x[(size_t)nd*64+k]:0.f;}
      for(int i=tid;i<6144;i+=256)dsh[DS_DW1+i]=dW1[i];
      if(tid<32)dsh[DS_DB1+tid]=db1[tid];
      if(tid<256)dsh[DS_DW2+tid]=dW2[tid];
      if(tid<8){dsh[DS_DB2+tid]=db2[tid];dsh[DS_DW3+tid]=dW3[tid];}
      if(tid==0)dsh[DS_DB3]=db3[0];
      __syncthreads();
      int j=lane, rr0=wid*8;
      for(int i=0;i<8;i++){
        int row=rr0+i, nd=base+row;
        float s1=dsh[DS_DB1+j];
        const float* xr=xsh+(size_t)row*64;
        const float* nr=D+(size_t)row*DST;
#pragma unroll 4
        for(int k=0;k<64;k++)s1=fmaf(xr[k],dsh[DS_DW1+k*32+j],s1);
#pragma unroll 4
        for(int k=0;k<128;k++)s1=fmaf(nr[k],dsh[DS_DW1+(64+k)*32+j],s1);
        s1=fmaxf(s1,0.f);
        float t2[8];
#pragma unroll
        for(int m=0;m<8;m++)t2[m]=s1*dsh[DS_DW2+j*8+m];
#pragma unroll
        for(int o=16;o>0;o>>=1)
#pragma unroll
          for(int m=0;m<8;m++)t2[m]+=__shfl_xor_sync(~0u,t2[m],o);
        float out=dsh[DS_DB3];
#pragma unroll
        for(int m=0;m<8;m++)out=fmaf(fmaxf(t2[m]+dsh[DS_DB2+m],0.f),dsh[DS_DW3+m],out);
        if(j==0&&nd<NN)outp[nd]=out;
      }
    }
  }
}

// ---- graph-level MLP ----
__device__ __forceinline__ int lbound(const int* __restrict__ a,int n,int v){
  int lo=0,hi=n;
  while(lo<hi){int m=(lo+hi)>>1; if(a[m]<v)lo=m+1; else hi=m;}
  return lo;
}
__global__ void k_gmlp(const int* __restrict__ bidx,
    const float* __restrict__ gW1,const float* __restrict__ gb1,
    const float* __restrict__ gW2,const float* __restrict__ gb2,
    const float* __restrict__ gW3,const float* __restrict__ gb3,
    float* __restrict__ outp){
  int tid=threadIdx.x,lane=tid&31;
  int g=blockIdx.x*8+(tid>>5);
  int lo=lbound(bidx,NN,g),hi=lbound(bidx,NN,g+1);
  float inv=1.f/fmaxf((float)(hi-lo),1.f);
  float s1=gb1[lane];
  for(int k=0;k<128;k++)s1=fmaf(g_gsum[g*128+k]*inv,gW1[k*32+lane],s1);
  s1=fmaxf(s1,0.f);
  float t2[8];
#pragma unroll
  for(int m=0;m<8;m++)t2[m]=s1*gW2[lane*8+m];
#pragma unroll
  for(int o=16;o>0;o>>=1)
#pragma unroll
    for(int m=0;m<8;m++)t2[m]+=__shfl_xor_sync(~0u,t2[m],o);
  float out=gb3[0];
#pragma unroll
  for(int m=0;m<8;m++)out=fmaf(fmaxf(t2[m]+gb2[m],0.f),gW3[m],out);
  if(lane==0)outp[NN+g]=out;
}

extern "C" void kernel_launch(void* const* d_in,const int* in_sizes,int n_in,
                              void* d_out,int out_size){
  (void)in_sizes;(void)n_in;(void)out_size;
  const float* x   =(const float*)d_in[0];
  const int*   ei  =(const int*)  d_in[1];
  const int*   bidx=(const int*)  d_in[2];
  const float* W_in=(const float*)d_in[3];
  const float* b_in=(const float*)d_in[4];
  const float* eps =(const float*)d_in[5];
  const float* mW1 =(const float*)d_in[6];
  const float* mb1 =(const float*)d_in[7];
  const float* mW2 =(const float*)d_in[8];
  const float* mb2 =(const float*)d_in[9];
  const float* lng =(const float*)d_in[10];
  const float* lnb =(const float*)d_in[11];
  const float* oW  =(const float*)d_in[12];
  const float* ob  =(const float*)d_in[13];
  const float* lfg =(const float*)d_in[14];
  const float* lfb =(const float*)d_in[15];
  const float* gW  =(const float*)d_in[16];
  const float* gb  =(const float*)d_in[17];
  const float* glg =(const float*)d_in[18];
  const float* glb =(const float*)d_in[19];
  const float* dW1 =(const float*)d_in[20];
  const float* db1 =(const float*)d_in[21];
  const float* dW2 =(const float*)d_in[22];
  const float* db2 =(const float*)d_in[23];
  const float* dW3 =(const float*)d_in[24];
  const float* db3 =(const float*)d_in[25];
  const float* gW1 =(const float*)d_in[26];
  const float* gb1 =(const float*)d_in[27];
  const float* gW2 =(const float*)d_in[28];
  const float* gb2 =(const float*)d_in[29];
  const float* gW3 =(const float*)d_in[30];
  const float* gb3 =(const float*)d_in[31];
  float* outp=(float*)d_out;

  const int NG=(NN+TM-1)/TM;   // 1563
  cudaFuncSetAttribute((const void*)k_mmp<64,64,0,0>,   cudaFuncAttributeMaxDynamicSharedMemorySize,SM_ALL);
  cudaFuncSetAttribute((const void*)k_mmp<192,64,0,1>,  cudaFuncAttributeMaxDynamicSharedMemorySize,SM_ALL);
  cudaFuncSetAttribute((const void*)k_mmp<128,128,2,4>, cudaFuncAttributeMaxDynamicSharedMemorySize,SM_ALL);
  cudaFuncSetAttribute((const void*)k_mmp<128,128,1,2>, cudaFuncAttributeMaxDynamicSharedMemorySize,SM_ALL);
  cudaFuncSetAttribute((const void*)k_mmp<128,128,1,3>, cudaFuncAttributeMaxDynamicSharedMemorySize,SM_ALL);

  k_prepx<<<12500,256>>>(x);                                             //0
  k_prepw<<<640,256>>>(W_in,mW1,mW2,gW,oW);                              //1
  k_mmp<64,64,0,0><<<NG,256,SM_ALL>>>(0,b_in,nullptr,nullptr,nullptr,nullptr,
      nullptr,nullptr,nullptr,nullptr,nullptr,nullptr,nullptr);          //2 encoder
  k_mmp<192,64,0,1><<<NG,256,SM_ALL>>>(16384,nullptr,nullptr,nullptr,nullptr,nullptr,
      nullptr,nullptr,nullptr,nullptr,nullptr,nullptr,nullptr);          //3 GEMM1 l0 (profiled)
  k_zero<<<391,256>>>();                                                 //4
  k_hist<<<6250,256>>>(ei);                                              //5
  k_scan1<<<98,1024>>>();                                                //6
  k_scan2<<<1,128>>>();                                                  //7
  k_scan3<<<98,1024>>>();                                                //8
  k_fill<<<6250,256>>>(ei);                                              //9

  for(int l=0;l<3;l++){
    k_gatheru<<<12500,256>>>(eps,l,mb1+l*128);
    k_mmp<128,128,2,4><<<NG,256,SM_ALL>>>(163840+l*32768,mb2+l*128,lng+l*128,lnb+l*128,
        nullptr,nullptr,nullptr,nullptr,nullptr,nullptr,nullptr,nullptr,nullptr);
    if(l<2)
      k_mmp<192,64,0,1><<<NG,256,SM_ALL>>>(16384+(l+1)*49152,nullptr,nullptr,nullptr,nullptr,nullptr,
          nullptr,nullptr,nullptr,nullptr,nullptr,nullptr,nullptr);
  }
  k_mmp<128,128,1,2><<<NG,256,SM_ALL>>>(262144,gb,glg,glb,bidx,nullptr,
      nullptr,nullptr,nullptr,nullptr,nullptr,nullptr,nullptr);
  k_mmp<128,128,1,3><<<NG,256,SM_ALL>>>(294912,ob,lfg,lfb,nullptr,x,
      dW1,db1,dW2,db2,dW3,db3,outp);
  k_gmlp<<<32,256>>>(bidx,gW1,gb1,gW2,gb2,gW3,gb3,outp);
}

// round 9
// speedup vs baseline: 2.7904x; 1.0747x over previous
#include <cuda_runtime.h>
#include <cuda_fp16.h>
#include <mma.h>

#define NN 100000
#define EE 1600000
#define BB 256
typedef unsigned long long u64;
typedef unsigned int u32;
using namespace nvcuda;

// ---- static scratch ----
__device__ __align__(16) __half g_xf[NN*64];
__device__ __align__(16) __half g_uf[NN*128];
__device__ __align__(16) __half g_q[NN*128];
__device__ __align__(16) __half g_wimg[327680];
__device__ float g_gsum[BB*128];
__device__ int g_deg[NN], g_rowptr[NN+1], g_cursor[NN], g_col[EE];
__device__ int g_bsum[128], g_boff[128];

__device__ __forceinline__ u32 pack_h2(float a,float b){
  __half2 h=__floats2half2_rn(a,b); return *(u32*)&h;
}
__device__ __forceinline__ void cpa16(void* dst,const void* src){
  u32 d=(u32)__cvta_generic_to_shared(dst);
  asm volatile("cp.async.cg.shared.global [%0],[%1],16;"::"r"(d),"l"(src));
}
__device__ __forceinline__ void cpcommit(){ asm volatile("cp.async.commit_group;":::"memory"); }
template<int N> __device__ __forceinline__ void cpwaitg(){ asm volatile("cp.async.wait_group %0;"::"n"(N):"memory"); }

// ---- CSR ----
__global__ void k_zero(){int i=blockIdx.x*blockDim.x+threadIdx.x; if(i<NN)g_deg[i]=0; if(i<BB*128)g_gsum[i]=0.f;}
__global__ void k_hist(const int* __restrict__ ei){int e=blockIdx.x*blockDim.x+threadIdx.x; if(e<EE)atomicAdd(&g_deg[ei[EE+e]],1);}
__global__ void k_scan1(){
  __shared__ int ws[32];
  int tid=threadIdx.x,lane=tid&31,wid=tid>>5;
  int i=blockIdx.x*1024+tid;
  int v=(i<NN)?g_deg[i]:0;
  int x=v;
#pragma unroll
  for(int o=16;o>0;o>>=1)x+=__shfl_xor_sync(~0u,x,o);
  if(lane==0)ws[wid]=x;
  __syncthreads();
  if(tid==0){int s=0;
#pragma unroll
    for(int w=0;w<32;w++)s+=ws[w];
    g_bsum[blockIdx.x]=s;}
}
__global__ void k_scan2(){
  __shared__ int ws[4];
  int tid=threadIdx.x,lane=tid&31,wid=tid>>5;
  int v=(tid<98)?g_bsum[tid]:0;
  int x=v;
#pragma unroll
  for(int o=1;o<32;o<<=1){int t=__shfl_up_sync(~0u,x,o); if(lane>=o)x+=t;}
  if(lane==31)ws[wid]=x;
  __syncthreads();
  int add=0;
  for(int w=0;w<wid;w++)add+=ws[w];
  if(tid<98)g_boff[tid]=add+x-v;
  if(tid==0)g_rowptr[NN]=EE;
}
__global__ void k_scan3(){
  __shared__ int ws[32];
  int tid=threadIdx.x,lane=tid&31,wid=tid>>5;
  int i=blockIdx.x*1024+tid;
  int v=(i<NN)?g_deg[i]:0;
  int x=v;
#pragma unroll
  for(int o=1;o<32;o<<=1){int t=__shfl_up_sync(~0u,x,o); if(lane>=o)x+=t;}
  if(lane==31)ws[wid]=x;
  __syncthreads();
  if(wid==0){int y=ws[lane];
#pragma unroll
    for(int o=1;o<32;o<<=1){int t=__shfl_up_sync(~0u,y,o); if(lane>=o)y+=t;} ws[lane]=y;}
  __syncthreads();
  if(i<NN){
    int ex=g_boff[blockIdx.x]+x-v+((wid>0)?ws[wid-1]:0);
    g_rowptr[i]=ex; g_cursor[i]=ex;
  }
}
__global__ void k_fill(const int* __restrict__ ei){
  int e=blockIdx.x*blockDim.x+threadIdx.x;
  if(e<EE){int d=ei[EE+e]; int p=atomicAdd(&g_cursor[d],1); g_col[p]=ei[e];}
}

// ---- prep ----
__global__ void k_prepx(const float* __restrict__ x){
  int i=blockIdx.x*blockDim.x+threadIdx.x; if(i>=NN*32)return;
  float2 v=((const float2*)x)[i];
  ((u32*)g_xf)[i]=pack_h2(v.x,v.y);
}
__global__ void k_prepw(const float* __restrict__ Win,const float* __restrict__ W1,
                        const float* __restrict__ W2,const float* __restrict__ gW,
                        const float* __restrict__ oW){
  int gid=blockIdx.x*blockDim.x+threadIdx.x; if(gid>=163840)return;
  const float* src; int idx,K; __half* img;
  if(gid<8192){src=Win;idx=gid;K=64;img=g_wimg;}
  else if(gid<81920){int t=gid-8192;int l=t/24576;idx=t%24576;K=192;src=W1+l*24576;img=g_wimg+16384+l*49152;}
  else if(gid<131072){int t=gid-81920;int l=t/16384;idx=t%16384;K=128;src=W2+l*16384;img=g_wimg+163840+l*32768;}
  else if(gid<147456){idx=gid-131072;K=128;src=gW;img=g_wimg+262144;}
  else {idx=gid-147456;K=128;src=oW;img=g_wimg+294912;}
  float w=src[idx];
  __half h=__float2half_rn(w);
  __half l=__float2half_rn(w-__half2float(h));
  img[idx]=h; img[K*128+idx]=l;
}

// ---- fused gather + GIN pre-act: u = relu((1+eps)q + sum_nbr q + b1) -> fp16 ----
__global__ void k_gatheru(const float* __restrict__ eps,int layer,const float* __restrict__ b1){
  int w=(blockIdx.x*blockDim.x+threadIdx.x)>>5, lane=threadIdx.x&31;
  if(w>=NN)return;
  float e1=1.f+eps[layer];
  int s=g_rowptr[w],t=g_rowptr[w+1];
  float4 a0=make_float4(0,0,0,0),a1=a0,a2=a0,a3=a0;
  int e=s;
  auto ld4=[&](int nb)->float4{
    uint2 r=*(const uint2*)(g_q+(size_t)nb*128+lane*4);
    float2 f0=__half22float2(*(__half2*)&r.x);
    float2 f1=__half22float2(*(__half2*)&r.y);
    return make_float4(f0.x,f0.y,f1.x,f1.y);
  };
  for(;e+4<=t;e+=4){
    float4 v0=ld4(g_col[e]),v1=ld4(g_col[e+1]),v2=ld4(g_col[e+2]),v3=ld4(g_col[e+3]);
    a0.x+=v0.x;a0.y+=v0.y;a0.z+=v0.z;a0.w+=v0.w;
    a1.x+=v1.x;a1.y+=v1.y;a1.z+=v1.z;a1.w+=v1.w;
    a2.x+=v2.x;a2.y+=v2.y;a2.z+=v2.z;a2.w+=v2.w;
    a3.x+=v3.x;a3.y+=v3.y;a3.z+=v3.z;a3.w+=v3.w;
  }
  for(;e<t;e++){
    float4 v=ld4(g_col[e]);
    a0.x+=v.x;a0.y+=v.y;a0.z+=v.z;a0.w+=v.w;
  }
  a0.x+=a1.x+a2.x+a3.x; a0.y+=a1.y+a2.y+a3.y;
  a0.z+=a1.z+a2.z+a3.z; a0.w+=a1.w+a2.w+a3.w;
  float4 qo=ld4(w);
  float4 bv=*(const float4*)(b1+lane*4);
  float u0=fmaxf(fmaf(e1,qo.x,a0.x)+bv.x,0.f);
  float u1=fmaxf(fmaf(e1,qo.y,a0.y)+bv.y,0.f);
  float u2=fmaxf(fmaf(e1,qo.z,a0.z)+bv.z,0.f);
  float u3=fmaxf(fmaf(e1,qo.w,a0.w)+bv.w,0.f);
  *(uint2*)(g_uf+(size_t)w*128+lane*4)=make_uint2(pack_h2(u0,u1),pack_h2(u2,u3));
}

// ---- fused GEMM kernels: 64-row tiles, 256 threads, 2 CTAs/SM ----
#define AS_OFF 4096
#define BS_OFF 22528
#define HS_OFF 92160
#define SM_TOT 109568
#define DMID_OFF (BS_OFF+34816)
#define SKA 72
#define SKH 136
#define SNB 136
#define DST 132
#define TM 64
#define APL 4608
#define BPL 8704
#define DS_DW1 0
#define DS_DB1 6144
#define DS_DW2 6176
#define DS_DB2 6432
#define DS_DW3 6440
#define DS_DB3 6448

using FragA=wmma::fragment<wmma::matrix_a,16,16,16,__half,wmma::row_major>;
using FragB=wmma::fragment<wmma::matrix_b,16,16,16,__half,wmma::row_major>;
using FragC=wmma::fragment<wmma::accumulator,16,16,16,float>;

__device__ __forceinline__ void mma_chunk(const __half* Ap,int astr,const __half* Bh,const __half* Bl,
    FragC&a00,FragC&a01,FragC&a10,FragC&a11,int r0,int cw){
#pragma unroll
  for(int kc=0;kc<4;kc++){
    FragA ah0,ah1;
    wmma::load_matrix_sync(ah0,Ap+(size_t)r0*astr+kc*16,astr);
    wmma::load_matrix_sync(ah1,Ap+(size_t)(r0+16)*astr+kc*16,astr);
    FragB bh0,bh1,bl0,bl1;
    wmma::load_matrix_sync(bh0,Bh+(size_t)(kc*16)*SNB+cw,SNB);
    wmma::load_matrix_sync(bh1,Bh+(size_t)(kc*16)*SNB+cw+16,SNB);
    wmma::load_matrix_sync(bl0,Bl+(size_t)(kc*16)*SNB+cw,SNB);
    wmma::load_matrix_sync(bl1,Bl+(size_t)(kc*16)*SNB+cw+16,SNB);
    wmma::mma_sync(a00,ah0,bh0,a00); wmma::mma_sync(a00,ah0,bl0,a00);
    wmma::mma_sync(a01,ah0,bh1,a01); wmma::mma_sync(a01,ah0,bl1,a01);
    wmma::mma_sync(a10,ah1,bh0,a10); wmma::mma_sync(a10,ah1,bl0,a10);
    wmma::mma_sync(a11,ah1,bh1,a11); wmma::mma_sync(a11,ah1,bl1,a11);
  }
}
__device__ __forceinline__ void acc_store(float* D,FragC&a00,FragC&a01,FragC&a10,FragC&a11,int r0,int cw){
  wmma::store_matrix_sync(D+(size_t)r0*DST+cw,a00,DST,wmma::mem_row_major);
  wmma::store_matrix_sync(D+(size_t)r0*DST+cw+16,a01,DST,wmma::mem_row_major);
  wmma::store_matrix_sync(D+(size_t)(r0+16)*DST+cw,a10,DST,wmma::mem_row_major);
  wmma::store_matrix_sync(D+(size_t)(r0+16)*DST+cw+16,a11,DST,wmma::mem_row_major);
}
__device__ __forceinline__ void stage_B(const __half* ws,int KT,int c,int buf,unsigned char* smx,int tid){
  __half* Bs=(__half*)(smx+BS_OFF);
  for(int i=tid;i<2048;i+=256){
    int pl=i>>10,j=i&1023,kk=j>>4,u=j&15;
    cpa16(Bs+(size_t)(buf*2+pl)*BPL+kk*SNB+u*8,
          ws+(size_t)pl*KT*128+(size_t)(c*64+kk)*128+u*8);
  }
}
__device__ __forceinline__ void stage_Ag(const __half* p0,int K0,int c,int buf,unsigned char* smx,int tid,int base){
  __half* As=(__half*)(smx+AS_OFF);
  for(int i=tid;i<512;i+=256){
    int row=i>>3,u=i&7;
    int gc=c*64+u*8,node=base+row;
    __half* dst=As+(size_t)buf*APL+row*SKA+u*8;
    if(node<NN) cpa16(dst,p0+(size_t)node*K0+gc);
    else *(uint4*)dst=make_uint4(0,0,0,0);
  }
}
// LN(+optional relu)(+ELU) epilogue from D_MID into Hs (fp16). mode 0: relu only (encoder); mode 1: LN+ELU (GIN)
template<int MODE>
__device__ __forceinline__ void epi_to_Hs(unsigned char* smx,const float* bias,const float* lg,const float* lb,int tid){
  float* D=(float*)(smx+DMID_OFF);
  float* sr1=(float*)(smx+512); float* sr2=(float*)(smx+1536);
  __half* Hs=(__half*)(smx+HS_OFF);
  int C0=(tid>>6)*32,R=tid&63;
  float v[32];
  u32 hw[16];
  if(MODE==0){
#pragma unroll
    for(int j=0;j<32;j++)v[j]=fmaxf(D[(size_t)R*DST+C0+j]+bias[C0+j],0.f);
#pragma unroll
    for(int j=0;j<16;j++)hw[j]=pack_h2(v[2*j],v[2*j+1]);
  }else{
    float s=0.f,s2=0.f;
#pragma unroll
    for(int j=0;j<32;j++){v[j]=D[(size_t)R*DST+C0+j]+bias[C0+j]; s+=v[j]; s2+=v[j]*v[j];}
    sr1[(tid>>6)*64+R]=s; sr2[(tid>>6)*64+R]=s2;
    __syncthreads();
    s=sr1[R]+sr1[64+R]+sr1[128+R]+sr1[192+R];
    s2=sr2[R]+sr2[64+R]+sr2[128+R]+sr2[192+R];
    float mu=s*(1.f/128.f), var=fmaxf(s2*(1.f/128.f)-mu*mu,0.f), rs=rsqrtf(var+1e-5f);
#pragma unroll
    for(int j=0;j<16;j++){
      float n0=(v[2*j]-mu)*rs*lg[C0+2*j]+lb[C0+2*j];
      float n1=(v[2*j+1]-mu)*rs*lg[C0+2*j+1]+lb[C0+2*j+1];
      n0=(n0>0.f)?n0:expm1f(n0);
      n1=(n1>0.f)?n1:expm1f(n1);
      hw[j]=pack_h2(n0,n1);
    }
  }
  uint4* oh=(uint4*)(Hs+(size_t)R*SKH+C0);
#pragma unroll
  for(int j=0;j<4;j++)oh[j]=((uint4*)hw)[j];
  __syncthreads();
}
// GEMM1 (K=192): A chunk0 = As buf0 (x), chunks 1,2 = Hs. D2 -> g_q
__device__ __forceinline__ void gemm1_to_q(int woff,unsigned char* smx,int tid,int base){
  __half* As=(__half*)(smx+AS_OFF);
  __half* Bs=(__half*)(smx+BS_OFF);
  __half* Hs=(__half*)(smx+HS_OFF);
  float* D=(float*)(smx+AS_OFF);
  const __half* ws=g_wimg+woff;
  int wid=tid>>5;
  int r0=(wid&1)*32, cw=(wid>>1)*32;
  FragC a00,a01,a10,a11;
  wmma::fill_fragment(a00,0.f); wmma::fill_fragment(a01,0.f);
  wmma::fill_fragment(a10,0.f); wmma::fill_fragment(a11,0.f);
  stage_B(ws,192,0,0,smx,tid); cpcommit();
  for(int c=0;c<3;c++){
    int buf=c&1;
    if(c+1<3){ stage_B(ws,192,c+1,buf^1,smx,tid); cpcommit(); cpwaitg<1>(); }
    else cpwaitg<0>();
    __syncthreads();
    const __half* Ap; int astr;
    if(c==0){Ap=As; astr=SKA;} else {Ap=Hs+(c-1)*64; astr=SKH;}
    mma_chunk(Ap,astr,Bs+(size_t)(buf*2)*BPL,Bs+(size_t)(buf*2+1)*BPL,a00,a01,a10,a11,r0,cw);
    __syncthreads();
  }
  acc_store(D,a00,a01,a10,a11,r0,cw);
  __syncthreads();
  int C0=(tid>>6)*32,R=tid&63,node=base+R;
  if(node<NN){
    u32 hw[16];
#pragma unroll
    for(int j=0;j<16;j++)hw[j]=pack_h2(D[(size_t)R*DST+C0+2*j],D[(size_t)R*DST+C0+2*j+1]);
    uint4* oq=(uint4*)(g_q+(size_t)node*128+C0);
#pragma unroll
    for(int j=0;j<4;j++)oq[j]=((uint4*)hw)[j];
  }
}
// generic K=128 GEMM from global A (u) or Hs into D_MID
template<int AHS>
__device__ __forceinline__ void gemm128_mid(int woff,const __half* p0,unsigned char* smx,int tid,int base){
  __half* As=(__half*)(smx+AS_OFF);
  __half* Bs=(__half*)(smx+BS_OFF);
  __half* Hs=(__half*)(smx+HS_OFF);
  float* D=(float*)(smx+DMID_OFF);
  const __half* ws=g_wimg+woff;
  int wid=tid>>5;
  int r0=(wid&1)*32, cw=(wid>>1)*32;
  FragC a00,a01,a10,a11;
  wmma::fill_fragment(a00,0.f); wmma::fill_fragment(a01,0.f);
  wmma::fill_fragment(a10,0.f); wmma::fill_fragment(a11,0.f);
  stage_B(ws,128,0,0,smx,tid);
  if(!AHS) stage_Ag(p0,128,0,0,smx,tid,base);
  cpcommit();
  stage_B(ws,128,1,1,smx,tid);
  if(!AHS) stage_Ag(p0,128,1,1,smx,tid,base);
  cpcommit();
  for(int c=0;c<2;c++){
    if(c==0) cpwaitg<1>(); else cpwaitg<0>();
    __syncthreads();
    const __half* Ap; int astr;
    if(AHS){Ap=Hs+c*64; astr=SKH;} else {Ap=As+(size_t)c*APL; astr=SKA;}
    mma_chunk(Ap,astr,Bs+(size_t)(c*2)*BPL,Bs+(size_t)(c*2+1)*BPL,a00,a01,a10,a11,r0,cw);
    __syncthreads();
  }
  acc_store(D,a00,a01,a10,a11,r0,cw);
  __syncthreads();
}

// fused: encoder + GEMM1 layer0
__global__ void __launch_bounds__(256,2) k_encg1(const float* __restrict__ b_in){
  extern __shared__ unsigned char smx[];
  int tid=threadIdx.x;
  int base=blockIdx.x*TM;
  int wid=tid>>5;
  int r0=(wid&1)*32, cw=(wid>>1)*32;
  __half* As=(__half*)(smx+AS_OFF);
  __half* Bs=(__half*)(smx+BS_OFF);
  float* D=(float*)(smx+DMID_OFF);
  // encoder K=64, single chunk
  stage_B(g_wimg,64,0,0,smx,tid);
  stage_Ag(g_xf,64,0,0,smx,tid,base);
  cpcommit(); cpwaitg<0>();
  __syncthreads();
  {
    FragC a00,a01,a10,a11;
    wmma::fill_fragment(a00,0.f); wmma::fill_fragment(a01,0.f);
    wmma::fill_fragment(a10,0.f); wmma::fill_fragment(a11,0.f);
    mma_chunk(As,SKA,Bs,Bs+BPL,a00,a01,a10,a11,r0,cw);
    __syncthreads();
    acc_store(D,a00,a01,a10,a11,r0,cw);
    __syncthreads();
  }
  epi_to_Hs<0>(smx,b_in,nullptr,nullptr,tid);
  gemm1_to_q(16384,smx,tid,base);
}

// fused: GEMM2 layer l + GEMM1 layer l+1
__global__ void __launch_bounds__(256,2) k_g2g1(int woff2,int woff1,
    const float* __restrict__ b2,const float* __restrict__ lg,const float* __restrict__ lb){
  extern __shared__ unsigned char smx[];
  int tid=threadIdx.x;
  int base=blockIdx.x*TM;
  gemm128_mid<0>(woff2,g_uf,smx,tid,base);
  epi_to_Hs<1>(smx,b2,lg,lb,tid);
  stage_Ag(g_xf,64,0,0,smx,tid,base);   // x tile for GEMM1 chunk0 (commits inside gemm1)
  gemm1_to_q(woff1,smx,tid,base);
}

// fused: GEMM2 layer2 + graphemb(LN+pool) + nodeout(LN+decoder)
__global__ void __launch_bounds__(256,2) k_g2fin(int woff2,
    const float* __restrict__ b2,const float* __restrict__ lg2,const float* __restrict__ lb2,
    const int* __restrict__ bidx,
    const float* __restrict__ gb,const float* __restrict__ glg,const float* __restrict__ glb,
    const float* __restrict__ ob,const float* __restrict__ lfg,const float* __restrict__ lfb,
    const float* __restrict__ x,
    const float* __restrict__ dW1,const float* __restrict__ db1,
    const float* __restrict__ dW2,const float* __restrict__ db2,
    const float* __restrict__ dW3,const float* __restrict__ db3,
    float* __restrict__ outp){
  extern __shared__ unsigned char smx[];
  int tid=threadIdx.x,lane=tid&31,wid=tid>>5;
  int base=blockIdx.x*TM;
  int* sbid=(int*)smx;
  float* sr1=(float*)(smx+512); float* sr2=(float*)(smx+1536);
  float* D=(float*)(smx+AS_OFF);
  __half* Hs=(__half*)(smx+HS_OFF);
  if(tid<TM){int nd=base+tid; sbid[tid]=(nd<NN)?bidx[nd]:-1;}
  // GEMM2 l2 -> Hs (h3)
  gemm128_mid<0>(woff2,g_uf,smx,tid,base);
  epi_to_Hs<1>(smx,b2,lg2,lb2,tid);
  // graphemb: A=Hs, B=gW
  {
    int r0=(wid&1)*32, cw=(wid>>1)*32;
    __half* Bs=(__half*)(smx+BS_OFF);
    const __half* ws=g_wimg+262144;
    FragC a00,a01,a10,a11;
    wmma::fill_fragment(a00,0.f); wmma::fill_fragment(a01,0.f);
    wmma::fill_fragment(a10,0.f); wmma::fill_fragment(a11,0.f);
    stage_B(ws,128,0,0,smx,tid); cpcommit();
    stage_B(ws,128,1,1,smx,tid); cpcommit();
    for(int c=0;c<2;c++){
      if(c==0) cpwaitg<1>(); else cpwaitg<0>();
      __syncthreads();
      mma_chunk(Hs+c*64,SKH,Bs+(size_t)(c*2)*BPL,Bs+(size_t)(c*2+1)*BPL,a00,a01,a10,a11,r0,cw);
      __syncthreads();
    }
    acc_store(D,a00,a01,a10,a11,r0,cw);
    __syncthreads();
  }
  // graphemb LN + pool
  {
    int C0=(tid>>6)*32,R=tid&63;
    float v[32]; float s=0.f,s2=0.f;
#pragma unroll
    for(int j=0;j<32;j++){v[j]=fmaxf(D[(size_t)R*DST+C0+j]+gb[C0+j],0.f); s+=v[j]; s2+=v[j]*v[j];}
    sr1[(tid>>6)*64+R]=s; sr2[(tid>>6)*64+R]=s2;
    __syncthreads();
    s=sr1[R]+sr1[64+R]+sr1[128+R]+sr1[192+R];
    s2=sr2[R]+sr2[64+R]+sr2[128+R]+sr2[192+R];
    float mu=s*(1.f/128.f), var=fmaxf(s2*(1.f/128.f)-mu*mu,0.f), rs=rsqrtf(var+1e-5f);
#pragma unroll
    for(int j=0;j<32;j++)D[(size_t)R*DST+C0+j]=(v[j]-mu)*rs*glg[C0+j]+glb[C0+j];
    __syncthreads();
    if(tid<128){
      int col=tid; float a=0.f; int cur=-1;
      for(int r=0;r<TM;r++){
        int bi=sbid[r];
        if(bi!=cur){ if(cur>=0)atomicAdd(&g_gsum[cur*128+col],a); a=0.f; cur=bi; }
        if(bi>=0)a+=D[(size_t)r*DST+col];
      }
      if(cur>=0)atomicAdd(&g_gsum[cur*128+col],a);
    }
    __syncthreads();
  }
  // nodeout: A=Hs, B=oW
  {
    int r0=(wid&1)*32, cw=(wid>>1)*32;
    __half* Bs=(__half*)(smx+BS_OFF);
    const __half* ws=g_wimg+294912;
    FragC a00,a01,a10,a11;
    wmma::fill_fragment(a00,0.f); wmma::fill_fragment(a01,0.f);
    wmma::fill_fragment(a10,0.f); wmma::fill_fragment(a11,0.f);
    stage_B(ws,128,0,0,smx,tid); cpcommit();
    stage_B(ws,128,1,1,smx,tid); cpcommit();
    for(int c=0;c<2;c++){
      if(c==0) cpwaitg<1>(); else cpwaitg<0>();
      __syncthreads();
      mma_chunk(Hs+c*64,SKH,Bs+(size_t)(c*2)*BPL,Bs+(size_t)(c*2+1)*BPL,a00,a01,a10,a11,r0,cw);
      __syncthreads();
    }
    acc_store(D,a00,a01,a10,a11,r0,cw);
    __syncthreads();
  }
  // nodeout LN (into D) + decoder
  {
    int C0=(tid>>6)*32,R=tid&63;
    float v[32]; float s=0.f,s2=0.f;
#pragma unroll
    for(int j=0;j<32;j++){v[j]=fmaxf(D[(size_t)R*DST+C0+j]+ob[C0+j],0.f); s+=v[j]; s2+=v[j]*v[j];}
    sr1[(tid>>6)*64+R]=s; sr2[(tid>>6)*64+R]=s2;
    __syncthreads();
    s=sr1[R]+sr1[64+R]+sr1[128+R]+sr1[192+R];
    s2=sr2[R]+sr2[64+R]+sr2[128+R]+sr2[192+R];
    float mu=s*(1.f/128.f), var=fmaxf(s2*(1.f/128.f)-mu*mu,0.f), rs=rsqrtf(var+1e-5f);
#pragma unroll
    for(int j=0;j<32;j++)D[(size_t)R*DST+C0+j]=(v[j]-mu)*rs*lfg[C0+j]+lfb[C0+j];
    // stage decoder data: xsh (fp32 x tile) into Hs region (dead), dsh into Bs tail
    float* xsh=(float*)(smx+HS_OFF);
    float* dsh=(float*)(smx+BS_OFF+40960);
    for(int i=tid;i<4096;i+=256){int r=i>>6,k=i&63;int nd=base+r;xsh[i]=(nd<NN)?x[(size_t)nd*64+k]:0.f;}
    for(int i=tid;i<6144;i+=256)dsh[DS_DW1+i]=dW1[i];
    if(tid<32)dsh[DS_DB1+tid]=db1[tid];
    if(tid<256)dsh[DS_DW2+tid]=dW2[tid];
    if(tid<8){dsh[DS_DB2+tid]=db2[tid];dsh[DS_DW3+tid]=dW3[tid];}
    if(tid==0)dsh[DS_DB3]=db3[0];
    __syncthreads();
    int j=lane, rr0=wid*8;
    for(int i=0;i<8;i++){
      int row=rr0+i, nd=base+row;
      float s1=dsh[DS_DB1+j];
      const float* xr=xsh+(size_t)row*64;
      const float* nr=D+(size_t)row*DST;
#pragma unroll 4
      for(int k=0;k<64;k++)s1=fmaf(xr[k],dsh[DS_DW1+k*32+j],s1);
#pragma unroll 4
      for(int k=0;k<128;k++)s1=fmaf(nr[k],dsh[DS_DW1+(64+k)*32+j],s1);
      s1=fmaxf(s1,0.f);
      float t2[8];
#pragma unroll
      for(int m=0;m<8;m++)t2[m]=s1*dsh[DS_DW2+j*8+m];
#pragma unroll
      for(int o=16;o>0;o>>=1)
#pragma unroll
        for(int m=0;m<8;m++)t2[m]+=__shfl_xor_sync(~0u,t2[m],o);
      float out=dsh[DS_DB3];
#pragma unroll
      for(int m=0;m<8;m++)out=fmaf(fmaxf(t2[m]+dsh[DS_DB2+m],0.f),dsh[DS_DW3+m],out);
      if(j==0&&nd<NN)outp[nd]=out;
    }
  }
}

// ---- graph-level MLP ----
__device__ __forceinline__ int lbound(const int* __restrict__ a,int n,int v){
  int lo=0,hi=n;
  while(lo<hi){int m=(lo+hi)>>1; if(a[m]<v)lo=m+1; else hi=m;}
  return lo;
}
__global__ void k_gmlp(const int* __restrict__ bidx,
    const float* __restrict__ gW1,const float* __restrict__ gb1,
    const float* __restrict__ gW2,const float* __restrict__ gb2,
    const float* __restrict__ gW3,const float* __restrict__ gb3,
    float* __restrict__ outp){
  int tid=threadIdx.x,lane=tid&31;
  int g=blockIdx.x*8+(tid>>5);
  int lo=lbound(bidx,NN,g),hi=lbound(bidx,NN,g+1);
  float inv=1.f/fmaxf((float)(hi-lo),1.f);
  float s1=gb1[lane];
  for(int k=0;k<128;k++)s1=fmaf(g_gsum[g*128+k]*inv,gW1[k*32+lane],s1);
  s1=fmaxf(s1,0.f);
  float t2[8];
#pragma unroll
  for(int m=0;m<8;m++)t2[m]=s1*gW2[lane*8+m];
#pragma unroll
  for(int o=16;o>0;o>>=1)
#pragma unroll
    for(int m=0;m<8;m++)t2[m]+=__shfl_xor_sync(~0u,t2[m],o);
  float out=gb3[0];
#pragma unroll
  for(int m=0;m<8;m++)out=fmaf(fmaxf(t2[m]+gb2[m],0.f),gW3[m],out);
  if(lane==0)outp[NN+g]=out;
}

extern "C" void kernel_launch(void* const* d_in,const int* in_sizes,int n_in,
                              void* d_out,int out_size){
  (void)in_sizes;(void)n_in;(void)out_size;
  const float* x   =(const float*)d_in[0];
  const int*   ei  =(const int*)  d_in[1];
  const int*   bidx=(const int*)  d_in[2];
  const float* W_in=(const float*)d_in[3];
  const float* b_in=(const float*)d_in[4];
  const float* eps =(const float*)d_in[5];
  const float* mW1 =(const float*)d_in[6];
  const float* mb1 =(const float*)d_in[7];
  const float* mW2 =(const float*)d_in[8];
  const float* mb2 =(const float*)d_in[9];
  const float* lng =(const float*)d_in[10];
  const float* lnb =(const float*)d_in[11];
  const float* oW  =(const float*)d_in[12];
  const float* ob  =(const float*)d_in[13];
  const float* lfg =(const float*)d_in[14];
  const float* lfb =(const float*)d_in[15];
  const float* gW  =(const float*)d_in[16];
  const float* gb  =(const float*)d_in[17];
  const float* glg =(const float*)d_in[18];
  const float* glb =(const float*)d_in[19];
  const float* dW1 =(const float*)d_in[20];
  const float* db1 =(const float*)d_in[21];
  const float* dW2 =(const float*)d_in[22];
  const float* db2 =(const float*)d_in[23];
  const float* dW3 =(const float*)d_in[24];
  const float* db3 =(const float*)d_in[25];
  const float* gW1 =(const float*)d_in[26];
  const float* gb1 =(const float*)d_in[27];
  const float* gW2 =(const float*)d_in[28];
  const float* gb2 =(const float*)d_in[29];
  const float* gW3 =(const float*)d_in[30];
  const float* gb3 =(const float*)d_in[31];
  float* outp=(float*)d_out;

  const int NG=(NN+TM-1)/TM;   // 1563
  cudaFuncSetAttribute((const void*)k_encg1,cudaFuncAttributeMaxDynamicSharedMemorySize,SM_TOT);
  cudaFuncSetAttribute((const void*)k_g2g1, cudaFuncAttributeMaxDynamicSharedMemorySize,SM_TOT);
  cudaFuncSetAttribute((const void*)k_g2fin,cudaFuncAttributeMaxDynamicSharedMemorySize,SM_TOT);

  k_prepx<<<12500,256>>>(x);                                             //0
  k_prepw<<<640,256>>>(W_in,mW1,mW2,gW,oW);                              //1
  k_zero<<<391,256>>>();                                                 //2
  k_encg1<<<NG,256,SM_TOT>>>(b_in);                                      //3 (profiled)
  k_hist<<<6250,256>>>(ei);                                              //4
  k_scan1<<<98,1024>>>();                                                //5
  k_scan2<<<1,128>>>();                                                  //6
  k_scan3<<<98,1024>>>();                                                //7
  k_fill<<<6250,256>>>(ei);                                              //8

  for(int l=0;l<2;l++){
    k_gatheru<<<12500,256>>>(eps,l,mb1+l*128);
    k_g2g1<<<NG,256,SM_TOT>>>(163840+l*32768,16384+(l+1)*49152,
        mb2+l*128,lng+l*128,lnb+l*128);
  }
  k_gatheru<<<12500,256>>>(eps,2,mb1+256);
  k_g2fin<<<NG,256,SM_TOT>>>(163840+2*32768,mb2+256,lng+256,lnb+256,bidx,
      gb,glg,glb,ob,lfg,lfb,x,dW1,db1,dW2,db2,dW3,db3,outp);
  k_gmlp<<<32,256>>>(bidx,gW1,gb1,gW2,gb2,gW3,gb3,outp);
}